// round 2
// baseline (speedup 1.0000x reference)
#include <cuda_runtime.h>
#include <math.h>

// Problem constants
#define NPIX   32768            // B*H*W = 8*64*64
#define QKVC   768

// Scratch (device globals: no allocation allowed)
__device__ float g_qkv[NPIX * QKVC];     // per-pixel q(256, pre-scaled) | k(256) | v(256)
__device__ float g_attn[NPIX * 256];     // attention output, pixel-major
__device__ float g_wf[1024 * 256];       // fused w_conv @ wo
__device__ float g_bf[1024];             // fused bias

// ---------------------------------------------------------------------------
// K0: fuse wo into conv:  Wf[o][i] = sum_c wc[o][c]*wo[c][i],  bf[o]=wc@bo+bc
// ---------------------------------------------------------------------------
__global__ __launch_bounds__(256) void k_fuse(const float* __restrict__ wo,
                                              const float* __restrict__ bo,
                                              const float* __restrict__ wc,
                                              const float* __restrict__ bc)
{
    int ob = blockIdx.x * 4;     // 256 blocks cover 1024 outputs
    int i  = threadIdx.x;        // attn-channel
    float a0 = 0.f, a1 = 0.f, a2 = 0.f, a3 = 0.f;
    for (int cc = 0; cc < 256; cc++) {
        float w = wo[cc * 256 + i];
        a0 += wc[(ob + 0) * 256 + cc] * w;
        a1 += wc[(ob + 1) * 256 + cc] * w;
        a2 += wc[(ob + 2) * 256 + cc] * w;
        a3 += wc[(ob + 3) * 256 + cc] * w;
    }
    g_wf[(ob + 0) * 256 + i] = a0;
    g_wf[(ob + 1) * 256 + i] = a1;
    g_wf[(ob + 2) * 256 + i] = a2;
    g_wf[(ob + 3) * 256 + i] = a3;
    if (i < 4) {
        int o = ob + i;
        float s = 0.f;
        for (int cc = 0; cc < 256; cc++) s += wc[o * 256 + cc] * bo[cc];
        g_bf[o] = s + bc[o];
    }
}

// ---------------------------------------------------------------------------
// K1: per-pixel QKV projection.  C[768,32768] = [wq;wk;wv] @ X[256,32768]
// X[c][n] = x[b*C*HW + c*HW + p], n = b*4096 + p.  Output pixel-major g_qkv.
// q rows (<256) pre-scaled by d^-0.5 = 0.125.
// ---------------------------------------------------------------------------
__global__ __launch_bounds__(256) void k_qkv(const float* __restrict__ x,
                                             const float* __restrict__ wq,
                                             const float* __restrict__ wkv)
{
    __shared__ float As[16][64];
    __shared__ float Bs[16][68];
    int t  = threadIdx.x;
    int m0 = blockIdx.y * 64;          // 12 tiles over 768
    int n0 = blockIdx.x * 64;          // 512 tiles over 32768
    int tm = t >> 4, tn = t & 15;
    int am = t >> 2, ak = (t & 3) * 4;
    int bk = t >> 4, bn = (t & 15) * 4;

    const float* wrow = (m0 + am < 256) ? (wq + (m0 + am) * 256)
                                        : (wkv + (m0 + am - 256) * 256);
    const float* xcol = x + (size_t)(n0 >> 12) * (256 * 4096) + (n0 & 4095);

    float acc[4][4] = {};
    for (int k0 = 0; k0 < 256; k0 += 16) {
        float4 a4 = *(const float4*)(wrow + k0 + ak);
        As[ak + 0][am] = a4.x; As[ak + 1][am] = a4.y;
        As[ak + 2][am] = a4.z; As[ak + 3][am] = a4.w;
        *(float4*)&Bs[bk][bn] = *(const float4*)(xcol + (size_t)(k0 + bk) * 4096 + bn);
        __syncthreads();
#pragma unroll
        for (int kk = 0; kk < 16; kk++) {
            float4 av = *(float4*)&As[kk][tm * 4];
            float4 bv = *(float4*)&Bs[kk][tn * 4];
            float a[4] = {av.x, av.y, av.z, av.w};
            float b[4] = {bv.x, bv.y, bv.z, bv.w};
#pragma unroll
            for (int im = 0; im < 4; im++)
#pragma unroll
                for (int in = 0; in < 4; in++)
                    acc[im][in] += a[im] * b[in];
        }
        __syncthreads();
    }
    float sc = (m0 < 256) ? 0.125f : 1.0f;   // tiles are 64-aligned: uniform
#pragma unroll
    for (int in = 0; in < 4; in++) {
        int n = n0 + tn * 4 + in;
        float4 v = make_float4(acc[0][in] * sc, acc[1][in] * sc,
                               acc[2][in] * sc, acc[3][in] * sc);
        *(float4*)&g_qkv[(size_t)n * QKVC + m0 + tm * 4] = v;
    }
}

// ---------------------------------------------------------------------------
// K2: halo attention. One CTA per (window nb, head hh). 256 threads.
// smem (floats):
//   qs   [dd*64 + qi]           0     .. 4096
//   ks   [dd*256 + j]           4096  .. 20480
//   vs   [j*68 + dd]            20480 .. 37888
//   lw   [qi*16 + jj]           37888 .. 38912
//   lh   [qi*16 + i]            38912 .. 39936
//   msk  [j]                    39936 .. 40192
//   simb [qi*260 + j]           40192 .. 56832   (rel tables overlaid here first)
// total 56832 floats = 227328 bytes
// ---------------------------------------------------------------------------
__global__ __launch_bounds__(256) void k_attn(const float* __restrict__ relh,
                                              const float* __restrict__ relw)
{
    extern __shared__ float sm[];
    float* qs   = sm;
    float* ks   = sm + 4096;
    float* vs   = sm + 20480;
    float* lw   = sm + 37888;
    float* lh   = sm + 38912;
    float* msk  = sm + 39936;
    float* simb = sm + 40192;
    float* srh  = simb;            // [r*65+dd], 31*65 = 2015
    float* srw  = simb + 2048;     // [r*65+dd]

    int t  = threadIdx.x;
    int nb = blockIdx.x;           // 0..511
    int hh = blockIdx.y;           // 0..3
    int bi = nb >> 6;
    int tb = nb & 63;
    int bh = tb >> 3, bw = tb & 7;
    int hco = hh * 64;

    // rel tables -> smem with stride 65 (bank-conflict-free row reads)
    for (int idx = t; idx < 1984; idx += 256) {
        int r = idx >> 6, dd = idx & 63;
        srh[r * 65 + dd] = relh[idx];
        srw[r * 65 + dd] = relw[idx];
    }
    // Q (transposed: dd-major)
    {
        int qi = t >> 2, dq = t & 3;
        int qx = qi >> 3, qy = qi & 7;
        const float* src = g_qkv +
            (size_t)(bi * 4096 + (bh * 8 + qx) * 64 + (bw * 8 + qy)) * QKVC + hco;
#pragma unroll
        for (int u = 0; u < 4; u++) {
            int dd = dq * 16 + u * 4;
            float4 v = *(const float4*)(src + dd);
            qs[(dd + 0) * 64 + qi] = v.x; qs[(dd + 1) * 64 + qi] = v.y;
            qs[(dd + 2) * 64 + qi] = v.z; qs[(dd + 3) * 64 + qi] = v.w;
        }
    }
    // K (transposed) / V / mask
    {
        int dq = t & 3;
        int jb = t >> 2;
#pragma unroll
        for (int rep = 0; rep < 4; rep++) {
            int j  = rep * 64 + jb;
            int ki = j >> 4, kj = j & 15;
            int gh = bh * 8 - 4 + ki, gw = bw * 8 - 4 + kj;
            bool valid = ((unsigned)gh < 64u) && ((unsigned)gw < 64u);
            size_t off = valid ? (size_t)(bi * 4096 + gh * 64 + gw) * QKVC + hco : 0;
            const float* src = g_qkv + off;
#pragma unroll
            for (int u = 0; u < 4; u++) {
                int dd = dq * 16 + u * 4;
                float4 kv = valid ? *(const float4*)(src + 256 + dd) : make_float4(0, 0, 0, 0);
                float4 vv = valid ? *(const float4*)(src + 512 + dd) : make_float4(0, 0, 0, 0);
                ks[(dd + 0) * 256 + j] = kv.x; ks[(dd + 1) * 256 + j] = kv.y;
                ks[(dd + 2) * 256 + j] = kv.z; ks[(dd + 3) * 256 + j] = kv.w;
                *(float4*)&vs[j * 68 + dd] = vv;
            }
            if (dq == 0) msk[j] = valid ? 0.0f : -3.0e38f;
        }
    }
    __syncthreads();

    // relative-position logits: 2048 dot products of length 64
#pragma unroll
    for (int m = 0; m < 8; m++) {
        int wk  = t + 256 * m;
        int qi  = wk >> 5;
        int sel = (wk >> 4) & 1;       // 0 -> lh (row), 1 -> lw (col)
        int pos = wk & 15;
        int qx = qi >> 3, qy = qi & 7;
        int ridx = pos - (sel ? qy : qx) + 15;
        const float* rrow = (sel ? srw : srh) + ridx * 65;
        float a = 0.f;
#pragma unroll 8
        for (int dd = 0; dd < 64; dd++) a += qs[dd * 64 + qi] * rrow[dd];
        (sel ? lw : lh)[qi * 16 + pos] = a;
    }
    __syncthreads();   // rel region free now; sim may overwrite it

    // sim = q @ k^T  (64x256, contract over dd=64).
    // 256 threads * 4x4 cover 64x64 per pass -> 4 passes over j-blocks.
    int tq = t >> 4, tj = t & 15;
#pragma unroll
    for (int jb4 = 0; jb4 < 4; jb4++) {
        int j0 = jb4 * 64;
        float acc[4][4] = {};
#pragma unroll 8
        for (int dd = 0; dd < 64; dd++) {
            float4 av = *(float4*)&qs[dd * 64 + tq * 4];
            float4 bv = *(float4*)&ks[dd * 256 + j0 + tj * 4];
            float a[4] = {av.x, av.y, av.z, av.w};
            float b[4] = {bv.x, bv.y, bv.z, bv.w};
#pragma unroll
            for (int iq = 0; iq < 4; iq++)
#pragma unroll
                for (int ij = 0; ij < 4; ij++)
                    acc[iq][ij] += a[iq] * b[ij];
        }
#pragma unroll
        for (int iq = 0; iq < 4; iq++) {
            int qi = tq * 4 + iq;
#pragma unroll
            for (int ij = 0; ij < 4; ij++) {
                int j = j0 + tj * 4 + ij;
                simb[qi * 260 + j] = acc[iq][ij] + lw[qi * 16 + (j & 15)]
                                   + lh[qi * 16 + (j >> 4)] + msk[j];
            }
        }
    }
    __syncthreads();

    // softmax over 256 keys: 4 consecutive lanes per row
    {
        int row = t >> 2, seg = t & 3;
        float* srow = simb + row * 260 + seg * 64;
        float mx = -3.4e38f;
#pragma unroll 8
        for (int j = 0; j < 64; j++) mx = fmaxf(mx, srow[j]);
        mx = fmaxf(mx, __shfl_xor_sync(0xffffffffu, mx, 1));
        mx = fmaxf(mx, __shfl_xor_sync(0xffffffffu, mx, 2));
        float sum = 0.f;
#pragma unroll 8
        for (int j = 0; j < 64; j++) { float e = __expf(srow[j] - mx); srow[j] = e; sum += e; }
        sum += __shfl_xor_sync(0xffffffffu, sum, 1);
        sum += __shfl_xor_sync(0xffffffffu, sum, 2);
        float inv = 1.0f / sum;
#pragma unroll 8
        for (int j = 0; j < 64; j++) srow[j] *= inv;
    }
    __syncthreads();

    // out = attn @ v  (64x64, contract over j=256)
    float o[4][4] = {};
    {
        const float* s0 = simb + (size_t)(tq * 4 + 0) * 260;
        const float* s1 = simb + (size_t)(tq * 4 + 1) * 260;
        const float* s2 = simb + (size_t)(tq * 4 + 2) * 260;
        const float* s3 = simb + (size_t)(tq * 4 + 3) * 260;
#pragma unroll 4
        for (int j = 0; j < 256; j++) {
            float4 bv = *(float4*)&vs[j * 68 + tj * 4];
            float b[4] = {bv.x, bv.y, bv.z, bv.w};
            float a0 = s0[j], a1 = s1[j], a2 = s2[j], a3 = s3[j];
#pragma unroll
            for (int id = 0; id < 4; id++) {
                o[0][id] += a0 * b[id];
                o[1][id] += a1 * b[id];
                o[2][id] += a2 * b[id];
                o[3][id] += a3 * b[id];
            }
        }
    }
#pragma unroll
    for (int iq = 0; iq < 4; iq++) {
        int qi = tq * 4 + iq;
        int qx = qi >> 3, qy = qi & 7;
        size_t p = (size_t)(bi * 4096 + (bh * 8 + qx) * 64 + (bw * 8 + qy));
        *(float4*)&g_attn[p * 256 + hco + tj * 4] =
            make_float4(o[iq][0], o[iq][1], o[iq][2], o[iq][3]);
    }
}

// ---------------------------------------------------------------------------
// K3: fused output GEMM + PixelShuffle.
// C[1024,32768] = Wf @ attn^T + bf; channel o=(c,r,s) -> out[b][c][2h+r][2w+s]
// ---------------------------------------------------------------------------
__global__ __launch_bounds__(256) void k_out(float* __restrict__ out)
{
    __shared__ float As[16][64];
    __shared__ float Bs[16][68];
    int t  = threadIdx.x;
    int m0 = blockIdx.y * 64;          // 16 tiles over 1024
    int n0 = blockIdx.x * 64;          // 512 tiles over 32768
    int tm = t >> 4, tn = t & 15;
    int am = t >> 2, ak = (t & 3) * 4;
    int bn = t >> 2, bkq = (t & 3) * 4;

    float acc[4][4] = {};
    for (int k0 = 0; k0 < 256; k0 += 16) {
        float4 a4 = *(const float4*)(g_wf + (size_t)(m0 + am) * 256 + k0 + ak);
        As[ak + 0][am] = a4.x; As[ak + 1][am] = a4.y;
        As[ak + 2][am] = a4.z; As[ak + 3][am] = a4.w;
        float4 b4 = *(const float4*)(g_attn + (size_t)(n0 + bn) * 256 + k0 + bkq);
        Bs[bkq + 0][bn] = b4.x; Bs[bkq + 1][bn] = b4.y;
        Bs[bkq + 2][bn] = b4.z; Bs[bkq + 3][bn] = b4.w;
        __syncthreads();
#pragma unroll
        for (int kk = 0; kk < 16; kk++) {
            float4 av = *(float4*)&As[kk][tm * 4];
            float4 bv = *(float4*)&Bs[kk][tn * 4];
            float a[4] = {av.x, av.y, av.z, av.w};
            float b[4] = {bv.x, bv.y, bv.z, bv.w};
#pragma unroll
            for (int im = 0; im < 4; im++)
#pragma unroll
                for (int in = 0; in < 4; in++)
                    acc[im][in] += a[im] * b[in];
        }
        __syncthreads();
    }
    // epilogue: o quad = 2x2 patch at (2h, 2w)
    int bimg = n0 >> 12;
    int p0   = n0 & 4095;
    int h    = p0 >> 6;               // tile-constant (64-aligned)
    int o    = m0 + tm * 4;
    int cch  = o >> 2;
    float b0 = g_bf[o + 0], b1 = g_bf[o + 1], b2 = g_bf[o + 2], b3 = g_bf[o + 3];
    float* obase0 = out + (size_t)bimg * (256 * 128 * 128) + (size_t)cch * 16384
                  + (size_t)(2 * h) * 128;
#pragma unroll
    for (int in = 0; in < 4; in++) {
        int w = tn * 4 + in;
        float* p = obase0 + 2 * w;
        *(float2*)(p)       = make_float2(acc[0][in] + b0, acc[1][in] + b1);
        *(float2*)(p + 128) = make_float2(acc[2][in] + b2, acc[3][in] + b3);
    }
}

// ---------------------------------------------------------------------------
extern "C" void kernel_launch(void* const* d_in, const int* in_sizes, int n_in,
                              void* d_out, int out_size)
{
    const float* x    = (const float*)d_in[0];
    const float* wq   = (const float*)d_in[1];
    const float* wkv  = (const float*)d_in[2];
    const float* wo   = (const float*)d_in[3];
    const float* bo   = (const float*)d_in[4];
    const float* relh = (const float*)d_in[5];
    const float* relw = (const float*)d_in[6];
    const float* wc   = (const float*)d_in[7];
    const float* bc   = (const float*)d_in[8];
    float* out = (float*)d_out;

    cudaFuncSetAttribute(k_attn, cudaFuncAttributeMaxDynamicSharedMemorySize, 227328);

    k_fuse<<<256, 256>>>(wo, bo, wc, bc);
    k_qkv<<<dim3(512, 12), 256>>>(x, wq, wkv);
    k_attn<<<dim3(512, 4), 256, 227328>>>(relh, relw);
    k_out<<<dim3(512, 16), 256>>>(out);
}

// round 4
// speedup vs baseline: 1.5231x; 1.5231x over previous
#include <cuda_runtime.h>
#include <cuda_bf16.h>
#include <stdint.h>

#define NPIX 32768            // B*H*W
#define QKVC 768

// Scratch (device globals; 16B-aligned for cp.async)
__device__ float g_qkv[NPIX * QKVC];                    // [pixel][q|k|v] fp32
__device__ __align__(16) __nv_bfloat16 g_bh[NPIX * 256];   // attn out hi, [n][256]
__device__ __align__(16) __nv_bfloat16 g_bl[NPIX * 256];   // attn out lo
__device__ __align__(16) __nv_bfloat16 g_wfh[1024 * 256];  // fused conv W hi, [m][k]
__device__ __align__(16) __nv_bfloat16 g_wfl[1024 * 256];
__device__ __align__(16) __nv_bfloat16 g_wqh[QKVC * 256];  // qkv W hi (q pre-scaled), [m][k]
__device__ __align__(16) __nv_bfloat16 g_wql[QKVC * 256];
__device__ __align__(16) __nv_bfloat16 g_xh[256 * NPIX];   // x split, [k][n]
__device__ __align__(16) __nv_bfloat16 g_xl[256 * NPIX];
__device__ float g_bf[1024];

// ---------------------------------------------------------------------------
// helpers (non-arch-specific PTX only: cp.async / ldmatrix / mma.sync)
// ---------------------------------------------------------------------------
__device__ __forceinline__ uint32_t smem_u32(const void* p) {
    uint32_t a;
    asm("{ .reg .u64 t; cvta.to.shared.u64 t, %1; cvt.u32.u64 %0, t; }" : "=r"(a) : "l"(p));
    return a;
}
__device__ __forceinline__ void cp16(uint32_t d, const void* s) {
    asm volatile("cp.async.ca.shared.global [%0], [%1], 16;" :: "r"(d), "l"(s));
}
#define CP_COMMIT() asm volatile("cp.async.commit_group;")
#define CP_WAIT1()  asm volatile("cp.async.wait_group 1;")
#define CP_WAIT0()  asm volatile("cp.async.wait_group 0;")

__device__ __forceinline__ void ldm4(uint32_t* r, uint32_t a) {
    asm volatile("ldmatrix.sync.aligned.m8n8.x4.shared.b16 {%0,%1,%2,%3}, [%4];"
                 : "=r"(r[0]), "=r"(r[1]), "=r"(r[2]), "=r"(r[3]) : "r"(a));
}
__device__ __forceinline__ void ldm4t(uint32_t* r, uint32_t a) {
    asm volatile("ldmatrix.sync.aligned.m8n8.x4.trans.shared.b16 {%0,%1,%2,%3}, [%4];"
                 : "=r"(r[0]), "=r"(r[1]), "=r"(r[2]), "=r"(r[3]) : "r"(a));
}
__device__ __forceinline__ void mma_bf16(float* d, const uint32_t* a, uint32_t b0, uint32_t b1) {
    asm volatile("mma.sync.aligned.m16n8k16.row.col.f32.bf16.bf16.f32 "
                 "{%0,%1,%2,%3}, {%4,%5,%6,%7}, {%8,%9}, {%0,%1,%2,%3};"
                 : "+f"(d[0]), "+f"(d[1]), "+f"(d[2]), "+f"(d[3])
                 : "r"(a[0]), "r"(a[1]), "r"(a[2]), "r"(a[3]), "r"(b0), "r"(b1));
}
__device__ __forceinline__ void split_bf(float v, __nv_bfloat16& h, __nv_bfloat16& l) {
    h = __float2bfloat16(v);
    l = __float2bfloat16(v - __bfloat162float(h));
}

// ---------------------------------------------------------------------------
// K0: fuse wo into conv: Wf = wc @ wo (bf16 hi/lo row-major), bf = wc@bo + bc
// ---------------------------------------------------------------------------
__global__ __launch_bounds__(256) void k_fuse(const float* __restrict__ wo,
                                              const float* __restrict__ bo,
                                              const float* __restrict__ wc,
                                              const float* __restrict__ bc)
{
    int ob = blockIdx.x * 4;
    int i  = threadIdx.x;
    float a0 = 0.f, a1 = 0.f, a2 = 0.f, a3 = 0.f;
    for (int cc = 0; cc < 256; cc++) {
        float w = wo[cc * 256 + i];
        a0 += wc[(ob + 0) * 256 + cc] * w;
        a1 += wc[(ob + 1) * 256 + cc] * w;
        a2 += wc[(ob + 2) * 256 + cc] * w;
        a3 += wc[(ob + 3) * 256 + cc] * w;
    }
    float vals[4] = {a0, a1, a2, a3};
#pragma unroll
    for (int j = 0; j < 4; j++) {
        __nv_bfloat16 h, l;
        split_bf(vals[j], h, l);
        size_t idx = (size_t)(ob + j) * 256 + i;
        g_wfh[idx] = h; g_wfl[idx] = l;
    }
    if (i < 4) {
        int o = ob + i;
        float s = 0.f;
        for (int c2 = 0; c2 < 256; c2++) s += wc[o * 256 + c2] * bo[c2];
        g_bf[o] = s + bc[o];
    }
}

// ---------------------------------------------------------------------------
// K0b: split wq (pre-scaled by 0.125) / wkv to bf16 hi/lo, row-major [768][256]
// ---------------------------------------------------------------------------
__global__ __launch_bounds__(256) void k_splitw(const float* __restrict__ wq,
                                                const float* __restrict__ wkv)
{
    int i = blockIdx.x * 256 + threadIdx.x;       // 0..196607
    int m = i >> 8, c = i & 255;
    float v = (m < 256) ? wq[m * 256 + c] * 0.125f : wkv[(m - 256) * 256 + c];
    __nv_bfloat16 h, l;
    split_bf(v, h, l);
    g_wqh[i] = h; g_wql[i] = l;
}

// ---------------------------------------------------------------------------
// K0c: split x -> [k=channel][n=b*4096+p] bf16 hi/lo
// ---------------------------------------------------------------------------
__global__ __launch_bounds__(256) void k_splitx(const float* __restrict__ x)
{
    size_t i = (size_t)(blockIdx.x * 256 + threadIdx.x) * 4;     // 8192 blocks
    float4 v = *(const float4*)(x + i);
    size_t o = (size_t)((i >> 12) & 255) * NPIX + ((i >> 20) << 12) + (i & 4095);
    __nv_bfloat16 h0, l0, h1, l1, h2, l2, h3, l3;
    split_bf(v.x, h0, l0); split_bf(v.y, h1, l1);
    split_bf(v.z, h2, l2); split_bf(v.w, h3, l3);
    uint2 uh = make_uint2((uint32_t)__bfloat16_as_ushort(h0) | ((uint32_t)__bfloat16_as_ushort(h1) << 16),
                          (uint32_t)__bfloat16_as_ushort(h2) | ((uint32_t)__bfloat16_as_ushort(h3) << 16));
    uint2 ul = make_uint2((uint32_t)__bfloat16_as_ushort(l0) | ((uint32_t)__bfloat16_as_ushort(l1) << 16),
                          (uint32_t)__bfloat16_as_ushort(l2) | ((uint32_t)__bfloat16_as_ushort(l3) << 16));
    *(uint2*)&g_xh[o] = uh;
    *(uint2*)&g_xl[o] = ul;
}

// ---------------------------------------------------------------------------
// K1: QKV projection on tensor cores. C[768, 32768] = Wqkv @ X, split-bf16 x3.
// A smem [128 m][40], B smem [32 k][136] (ldmatrix .trans). Epilogue transposes
// through smem and writes g_qkv [n][768] fp32 coalesced.
// ---------------------------------------------------------------------------
__global__ __launch_bounds__(256) void k_qkv_tc()
{
    __shared__ __align__(16) __nv_bfloat16 sA[2][128 * 40];
    __shared__ __align__(16) __nv_bfloat16 sB[2][32 * 136];
    int tid = threadIdx.x, lane = tid & 31, wrp = tid >> 5;
    int wm = wrp >> 1, wn = wrp & 1;
    int mt = blockIdx.y, n0 = blockIdx.x << 7;
    int m0 = mt << 7;
    uint32_t sAu = smem_u32(sA), sBu = smem_u32(sB);

    float acc[2][8][4];
#pragma unroll
    for (int a = 0; a < 2; a++)
#pragma unroll
        for (int b = 0; b < 8; b++)
#pragma unroll
            for (int c = 0; c < 4; c++) acc[a][b][c] = 0.f;

    int ar = tid >> 1, ac = (tid & 1) << 4;
    int br = tid >> 3, bc = (tid & 7) << 4;

    auto issue = [&](int s, int buf) {
        int p = s >> 3, kk = (s & 7) << 5;
        const __nv_bfloat16* A = (p == 1 ? g_wql : g_wqh) + (size_t)(m0 + ar) * 256 + kk + ac;
        uint32_t da = sAu + buf * 10240 + ((ar * 40 + ac) << 1);
        cp16(da, A); cp16(da + 16, A + 8);
        const __nv_bfloat16* B = (p == 2 ? g_xl : g_xh) + (size_t)(kk + br) * NPIX + n0 + bc;
        uint32_t db = sBu + buf * 8704 + ((br * 136 + bc) << 1);
        cp16(db, B); cp16(db + 16, B + 8);
    };
    auto compute = [&](int buf) {
        uint32_t ab = sAu + buf * 10240;
        uint32_t bb = sBu + buf * 8704;
#pragma unroll
        for (int kh = 0; kh < 32; kh += 16) {
            uint32_t af[2][4];
#pragma unroll
            for (int mf = 0; mf < 2; mf++)
                ldm4(af[mf], ab + (((wm * 32 + mf * 16 + (lane & 15)) * 40
                                   + kh + ((lane >> 4) << 3)) << 1));
            uint32_t bf[4][4];
#pragma unroll
            for (int nb = 0; nb < 4; nb++)
                ldm4t(bf[nb], bb + (((kh + ((lane >> 3) & 1) * 8 + (lane & 7)) * 136
                                     + wn * 64 + nb * 16 + ((lane >> 4) << 3)) << 1));
#pragma unroll
            for (int mf = 0; mf < 2; mf++)
#pragma unroll
                for (int nb = 0; nb < 4; nb++) {
                    mma_bf16(acc[mf][nb * 2],     af[mf], bf[nb][0], bf[nb][1]);
                    mma_bf16(acc[mf][nb * 2 + 1], af[mf], bf[nb][2], bf[nb][3]);
                }
        }
    };

    issue(0, 0); CP_COMMIT();
    for (int s = 0; s < 24; s++) {
        int buf = s & 1;
        if (s + 1 < 24) { issue(s + 1, buf ^ 1); CP_COMMIT(); CP_WAIT1(); }
        else             { CP_WAIT0(); }
        __syncthreads();
        compute(buf);
        __syncthreads();
    }

    // epilogue: transpose per 32-row m-quarter via smem, write [n][768] fp32
    float* tb = (float*)sA;                       // 128*33 floats = 16896B < 20480B
    int g = lane >> 2, q = lane & 3;
#pragma unroll
    for (int mq = 0; mq < 4; mq++) {
        if (wm == mq) {
#pragma unroll
            for (int mf = 0; mf < 2; mf++)
#pragma unroll
                for (int nf = 0; nf < 8; nf++) {
                    int nl = wn * 64 + nf * 8 + q * 2;
                    int ml = mf * 16 + g;
                    tb[nl * 33 + ml]            = acc[mf][nf][0];
                    tb[(nl + 1) * 33 + ml]      = acc[mf][nf][1];
                    tb[nl * 33 + ml + 8]        = acc[mf][nf][2];
                    tb[(nl + 1) * 33 + ml + 8]  = acc[mf][nf][3];
                }
        }
        __syncthreads();
        int nl = tid >> 1, half = tid & 1;
        const float* src = tb + nl * 33 + half * 16;
        float* dst = g_qkv + (size_t)(n0 + nl) * QKVC + m0 + mq * 32 + half * 16;
#pragma unroll
        for (int u = 0; u < 4; u++)
            *(float4*)(dst + u * 4) = make_float4(src[u*4], src[u*4+1], src[u*4+2], src[u*4+3]);
        __syncthreads();
    }
}

// ---------------------------------------------------------------------------
// K2: halo attention (fp32, unchanged core; output as bf16 hi/lo pixel-major)
// ---------------------------------------------------------------------------
__global__ __launch_bounds__(256) void k_attn(const float* __restrict__ relh,
                                              const float* __restrict__ relw)
{
    extern __shared__ float sm[];
    float* qs   = sm;
    float* ks   = sm + 4096;
    float* vs   = sm + 20480;
    float* lw   = sm + 37888;
    float* lh   = sm + 38912;
    float* msk  = sm + 39936;
    float* simb = sm + 40192;
    float* srh  = simb;
    float* srw  = simb + 2048;

    int t  = threadIdx.x;
    int nb = blockIdx.x;
    int hh = blockIdx.y;
    int bi = nb >> 6;
    int tb = nb & 63;
    int bh = tb >> 3, bw = tb & 7;
    int hco = hh * 64;

    for (int idx = t; idx < 1984; idx += 256) {
        int r = idx >> 6, dd = idx & 63;
        srh[r * 65 + dd] = relh[idx];
        srw[r * 65 + dd] = relw[idx];
    }
    {
        int qi = t >> 2, dq = t & 3;
        int qx = qi >> 3, qy = qi & 7;
        const float* src = g_qkv +
            (size_t)(bi * 4096 + (bh * 8 + qx) * 64 + (bw * 8 + qy)) * QKVC + hco;
#pragma unroll
        for (int u = 0; u < 4; u++) {
            int dd = dq * 16 + u * 4;
            float4 v = *(const float4*)(src + dd);
            qs[(dd + 0) * 64 + qi] = v.x; qs[(dd + 1) * 64 + qi] = v.y;
            qs[(dd + 2) * 64 + qi] = v.z; qs[(dd + 3) * 64 + qi] = v.w;
        }
    }
    {
        int dq = t & 3;
        int jb = t >> 2;
#pragma unroll
        for (int rep = 0; rep < 4; rep++) {
            int j  = rep * 64 + jb;
            int ki = j >> 4, kj = j & 15;
            int gh = bh * 8 - 4 + ki, gw = bw * 8 - 4 + kj;
            bool valid = ((unsigned)gh < 64u) && ((unsigned)gw < 64u);
            size_t off = valid ? (size_t)(bi * 4096 + gh * 64 + gw) * QKVC + hco : 0;
            const float* src = g_qkv + off;
#pragma unroll
            for (int u = 0; u < 4; u++) {
                int dd = dq * 16 + u * 4;
                float4 kv = valid ? *(const float4*)(src + 256 + dd) : make_float4(0, 0, 0, 0);
                float4 vv = valid ? *(const float4*)(src + 512 + dd) : make_float4(0, 0, 0, 0);
                ks[(dd + 0) * 256 + j] = kv.x; ks[(dd + 1) * 256 + j] = kv.y;
                ks[(dd + 2) * 256 + j] = kv.z; ks[(dd + 3) * 256 + j] = kv.w;
                *(float4*)&vs[j * 68 + dd] = vv;
            }
            if (dq == 0) msk[j] = valid ? 0.0f : -3.0e38f;
        }
    }
    __syncthreads();

#pragma unroll
    for (int m = 0; m < 8; m++) {
        int wk  = t + 256 * m;
        int qi  = wk >> 5;
        int sel = (wk >> 4) & 1;
        int pos = wk & 15;
        int qx = qi >> 3, qy = qi & 7;
        int ridx = pos - (sel ? qy : qx) + 15;
        const float* rrow = (sel ? srw : srh) + ridx * 65;
        float a = 0.f;
#pragma unroll 8
        for (int dd = 0; dd < 64; dd++) a += qs[dd * 64 + qi] * rrow[dd];
        (sel ? lw : lh)[qi * 16 + pos] = a;
    }
    __syncthreads();

    int tq = t >> 4, tj = t & 15;
#pragma unroll
    for (int jb4 = 0; jb4 < 4; jb4++) {
        int j0 = jb4 * 64;
        float acc[4][4] = {};
#pragma unroll 8
        for (int dd = 0; dd < 64; dd++) {
            float4 av = *(float4*)&qs[dd * 64 + tq * 4];
            float4 bv = *(float4*)&ks[dd * 256 + j0 + tj * 4];
            float a[4] = {av.x, av.y, av.z, av.w};
            float b[4] = {bv.x, bv.y, bv.z, bv.w};
#pragma unroll
            for (int iq = 0; iq < 4; iq++)
#pragma unroll
                for (int ij = 0; ij < 4; ij++)
                    acc[iq][ij] += a[iq] * b[ij];
        }
#pragma unroll
        for (int iq = 0; iq < 4; iq++) {
            int qi = tq * 4 + iq;
#pragma unroll
            for (int ij = 0; ij < 4; ij++) {
                int j = j0 + tj * 4 + ij;
                simb[qi * 260 + j] = acc[iq][ij] + lw[qi * 16 + (j & 15)]
                                   + lh[qi * 16 + (j >> 4)] + msk[j];
            }
        }
    }
    __syncthreads();

    {
        int row = t >> 2, seg = t & 3;
        float* srow = simb + row * 260 + seg * 64;
        float mx = -3.4e38f;
#pragma unroll 8
        for (int j = 0; j < 64; j++) mx = fmaxf(mx, srow[j]);
        mx = fmaxf(mx, __shfl_xor_sync(0xffffffffu, mx, 1));
        mx = fmaxf(mx, __shfl_xor_sync(0xffffffffu, mx, 2));
        float sum = 0.f;
#pragma unroll 8
        for (int j = 0; j < 64; j++) { float e = __expf(srow[j] - mx); srow[j] = e; sum += e; }
        sum += __shfl_xor_sync(0xffffffffu, sum, 1);
        sum += __shfl_xor_sync(0xffffffffu, sum, 2);
        float inv = 1.0f / sum;
#pragma unroll 8
        for (int j = 0; j < 64; j++) srow[j] *= inv;
    }
    __syncthreads();

    float o[4][4] = {};
    {
        const float* s0 = simb + (size_t)(tq * 4 + 0) * 260;
        const float* s1 = simb + (size_t)(tq * 4 + 1) * 260;
        const float* s2 = simb + (size_t)(tq * 4 + 2) * 260;
        const float* s3 = simb + (size_t)(tq * 4 + 3) * 260;
#pragma unroll 4
        for (int j = 0; j < 256; j++) {
            float4 bv = *(float4*)&vs[j * 68 + tj * 4];
            float b[4] = {bv.x, bv.y, bv.z, bv.w};
            float a0 = s0[j], a1 = s1[j], a2 = s2[j], a3 = s3[j];
#pragma unroll
            for (int id = 0; id < 4; id++) {
                o[0][id] += a0 * b[id];
                o[1][id] += a1 * b[id];
                o[2][id] += a2 * b[id];
                o[3][id] += a3 * b[id];
            }
        }
    }
#pragma unroll
    for (int iq = 0; iq < 4; iq++) {
        int qi = tq * 4 + iq;
        int qx = qi >> 3, qy = qi & 7;
        size_t p = (size_t)(bi * 4096 + (bh * 8 + qx) * 64 + (bw * 8 + qy));
        size_t base = p * 256 + hco + tj * 4;
        unsigned short hs[4], ls[4];
#pragma unroll
        for (int id = 0; id < 4; id++) {
            __nv_bfloat16 hb, lb;
            split_bf(o[iq][id], hb, lb);
            hs[id] = __bfloat16_as_ushort(hb);
            ls[id] = __bfloat16_as_ushort(lb);
        }
        *(uint2*)&g_bh[base] = make_uint2((uint32_t)hs[0] | ((uint32_t)hs[1] << 16),
                                          (uint32_t)hs[2] | ((uint32_t)hs[3] << 16));
        *(uint2*)&g_bl[base] = make_uint2((uint32_t)ls[0] | ((uint32_t)ls[1] << 16),
                                          (uint32_t)ls[2] | ((uint32_t)ls[3] << 16));
    }
}

// ---------------------------------------------------------------------------
// K3: output GEMM on tensor cores + PixelShuffle epilogue.
// C[1024, 32768] = Wf @ attn^T, split-bf16 x3. B smem [n][k] (non-trans ldmatrix).
// ---------------------------------------------------------------------------
__global__ __launch_bounds__(256) void k_out_tc(float* __restrict__ out)
{
    __shared__ __align__(16) __nv_bfloat16 sA[2][128 * 40];
    __shared__ __align__(16) __nv_bfloat16 sB[2][128 * 40];
    int tid = threadIdx.x, lane = tid & 31, wrp = tid >> 5;
    int wm = wrp >> 1, wn = wrp & 1;
    int mt = blockIdx.y, n0 = blockIdx.x << 7;
    int m0 = mt << 7;
    uint32_t sAu = smem_u32(sA), sBu = smem_u32(sB);

    float acc[2][8][4];
#pragma unroll
    for (int a = 0; a < 2; a++)
#pragma unroll
        for (int b = 0; b < 8; b++)
#pragma unroll
            for (int c = 0; c < 4; c++) acc[a][b][c] = 0.f;

    int ar = tid >> 1, ac = (tid & 1) << 4;

    auto issue = [&](int s, int buf) {
        int p = s >> 3, kk = (s & 7) << 5;
        const __nv_bfloat16* A = (p == 1 ? g_wfl : g_wfh) + (size_t)(m0 + ar) * 256 + kk + ac;
        uint32_t da = sAu + buf * 10240 + ((ar * 40 + ac) << 1);
        cp16(da, A); cp16(da + 16, A + 8);
        const __nv_bfloat16* B = (p == 2 ? g_bl : g_bh) + (size_t)(n0 + ar) * 256 + kk + ac;
        uint32_t db = sBu + buf * 10240 + ((ar * 40 + ac) << 1);
        cp16(db, B); cp16(db + 16, B + 8);
    };
    auto compute = [&](int buf) {
        uint32_t ab = sAu + buf * 10240;
        uint32_t bb = sBu + buf * 10240;
#pragma unroll
        for (int kh = 0; kh < 32; kh += 16) {
            uint32_t af[2][4];
#pragma unroll
            for (int mf = 0; mf < 2; mf++)
                ldm4(af[mf], ab + (((wm * 32 + mf * 16 + (lane & 15)) * 40
                                   + kh + ((lane >> 4) << 3)) << 1));
            uint32_t bf[4][4];
#pragma unroll
            for (int nb = 0; nb < 4; nb++)
                ldm4(bf[nb], bb + (((wn * 64 + nb * 16 + ((lane >> 4) << 3) + (lane & 7)) * 40
                                   + kh + (((lane >> 3) & 1) << 3)) << 1));
#pragma unroll
            for (int mf = 0; mf < 2; mf++)
#pragma unroll
                for (int nb = 0; nb < 4; nb++) {
                    mma_bf16(acc[mf][nb * 2],     af[mf], bf[nb][0], bf[nb][1]);
                    mma_bf16(acc[mf][nb * 2 + 1], af[mf], bf[nb][2], bf[nb][3]);
                }
        }
    };

    issue(0, 0); CP_COMMIT();
    for (int s = 0; s < 24; s++) {
        int buf = s & 1;
        if (s + 1 < 24) { issue(s + 1, buf ^ 1); CP_COMMIT(); CP_WAIT1(); }
        else             { CP_WAIT0(); }
        __syncthreads();
        compute(buf);
        __syncthreads();
    }

    // epilogue: pixel-shuffle scatter. channel m=(cch,r,s): out[b][cch][2h+r][2w+s]
    int g = lane >> 2, q = lane & 3;
    int h0 = (n0 & 4095) >> 6, bimg = n0 >> 12;
    int hrow = h0 + wn;
#pragma unroll
    for (int mf = 0; mf < 2; mf++) {
#pragma unroll
        for (int which = 0; which < 2; which++) {
            int mm = m0 + wm * 32 + mf * 16 + g + which * 8;
            float bias = g_bf[mm];
            int cch = mm >> 2, r = (mm >> 1) & 1, s2 = mm & 1;
            float* rowp = out + ((size_t)(bimg * 256 + cch) * 128 + 2 * hrow + r) * 128 + s2;
#pragma unroll
            for (int nf = 0; nf < 8; nf++) {
                int w0 = nf * 8 + 2 * q;
                rowp[2 * w0]     = acc[mf][nf][which * 2 + 0] + bias;
                rowp[2 * w0 + 2] = acc[mf][nf][which * 2 + 1] + bias;
            }
        }
    }
}

// ---------------------------------------------------------------------------
extern "C" void kernel_launch(void* const* d_in, const int* in_sizes, int n_in,
                              void* d_out, int out_size)
{
    const float* x    = (const float*)d_in[0];
    const float* wq   = (const float*)d_in[1];
    const float* wkv  = (const float*)d_in[2];
    const float* wo   = (const float*)d_in[3];
    const float* bo   = (const float*)d_in[4];
    const float* relh = (const float*)d_in[5];
    const float* relw = (const float*)d_in[6];
    const float* wc   = (const float*)d_in[7];
    const float* bc   = (const float*)d_in[8];
    float* out = (float*)d_out;

    cudaFuncSetAttribute(k_attn, cudaFuncAttributeMaxDynamicSharedMemorySize, 227328);

    k_fuse<<<256, 256>>>(wo, bo, wc, bc);
    k_splitw<<<768, 256>>>(wq, wkv);
    k_splitx<<<8192, 256>>>(x);
    k_qkv_tc<<<dim3(256, 6), 256>>>();
    k_attn<<<dim3(512, 4), 256, 227328>>>(relh, relw);
    k_out_tc<<<dim3(256, 8), 256>>>(out);
}

// round 5
// speedup vs baseline: 2.1580x; 1.4169x over previous
#include <cuda_runtime.h>
#include <cuda_bf16.h>
#include <stdint.h>

#define NPIX 32768            // B*H*W
#define QKVC 768

// Scratch (device globals; 16B-aligned)
__device__ __align__(16) __nv_bfloat16 g_qh[NPIX * QKVC];  // qkv hi, [pixel][q|k|v]
__device__ __align__(16) __nv_bfloat16 g_ql[NPIX * QKVC];  // qkv lo
__device__ __align__(16) __nv_bfloat16 g_bh[NPIX * 256];   // attn out hi, [n][256]
__device__ __align__(16) __nv_bfloat16 g_bl[NPIX * 256];   // attn out lo
__device__ __align__(16) __nv_bfloat16 g_wfh[1024 * 256];  // fused conv W hi, [m][k]
__device__ __align__(16) __nv_bfloat16 g_wfl[1024 * 256];
__device__ __align__(16) __nv_bfloat16 g_wqh[QKVC * 256];  // qkv W hi (q pre-scaled), [m][k]
__device__ __align__(16) __nv_bfloat16 g_wql[QKVC * 256];
__device__ __align__(16) __nv_bfloat16 g_xh[256 * NPIX];   // x split, [k][n]
__device__ __align__(16) __nv_bfloat16 g_xl[256 * NPIX];
__device__ float g_bf[1024];

// ---------------------------------------------------------------------------
// helpers (non-arch-specific PTX only: cp.async / ldmatrix / mma.sync)
// ---------------------------------------------------------------------------
__device__ __forceinline__ uint32_t smem_u32(const void* p) {
    uint32_t a;
    asm("{ .reg .u64 t; cvta.to.shared.u64 t, %1; cvt.u32.u64 %0, t; }" : "=r"(a) : "l"(p));
    return a;
}
__device__ __forceinline__ void cp16(uint32_t d, const void* s) {
    asm volatile("cp.async.ca.shared.global [%0], [%1], 16;" :: "r"(d), "l"(s));
}
#define CP_COMMIT() asm volatile("cp.async.commit_group;")
#define CP_WAIT1()  asm volatile("cp.async.wait_group 1;")
#define CP_WAIT0()  asm volatile("cp.async.wait_group 0;")

__device__ __forceinline__ void ldm4(uint32_t* r, uint32_t a) {
    asm volatile("ldmatrix.sync.aligned.m8n8.x4.shared.b16 {%0,%1,%2,%3}, [%4];"
                 : "=r"(r[0]), "=r"(r[1]), "=r"(r[2]), "=r"(r[3]) : "r"(a));
}
__device__ __forceinline__ void ldm4t(uint32_t* r, uint32_t a) {
    asm volatile("ldmatrix.sync.aligned.m8n8.x4.trans.shared.b16 {%0,%1,%2,%3}, [%4];"
                 : "=r"(r[0]), "=r"(r[1]), "=r"(r[2]), "=r"(r[3]) : "r"(a));
}
__device__ __forceinline__ void mma_bf16(float* d, const uint32_t* a, uint32_t b0, uint32_t b1) {
    asm volatile("mma.sync.aligned.m16n8k16.row.col.f32.bf16.bf16.f32 "
                 "{%0,%1,%2,%3}, {%4,%5,%6,%7}, {%8,%9}, {%0,%1,%2,%3};"
                 : "+f"(d[0]), "+f"(d[1]), "+f"(d[2]), "+f"(d[3])
                 : "r"(a[0]), "r"(a[1]), "r"(a[2]), "r"(a[3]), "r"(b0), "r"(b1));
}
__device__ __forceinline__ void split_bf(float v, __nv_bfloat16& h, __nv_bfloat16& l) {
    h = __float2bfloat16(v);
    l = __float2bfloat16(v - __bfloat162float(h));
}
__device__ __forceinline__ uint32_t packbf(__nv_bfloat16 a, __nv_bfloat16 b) {
    return (uint32_t)__bfloat16_as_ushort(a) | ((uint32_t)__bfloat16_as_ushort(b) << 16);
}

// ---------------------------------------------------------------------------
// K0: fuse wo into conv: Wf = wc @ wo (bf16 hi/lo row-major), bf = wc@bo + bc
// ---------------------------------------------------------------------------
__global__ __launch_bounds__(256) void k_fuse(const float* __restrict__ wo,
                                              const float* __restrict__ bo,
                                              const float* __restrict__ wc,
                                              const float* __restrict__ bc)
{
    int ob = blockIdx.x * 4;
    int i  = threadIdx.x;
    float a0 = 0.f, a1 = 0.f, a2 = 0.f, a3 = 0.f;
    for (int cc = 0; cc < 256; cc++) {
        float w = wo[cc * 256 + i];
        a0 += wc[(ob + 0) * 256 + cc] * w;
        a1 += wc[(ob + 1) * 256 + cc] * w;
        a2 += wc[(ob + 2) * 256 + cc] * w;
        a3 += wc[(ob + 3) * 256 + cc] * w;
    }
    float vals[4] = {a0, a1, a2, a3};
#pragma unroll
    for (int j = 0; j < 4; j++) {
        __nv_bfloat16 h, l;
        split_bf(vals[j], h, l);
        size_t idx = (size_t)(ob + j) * 256 + i;
        g_wfh[idx] = h; g_wfl[idx] = l;
    }
    if (i < 4) {
        int o = ob + i;
        float s = 0.f;
        for (int c2 = 0; c2 < 256; c2++) s += wc[o * 256 + c2] * bo[c2];
        g_bf[o] = s + bc[o];
    }
}

// ---------------------------------------------------------------------------
// K0b: split wq (pre-scaled by 0.125) / wkv to bf16 hi/lo, row-major [768][256]
// ---------------------------------------------------------------------------
__global__ __launch_bounds__(256) void k_splitw(const float* __restrict__ wq,
                                                const float* __restrict__ wkv)
{
    int i = blockIdx.x * 256 + threadIdx.x;
    int m = i >> 8, c = i & 255;
    float v = (m < 256) ? wq[m * 256 + c] * 0.125f : wkv[(m - 256) * 256 + c];
    __nv_bfloat16 h, l;
    split_bf(v, h, l);
    g_wqh[i] = h; g_wql[i] = l;
}

// ---------------------------------------------------------------------------
// K0c: split x -> [k=channel][n=b*4096+p] bf16 hi/lo
// ---------------------------------------------------------------------------
__global__ __launch_bounds__(256) void k_splitx(const float* __restrict__ x)
{
    size_t i = (size_t)(blockIdx.x * 256 + threadIdx.x) * 4;
    float4 v = *(const float4*)(x + i);
    size_t o = (size_t)((i >> 12) & 255) * NPIX + ((i >> 20) << 12) + (i & 4095);
    __nv_bfloat16 h0, l0, h1, l1, h2, l2, h3, l3;
    split_bf(v.x, h0, l0); split_bf(v.y, h1, l1);
    split_bf(v.z, h2, l2); split_bf(v.w, h3, l3);
    *(uint2*)&g_xh[o] = make_uint2(packbf(h0, h1), packbf(h2, h3));
    *(uint2*)&g_xl[o] = make_uint2(packbf(l0, l1), packbf(l2, l3));
}

// ---------------------------------------------------------------------------
// K1: QKV projection (tensor cores). C[768,32768] = Wqkv @ X, split-bf16 x3.
// Epilogue transposes via smem and writes g_qh/g_ql [pixel][768] bf16 hi/lo.
// ---------------------------------------------------------------------------
__global__ __launch_bounds__(256) void k_qkv_tc()
{
    __shared__ __align__(16) __nv_bfloat16 sA[2][128 * 40];
    __shared__ __align__(16) __nv_bfloat16 sB[2][32 * 136];
    int tid = threadIdx.x, lane = tid & 31, wrp = tid >> 5;
    int wm = wrp >> 1, wn = wrp & 1;
    int mt = blockIdx.y, n0 = blockIdx.x << 7;
    int m0 = mt << 7;
    uint32_t sAu = smem_u32(sA), sBu = smem_u32(sB);

    float acc[2][8][4];
#pragma unroll
    for (int a = 0; a < 2; a++)
#pragma unroll
        for (int b = 0; b < 8; b++)
#pragma unroll
            for (int c = 0; c < 4; c++) acc[a][b][c] = 0.f;

    int ar = tid >> 1, ac = (tid & 1) << 4;
    int br = tid >> 3, bc = (tid & 7) << 4;

    auto issue = [&](int s, int buf) {
        int p = s >> 3, kk = (s & 7) << 5;
        const __nv_bfloat16* A = (p == 1 ? g_wql : g_wqh) + (size_t)(m0 + ar) * 256 + kk + ac;
        uint32_t da = sAu + buf * 10240 + ((ar * 40 + ac) << 1);
        cp16(da, A); cp16(da + 16, A + 8);
        const __nv_bfloat16* B = (p == 2 ? g_xl : g_xh) + (size_t)(kk + br) * NPIX + n0 + bc;
        uint32_t db = sBu + buf * 8704 + ((br * 136 + bc) << 1);
        cp16(db, B); cp16(db + 16, B + 8);
    };
    auto compute = [&](int buf) {
        uint32_t ab = sAu + buf * 10240;
        uint32_t bb = sBu + buf * 8704;
#pragma unroll
        for (int kh = 0; kh < 32; kh += 16) {
            uint32_t af[2][4];
#pragma unroll
            for (int mf = 0; mf < 2; mf++)
                ldm4(af[mf], ab + (((wm * 32 + mf * 16 + (lane & 15)) * 40
                                   + kh + ((lane >> 4) << 3)) << 1));
            uint32_t bf[4][4];
#pragma unroll
            for (int nb = 0; nb < 4; nb++)
                ldm4t(bf[nb], bb + (((kh + ((lane >> 3) & 1) * 8 + (lane & 7)) * 136
                                     + wn * 64 + nb * 16 + ((lane >> 4) << 3)) << 1));
#pragma unroll
            for (int mf = 0; mf < 2; mf++)
#pragma unroll
                for (int nb = 0; nb < 4; nb++) {
                    mma_bf16(acc[mf][nb * 2],     af[mf], bf[nb][0], bf[nb][1]);
                    mma_bf16(acc[mf][nb * 2 + 1], af[mf], bf[nb][2], bf[nb][3]);
                }
        }
    };

    issue(0, 0); CP_COMMIT();
    for (int s = 0; s < 24; s++) {
        int buf = s & 1;
        if (s + 1 < 24) { issue(s + 1, buf ^ 1); CP_COMMIT(); CP_WAIT1(); }
        else             { CP_WAIT0(); }
        __syncthreads();
        compute(buf);
        __syncthreads();
    }

    // epilogue: transpose per 32-row m-quarter via smem, write bf16 hi/lo
    float* tb = (float*)sA;
    int g = lane >> 2, q = lane & 3;
#pragma unroll
    for (int mq = 0; mq < 4; mq++) {
        if (wm == mq) {
#pragma unroll
            for (int mf = 0; mf < 2; mf++)
#pragma unroll
                for (int nf = 0; nf < 8; nf++) {
                    int nl = wn * 64 + nf * 8 + q * 2;
                    int ml = mf * 16 + g;
                    tb[nl * 33 + ml]            = acc[mf][nf][0];
                    tb[(nl + 1) * 33 + ml]      = acc[mf][nf][1];
                    tb[nl * 33 + ml + 8]        = acc[mf][nf][2];
                    tb[(nl + 1) * 33 + ml + 8]  = acc[mf][nf][3];
                }
        }
        __syncthreads();
        int nl = tid >> 1, half = tid & 1;
        const float* src = tb + nl * 33 + half * 16;
        size_t dst = (size_t)(n0 + nl) * QKVC + m0 + mq * 32 + half * 16;
        unsigned short hs[16], ls[16];
#pragma unroll
        for (int u = 0; u < 16; u++) {
            float v = src[u];
            __nv_bfloat16 h, l;
            split_bf(v, h, l);
            hs[u] = __bfloat16_as_ushort(h); ls[u] = __bfloat16_as_ushort(l);
        }
        *(uint4*)&g_qh[dst]     = *(uint4*)&hs[0];
        *(uint4*)&g_qh[dst + 8] = *(uint4*)&hs[8];
        *(uint4*)&g_ql[dst]     = *(uint4*)&ls[0];
        *(uint4*)&g_ql[dst + 8] = *(uint4*)&ls[8];
        __syncthreads();
    }
}

// ---------------------------------------------------------------------------
// K2: tensor-core halo attention. CTA = (window, head), 8 warps.
// warp = (wm = m-tile of 16 q-rows, wn = 128-key half). sim in registers.
// smem layout (bytes):
//   0      sQh [64][72] bf16        (Red [64][68] fp32 overlays after QK)
//   9216   sQl [64][72]
//   18432  sKh [256][72] bf16       (V hi replaces K hi after QK)
//   55296  sKl [256][72]
//   92160  srh [31][65] fp32; srw @ +8064   (lw/lh/rmx/rsum overlay after rel)
// total 108288
// ---------------------------------------------------------------------------
#define AT_SQH  0
#define AT_SQL  9216
#define AT_SK   18432
#define AT_SKL  55296
#define AT_REL  92160
#define AT_LW   92160
#define AT_LH   96256
#define AT_RMX  100352
#define AT_RSUM 100864
#define AT_SMEM 108288

__global__ void __launch_bounds__(256, 2) k_attn_tc(const float* __restrict__ relh,
                                                    const float* __restrict__ relw)
{
    extern __shared__ char smc[];
    uint32_t sb = smem_u32(smc);
    int t = threadIdx.x, lane = t & 31, wid = t >> 5;
    int wm = wid >> 1, wn = wid & 1;
    int nbk = blockIdx.x, hh = blockIdx.y;
    int bi = nbk >> 6, tbw = nbk & 63;
    int bh = tbw >> 3, bw = tbw & 7;
    int hco = hh * 64;

    uint32_t qhB = sb + AT_SQH, qlB = sb + AT_SQL;
    uint32_t khB = sb + AT_SK,  klB = sb + AT_SKL;

    // ---- loads: Q (hi/lo), K (hi/lo, zero-filled), rel tables ----
    {
        int chunk = t & 7, rr = t >> 3;
#pragma unroll
        for (int p = 0; p < 2; p++) {
            int row = p * 32 + rr;
            int qx = row >> 3, qy = row & 7;
            size_t pix = (size_t)(bi * 4096 + (bh * 8 + qx) * 64 + bw * 8 + qy) * QKVC + hco;
            ((uint4*)(smc + AT_SQH))[row * 9 + chunk] = *(const uint4*)(g_qh + pix + chunk * 8);
            ((uint4*)(smc + AT_SQL))[row * 9 + chunk] = *(const uint4*)(g_ql + pix + chunk * 8);
        }
#pragma unroll
        for (int p = 0; p < 8; p++) {
            int row = p * 32 + rr;
            int ki = row >> 4, kj = row & 15;
            int gh = bh * 8 - 4 + ki, gw = bw * 8 - 4 + kj;
            bool valid = ((unsigned)gh < 64u) && ((unsigned)gw < 64u);
            size_t pix = (size_t)(valid ? bi * 4096 + gh * 64 + gw : bi * 4096) * QKVC
                       + 256 + hco + chunk * 8;
            uint4 z = make_uint4(0, 0, 0, 0);
            uint4 vh = valid ? *(const uint4*)(g_qh + pix) : z;
            uint4 vl = valid ? *(const uint4*)(g_ql + pix) : z;
            ((uint4*)(smc + AT_SK ))[row * 9 + chunk] = vh;
            ((uint4*)(smc + AT_SKL))[row * 9 + chunk] = vl;
        }
        float* srh = (float*)(smc + AT_REL);
        float* srw = (float*)(smc + AT_REL + 8064);
        for (int idx = t; idx < 1984; idx += 256) {
            int r = idx >> 6, dd = idx & 63;
            srh[r * 65 + dd] = relh[idx];
            srw[r * 65 + dd] = relw[idx];
        }
    }
    __syncthreads();

    // ---- rel logits into registers (tables die, then lw/lh overlay them) ----
    float rv[8];
    {
        const float* srh = (const float*)(smc + AT_REL);
        const float* srw = (const float*)(smc + AT_REL + 8064);
        const __nv_bfloat16* Qh = (const __nv_bfloat16*)(smc + AT_SQH);
        const __nv_bfloat16* Ql = (const __nv_bfloat16*)(smc + AT_SQL);
#pragma unroll
        for (int m = 0; m < 8; m++) {
            int wk = t + 256 * m;
            int qi = wk >> 5, sel = (wk >> 4) & 1, pos = wk & 15;
            int qx = qi >> 3, qy = qi & 7;
            int ridx = pos - (sel ? qy : qx) + 15;
            const float* rrow = (sel ? srw : srh) + ridx * 65;
            const __nv_bfloat16* qh = Qh + qi * 72;
            const __nv_bfloat16* ql = Ql + qi * 72;
            float a = 0.f;
#pragma unroll 16
            for (int dd = 0; dd < 64; dd++)
                a += (__bfloat162float(qh[dd]) + __bfloat162float(ql[dd])) * rrow[dd];
            rv[m] = a;
        }
    }
    __syncthreads();           // table reads done everywhere
    {
        float* lw = (float*)(smc + AT_LW);
        float* lh = (float*)(smc + AT_LH);
#pragma unroll
        for (int m = 0; m < 8; m++) {
            int wk = t + 256 * m;
            int qi = wk >> 5, sel = (wk >> 4) & 1, pos = wk & 15;
            (sel ? lw : lh)[qi * 16 + pos] = rv[m];
        }
    }

    // ---- QK^T: 3-term split mma, sim in registers ----
    float s[16][4];
#pragma unroll
    for (int a = 0; a < 16; a++)
#pragma unroll
        for (int b = 0; b < 4; b++) s[a][b] = 0.f;
#pragma unroll
    for (int kt = 0; kt < 4; kt++) {
        uint32_t ah[4], al[4];
        uint32_t aoff = (((wm * 16 + (lane & 15)) * 72 + kt * 16 + ((lane >> 4) << 3)) << 1);
        ldm4(ah, qhB + aoff);
        ldm4(al, qlB + aoff);
#pragma unroll
        for (int nb = 0; nb < 8; nb++) {
            uint32_t boff = (((wn * 128 + nb * 16 + ((lane >> 4) << 3) + (lane & 7)) * 72
                             + kt * 16 + (((lane >> 3) & 1) << 3)) << 1);
            uint32_t bh4[4], bl4[4];
            ldm4(bh4, khB + boff);
            ldm4(bl4, klB + boff);
            mma_bf16(s[nb * 2],     ah, bh4[0], bh4[1]);
            mma_bf16(s[nb * 2],     al, bh4[0], bh4[1]);
            mma_bf16(s[nb * 2],     ah, bl4[0], bl4[1]);
            mma_bf16(s[nb * 2 + 1], ah, bh4[2], bh4[3]);
            mma_bf16(s[nb * 2 + 1], al, bh4[2], bh4[3]);
            mma_bf16(s[nb * 2 + 1], ah, bl4[2], bl4[3]);
        }
    }
    __syncthreads();           // K fully consumed by all warps

    // ---- prefetch V into K buffers while we do fixup + softmax ----
    {
        int chunk = t & 7, rr = t >> 3;
#pragma unroll
        for (int p = 0; p < 8; p++) {
            int row = p * 32 + rr;
            int ki = row >> 4, kj = row & 15;
            int gh = bh * 8 - 4 + ki, gw = bw * 8 - 4 + kj;
            bool valid = ((unsigned)gh < 64u) && ((unsigned)gw < 64u);
            size_t pix = (size_t)(valid ? bi * 4096 + gh * 64 + gw : bi * 4096) * QKVC
                       + 512 + hco + chunk * 8;
            uint32_t doff = (uint32_t)(row * 9 + chunk) << 4;
            cp16(khB + doff, g_qh + pix);
            cp16(klB + doff, g_ql + pix);
        }
        CP_COMMIT();
    }

    // ---- fixup: rel logits + mask (arithmetic) ----
    {
        const float* lw = (const float*)(smc + AT_LW);
        const float* lh = (const float*)(smc + AT_LH);
        int g = lane >> 2, tt = lane & 3;
#pragma unroll
        for (int nt = 0; nt < 16; nt++) {
            int jbase = wn * 128 + nt * 8 + 2 * tt;
#pragma unroll
            for (int e = 0; e < 4; e++) {
                int row = wm * 16 + g + ((e >= 2) ? 8 : 0);
                int jj = jbase + (e & 1);
                int ki = jj >> 4, kj = jj & 15;
                int gh = bh * 8 - 4 + ki, gw = bw * 8 - 4 + kj;
                if (((unsigned)gh >= 64u) || ((unsigned)gw >= 64u))
                    s[nt][e] = -3.0e38f;
                else
                    s[nt][e] += lw[row * 16 + kj] + lh[row * 16 + ki];
            }
        }
    }

    // ---- softmax on fragments ----
    float* rmx  = (float*)(smc + AT_RMX);
    float* rsum = (float*)(smc + AT_RSUM);
    int gg = lane >> 2;
    int rA = wm * 16 + gg, rB = rA + 8;
    {
        float mA = -3.4e38f, mB = -3.4e38f;
#pragma unroll
        for (int nt = 0; nt < 16; nt++) {
            mA = fmaxf(mA, fmaxf(s[nt][0], s[nt][1]));
            mB = fmaxf(mB, fmaxf(s[nt][2], s[nt][3]));
        }
        mA = fmaxf(mA, __shfl_xor_sync(0xffffffffu, mA, 1));
        mA = fmaxf(mA, __shfl_xor_sync(0xffffffffu, mA, 2));
        mB = fmaxf(mB, __shfl_xor_sync(0xffffffffu, mB, 1));
        mB = fmaxf(mB, __shfl_xor_sync(0xffffffffu, mB, 2));
        if ((lane & 3) == 0) { rmx[wn * 64 + rA] = mA; rmx[wn * 64 + rB] = mB; }
    }
    __syncthreads();
    {
        float mA = fmaxf(rmx[rA], rmx[64 + rA]);
        float mB = fmaxf(rmx[rB], rmx[64 + rB]);
        float sA = 0.f, sB = 0.f;
#pragma unroll
        for (int nt = 0; nt < 16; nt++) {
            s[nt][0] = __expf(s[nt][0] - mA); sA += s[nt][0];
            s[nt][1] = __expf(s[nt][1] - mA); sA += s[nt][1];
            s[nt][2] = __expf(s[nt][2] - mB); sB += s[nt][2];
            s[nt][3] = __expf(s[nt][3] - mB); sB += s[nt][3];
        }
        sA += __shfl_xor_sync(0xffffffffu, sA, 1);
        sA += __shfl_xor_sync(0xffffffffu, sA, 2);
        sB += __shfl_xor_sync(0xffffffffu, sB, 1);
        sB += __shfl_xor_sync(0xffffffffu, sB, 2);
        if ((lane & 3) == 0) { rsum[wn * 64 + rA] = sA; rsum[wn * 64 + rB] = sB; }
    }
    __syncthreads();
    {
        float invA = 1.0f / (rsum[rA] + rsum[64 + rA]);
        float invB = 1.0f / (rsum[rB] + rsum[64 + rB]);
        // convert P -> bf16 hi/lo A-fragments IN PLACE:
        // s[nt][0] <- pack(h of e0,e1); s[nt][1] <- pack(h of e2,e3);
        // s[nt][2] <- pack(l of e0,e1); s[nt][3] <- pack(l of e2,e3)
#pragma unroll
        for (int nt = 0; nt < 16; nt++) {
            float v0 = s[nt][0] * invA, v1 = s[nt][1] * invA;
            float v2 = s[nt][2] * invB, v3 = s[nt][3] * invB;
            __nv_bfloat16 h0, l0, h1, l1, h2, l2, h3, l3;
            split_bf(v0, h0, l0); split_bf(v1, h1, l1);
            split_bf(v2, h2, l2); split_bf(v3, h3, l3);
            s[nt][0] = __uint_as_float(packbf(h0, h1));
            s[nt][1] = __uint_as_float(packbf(h2, h3));
            s[nt][2] = __uint_as_float(packbf(l0, l1));
            s[nt][3] = __uint_as_float(packbf(l2, l3));
        }
    }
    CP_WAIT0();
    __syncthreads();           // V resident

    // ---- AV: 3-term split mma, k = warp's 128 keys ----
    float avc[8][4];
#pragma unroll
    for (int a = 0; a < 8; a++)
#pragma unroll
        for (int b = 0; b < 4; b++) avc[a][b] = 0.f;
#pragma unroll
    for (int kt2 = 0; kt2 < 8; kt2++) {
        uint32_t pa[4] = { __float_as_uint(s[2 * kt2][0]), __float_as_uint(s[2 * kt2][1]),
                           __float_as_uint(s[2 * kt2 + 1][0]), __float_as_uint(s[2 * kt2 + 1][1]) };
        uint32_t qa[4] = { __float_as_uint(s[2 * kt2][2]), __float_as_uint(s[2 * kt2][3]),
                           __float_as_uint(s[2 * kt2 + 1][2]), __float_as_uint(s[2 * kt2 + 1][3]) };
#pragma unroll
        for (int nb = 0; nb < 4; nb++) {
            uint32_t off = (((wn * 128 + kt2 * 16 + ((lane >> 3) & 1) * 8 + (lane & 7)) * 72
                            + nb * 16 + ((lane >> 4) << 3)) << 1);
            uint32_t vh4[4], vl4[4];
            ldm4t(vh4, khB + off);
            ldm4t(vl4, klB + off);
            mma_bf16(avc[nb * 2],     pa, vh4[0], vh4[1]);
            mma_bf16(avc[nb * 2],     qa, vh4[0], vh4[1]);
            mma_bf16(avc[nb * 2],     pa, vl4[0], vl4[1]);
            mma_bf16(avc[nb * 2 + 1], pa, vh4[2], vh4[3]);
            mma_bf16(avc[nb * 2 + 1], qa, vh4[2], vh4[3]);
            mma_bf16(avc[nb * 2 + 1], pa, vl4[2], vl4[3]);
        }
    }

    // ---- cross-warp k-reduction via smem (Red overlays dead Q region) ----
    float* Red = (float*)(smc + AT_SQH);
    __syncthreads();
    if (wn == 0) {
#pragma unroll
        for (int nf = 0; nf < 8; nf++)
#pragma unroll
            for (int e = 0; e < 4; e++) {
                int row = wm * 16 + gg + ((e >= 2) ? 8 : 0);
                int col = nf * 8 + 2 * (lane & 3) + (e & 1);
                Red[row * 68 + col] = avc[nf][e];
            }
    }
    __syncthreads();
    if (wn == 1) {
#pragma unroll
        for (int nf = 0; nf < 8; nf++)
#pragma unroll
            for (int e = 0; e < 4; e++) {
                int row = wm * 16 + gg + ((e >= 2) ? 8 : 0);
                int col = nf * 8 + 2 * (lane & 3) + (e & 1);
                Red[row * 68 + col] += avc[nf][e];
            }
    }
    __syncthreads();

    // ---- store: bf16 hi/lo to g_bh/g_bl [pixel][256] ----
    {
        int qi = t >> 2, c0 = (t & 3) * 16;
        int qx = qi >> 3, qy = qi & 7;
        size_t base = (size_t)(bi * 4096 + (bh * 8 + qx) * 64 + bw * 8 + qy) * 256 + hco + c0;
        unsigned short hs[16], ls[16];
#pragma unroll
        for (int u = 0; u < 16; u++) {
            float v = Red[qi * 68 + c0 + u];
            __nv_bfloat16 h, l;
            split_bf(v, h, l);
            hs[u] = __bfloat16_as_ushort(h); ls[u] = __bfloat16_as_ushort(l);
        }
        *(uint4*)&g_bh[base]     = *(uint4*)&hs[0];
        *(uint4*)&g_bh[base + 8] = *(uint4*)&hs[8];
        *(uint4*)&g_bl[base]     = *(uint4*)&ls[0];
        *(uint4*)&g_bl[base + 8] = *(uint4*)&ls[8];
    }
}

// ---------------------------------------------------------------------------
// K3: output GEMM (tensor cores) + PixelShuffle epilogue.
// ---------------------------------------------------------------------------
__global__ __launch_bounds__(256) void k_out_tc(float* __restrict__ out)
{
    __shared__ __align__(16) __nv_bfloat16 sA[2][128 * 40];
    __shared__ __align__(16) __nv_bfloat16 sB[2][128 * 40];
    int tid = threadIdx.x, lane = tid & 31, wrp = tid >> 5;
    int wm = wrp >> 1, wn = wrp & 1;
    int mt = blockIdx.y, n0 = blockIdx.x << 7;
    int m0 = mt << 7;
    uint32_t sAu = smem_u32(sA), sBu = smem_u32(sB);

    float acc[2][8][4];
#pragma unroll
    for (int a = 0; a < 2; a++)
#pragma unroll
        for (int b = 0; b < 8; b++)
#pragma unroll
            for (int c = 0; c < 4; c++) acc[a][b][c] = 0.f;

    int ar = tid >> 1, ac = (tid & 1) << 4;

    auto issue = [&](int s, int buf) {
        int p = s >> 3, kk = (s & 7) << 5;
        const __nv_bfloat16* A = (p == 1 ? g_wfl : g_wfh) + (size_t)(m0 + ar) * 256 + kk + ac;
        uint32_t da = sAu + buf * 10240 + ((ar * 40 + ac) << 1);
        cp16(da, A); cp16(da + 16, A + 8);
        const __nv_bfloat16* B = (p == 2 ? g_bl : g_bh) + (size_t)(n0 + ar) * 256 + kk + ac;
        uint32_t db = sBu + buf * 10240 + ((ar * 40 + ac) << 1);
        cp16(db, B); cp16(db + 16, B + 8);
    };
    auto compute = [&](int buf) {
        uint32_t ab = sAu + buf * 10240;
        uint32_t bb = sBu + buf * 10240;
#pragma unroll
        for (int kh = 0; kh < 32; kh += 16) {
            uint32_t af[2][4];
#pragma unroll
            for (int mf = 0; mf < 2; mf++)
                ldm4(af[mf], ab + (((wm * 32 + mf * 16 + (lane & 15)) * 40
                                   + kh + ((lane >> 4) << 3)) << 1));
            uint32_t bf[4][4];
#pragma unroll
            for (int nb = 0; nb < 4; nb++)
                ldm4(bf[nb], bb + (((wn * 64 + nb * 16 + ((lane >> 4) << 3) + (lane & 7)) * 40
                                   + kh + (((lane >> 3) & 1) << 3)) << 1));
#pragma unroll
            for (int mf = 0; mf < 2; mf++)
#pragma unroll
                for (int nb = 0; nb < 4; nb++) {
                    mma_bf16(acc[mf][nb * 2],     af[mf], bf[nb][0], bf[nb][1]);
                    mma_bf16(acc[mf][nb * 2 + 1], af[mf], bf[nb][2], bf[nb][3]);
                }
        }
    };

    issue(0, 0); CP_COMMIT();
    for (int s = 0; s < 24; s++) {
        int buf = s & 1;
        if (s + 1 < 24) { issue(s + 1, buf ^ 1); CP_COMMIT(); CP_WAIT1(); }
        else             { CP_WAIT0(); }
        __syncthreads();
        compute(buf);
        __syncthreads();
    }

    int g = lane >> 2, q = lane & 3;
    int h0 = (n0 & 4095) >> 6, bimg = n0 >> 12;
    int hrow = h0 + wn;
#pragma unroll
    for (int mf = 0; mf < 2; mf++) {
#pragma unroll
        for (int which = 0; which < 2; which++) {
            int mm = m0 + wm * 32 + mf * 16 + g + which * 8;
            float bias = g_bf[mm];
            int cch = mm >> 2, r = (mm >> 1) & 1, s2 = mm & 1;
            float* rowp = out + ((size_t)(bimg * 256 + cch) * 128 + 2 * hrow + r) * 128 + s2;
#pragma unroll
            for (int nf = 0; nf < 8; nf++) {
                int w0 = nf * 8 + 2 * q;
                rowp[2 * w0]     = acc[mf][nf][which * 2 + 0] + bias;
                rowp[2 * w0 + 2] = acc[mf][nf][which * 2 + 1] + bias;
            }
        }
    }
}

// ---------------------------------------------------------------------------
extern "C" void kernel_launch(void* const* d_in, const int* in_sizes, int n_in,
                              void* d_out, int out_size)
{
    const float* x    = (const float*)d_in[0];
    const float* wq   = (const float*)d_in[1];
    const float* wkv  = (const float*)d_in[2];
    const float* wo   = (const float*)d_in[3];
    const float* bo   = (const float*)d_in[4];
    const float* relh = (const float*)d_in[5];
    const float* relw = (const float*)d_in[6];
    const float* wc   = (const float*)d_in[7];
    const float* bc   = (const float*)d_in[8];
    float* out = (float*)d_out;

    cudaFuncSetAttribute(k_attn_tc, cudaFuncAttributeMaxDynamicSharedMemorySize, AT_SMEM);

    k_fuse<<<256, 256>>>(wo, bo, wc, bc);
    k_splitw<<<768, 256>>>(wq, wkv);
    k_splitx<<<8192, 256>>>(x);
    k_qkv_tc<<<dim3(256, 6), 256>>>();
    k_attn_tc<<<dim3(512, 4), 256, AT_SMEM>>>(relh, relw);
    k_out_tc<<<dim3(256, 8), 256>>>(out);
}

// round 6
// speedup vs baseline: 2.4066x; 1.1152x over previous
#include <cuda_runtime.h>
#include <cuda_bf16.h>
#include <stdint.h>

#define NPIX 32768            // B*H*W
#define QKVC 768

// Scratch (device globals; 16B-aligned)
__device__ __align__(16) __nv_bfloat16 g_qh[NPIX * QKVC];  // qkv hi, [pixel][q|k|v]
__device__ __align__(16) __nv_bfloat16 g_ql[NPIX * QKVC];  // qkv lo
__device__ __align__(16) __nv_bfloat16 g_bh[NPIX * 256];   // attn out hi, [n][256]
__device__ __align__(16) __nv_bfloat16 g_bl[NPIX * 256];   // attn out lo
__device__ __align__(16) __nv_bfloat16 g_wfh[1024 * 256];  // fused conv W hi, [m][k]
__device__ __align__(16) __nv_bfloat16 g_wfl[1024 * 256];
__device__ __align__(16) __nv_bfloat16 g_wqh[QKVC * 256];  // qkv W hi (q pre-scaled), [m][k]
__device__ __align__(16) __nv_bfloat16 g_wql[QKVC * 256];
__device__ __align__(16) __nv_bfloat16 g_xh[256 * NPIX];   // x split, [k][n]
__device__ __align__(16) __nv_bfloat16 g_xl[256 * NPIX];
__device__ float g_bf[1024];

// ---------------------------------------------------------------------------
// helpers (non-arch-specific PTX only: cp.async / ldmatrix / mma.sync)
// ---------------------------------------------------------------------------
__device__ __forceinline__ uint32_t smem_u32(const void* p) {
    uint32_t a;
    asm("{ .reg .u64 t; cvta.to.shared.u64 t, %1; cvt.u32.u64 %0, t; }" : "=r"(a) : "l"(p));
    return a;
}
__device__ __forceinline__ void cp16(uint32_t d, const void* s) {
    asm volatile("cp.async.ca.shared.global [%0], [%1], 16;" :: "r"(d), "l"(s));
}
#define CP_COMMIT() asm volatile("cp.async.commit_group;")
#define CP_WAIT1()  asm volatile("cp.async.wait_group 1;")
#define CP_WAIT0()  asm volatile("cp.async.wait_group 0;")

__device__ __forceinline__ void ldm4(uint32_t* r, uint32_t a) {
    asm volatile("ldmatrix.sync.aligned.m8n8.x4.shared.b16 {%0,%1,%2,%3}, [%4];"
                 : "=r"(r[0]), "=r"(r[1]), "=r"(r[2]), "=r"(r[3]) : "r"(a));
}
__device__ __forceinline__ void ldm4t(uint32_t* r, uint32_t a) {
    asm volatile("ldmatrix.sync.aligned.m8n8.x4.trans.shared.b16 {%0,%1,%2,%3}, [%4];"
                 : "=r"(r[0]), "=r"(r[1]), "=r"(r[2]), "=r"(r[3]) : "r"(a));
}
__device__ __forceinline__ void mma_bf16(float* d, const uint32_t* a, uint32_t b0, uint32_t b1) {
    asm volatile("mma.sync.aligned.m16n8k16.row.col.f32.bf16.bf16.f32 "
                 "{%0,%1,%2,%3}, {%4,%5,%6,%7}, {%8,%9}, {%0,%1,%2,%3};"
                 : "+f"(d[0]), "+f"(d[1]), "+f"(d[2]), "+f"(d[3])
                 : "r"(a[0]), "r"(a[1]), "r"(a[2]), "r"(a[3]), "r"(b0), "r"(b1));
}
__device__ __forceinline__ void split_bf(float v, __nv_bfloat16& h, __nv_bfloat16& l) {
    h = __float2bfloat16(v);
    l = __float2bfloat16(v - __bfloat162float(h));
}
__device__ __forceinline__ uint32_t packbf(__nv_bfloat16 a, __nv_bfloat16 b) {
    return (uint32_t)__bfloat16_as_ushort(a) | ((uint32_t)__bfloat16_as_ushort(b) << 16);
}

// ---------------------------------------------------------------------------
// K0: fuse wo into conv: Wf = wc @ wo (bf16 hi/lo row-major), bf = wc@bo + bc
// ---------------------------------------------------------------------------
__global__ __launch_bounds__(256) void k_fuse(const float* __restrict__ wo,
                                              const float* __restrict__ bo,
                                              const float* __restrict__ wc,
                                              const float* __restrict__ bc)
{
    int ob = blockIdx.x * 4;
    int i  = threadIdx.x;
    float a0 = 0.f, a1 = 0.f, a2 = 0.f, a3 = 0.f;
    for (int cc = 0; cc < 256; cc++) {
        float w = wo[cc * 256 + i];
        a0 += wc[(ob + 0) * 256 + cc] * w;
        a1 += wc[(ob + 1) * 256 + cc] * w;
        a2 += wc[(ob + 2) * 256 + cc] * w;
        a3 += wc[(ob + 3) * 256 + cc] * w;
    }
    float vals[4] = {a0, a1, a2, a3};
#pragma unroll
    for (int j = 0; j < 4; j++) {
        __nv_bfloat16 h, l;
        split_bf(vals[j], h, l);
        size_t idx = (size_t)(ob + j) * 256 + i;
        g_wfh[idx] = h; g_wfl[idx] = l;
    }
    if (i < 4) {
        int o = ob + i;
        float s = 0.f;
        for (int c2 = 0; c2 < 256; c2++) s += wc[o * 256 + c2] * bo[c2];
        g_bf[o] = s + bc[o];
    }
}

// ---------------------------------------------------------------------------
// K0b: split wq (pre-scaled by 0.125) / wkv to bf16 hi/lo, row-major [768][256]
// ---------------------------------------------------------------------------
__global__ __launch_bounds__(256) void k_splitw(const float* __restrict__ wq,
                                                const float* __restrict__ wkv)
{
    int i = blockIdx.x * 256 + threadIdx.x;
    int m = i >> 8, c = i & 255;
    float v = (m < 256) ? wq[m * 256 + c] * 0.125f : wkv[(m - 256) * 256 + c];
    __nv_bfloat16 h, l;
    split_bf(v, h, l);
    g_wqh[i] = h; g_wql[i] = l;
}

// ---------------------------------------------------------------------------
// K0c: split x -> [k=channel][n=b*4096+p] bf16 hi/lo
// ---------------------------------------------------------------------------
__global__ __launch_bounds__(256) void k_splitx(const float* __restrict__ x)
{
    size_t i = (size_t)(blockIdx.x * 256 + threadIdx.x) * 4;
    float4 v = *(const float4*)(x + i);
    size_t o = (size_t)((i >> 12) & 255) * NPIX + ((i >> 20) << 12) + (i & 4095);
    __nv_bfloat16 h0, l0, h1, l1, h2, l2, h3, l3;
    split_bf(v.x, h0, l0); split_bf(v.y, h1, l1);
    split_bf(v.z, h2, l2); split_bf(v.w, h3, l3);
    *(uint2*)&g_xh[o] = make_uint2(packbf(h0, h1), packbf(h2, h3));
    *(uint2*)&g_xl[o] = make_uint2(packbf(l0, l1), packbf(l2, l3));
}

// ---------------------------------------------------------------------------
// K1: QKV projection (tensor cores). C[768,32768] = Wqkv @ X, split-bf16 x3.
// Single-pass hi/lo staging: per k-chunk of 32 load Ah,Al,Bh,Bl and run all
// 3 correction terms (96 MMAs / stage, 8 stages).
// smem per buffer: Ah 10240 | Al 10240 | Bh 8704 | Bl 8704 = 37888 B, x2 bufs.
// ---------------------------------------------------------------------------
#define QK_BUF  37888
#define QK_SMEM (QK_BUF * 2)

__global__ void __launch_bounds__(256, 2) k_qkv_tc()
{
    extern __shared__ char qsm[];
    uint32_t base = smem_u32(qsm);
    int tid = threadIdx.x, lane = tid & 31, wrp = tid >> 5;
    int wm = wrp >> 1, wn = wrp & 1;
    int mt = blockIdx.y, n0 = blockIdx.x << 7;
    int m0 = mt << 7;

    float acc[2][8][4];
#pragma unroll
    for (int a = 0; a < 2; a++)
#pragma unroll
        for (int b = 0; b < 8; b++)
#pragma unroll
            for (int c = 0; c < 4; c++) acc[a][b][c] = 0.f;

    int ar = tid >> 1, ac = (tid & 1) << 4;
    int br = tid >> 3, bc = (tid & 7) << 4;

    auto issue = [&](int s, int buf) {
        int kk = s << 5;
        uint32_t qa = base + buf * QK_BUF;
        const __nv_bfloat16* Ah = g_wqh + (size_t)(m0 + ar) * 256 + kk + ac;
        const __nv_bfloat16* Al = g_wql + (size_t)(m0 + ar) * 256 + kk + ac;
        uint32_t da = qa + ((ar * 40 + ac) << 1);
        cp16(da, Ah);            cp16(da + 16, Ah + 8);
        cp16(da + 10240, Al);    cp16(da + 10240 + 16, Al + 8);
        const __nv_bfloat16* Bh = g_xh + (size_t)(kk + br) * NPIX + n0 + bc;
        const __nv_bfloat16* Bl = g_xl + (size_t)(kk + br) * NPIX + n0 + bc;
        uint32_t db = qa + 20480 + ((br * 136 + bc) << 1);
        cp16(db, Bh);            cp16(db + 16, Bh + 8);
        cp16(db + 8704, Bl);     cp16(db + 8704 + 16, Bl + 8);
    };
    auto compute = [&](int buf) {
        uint32_t qa  = base + buf * QK_BUF;
        uint32_t abh = qa, abl = qa + 10240;
        uint32_t bbh = qa + 20480, bbl = qa + 29184;
#pragma unroll
        for (int kh = 0; kh < 32; kh += 16) {
            uint32_t ah[2][4], al[2][4];
#pragma unroll
            for (int mf = 0; mf < 2; mf++) {
                uint32_t aoff = (((wm * 32 + mf * 16 + (lane & 15)) * 40
                                  + kh + ((lane >> 4) << 3)) << 1);
                ldm4(ah[mf], abh + aoff);
                ldm4(al[mf], abl + aoff);
            }
#pragma unroll
            for (int nb = 0; nb < 4; nb++) {
                uint32_t boff = (((kh + ((lane >> 3) & 1) * 8 + (lane & 7)) * 136
                                  + wn * 64 + nb * 16 + ((lane >> 4) << 3)) << 1);
                uint32_t bh4[4], bl4[4];
                ldm4t(bh4, bbh + boff);
                ldm4t(bl4, bbl + boff);
#pragma unroll
                for (int mf = 0; mf < 2; mf++) {
                    mma_bf16(acc[mf][nb * 2],     ah[mf], bh4[0], bh4[1]);
                    mma_bf16(acc[mf][nb * 2],     al[mf], bh4[0], bh4[1]);
                    mma_bf16(acc[mf][nb * 2],     ah[mf], bl4[0], bl4[1]);
                    mma_bf16(acc[mf][nb * 2 + 1], ah[mf], bh4[2], bh4[3]);
                    mma_bf16(acc[mf][nb * 2 + 1], al[mf], bh4[2], bh4[3]);
                    mma_bf16(acc[mf][nb * 2 + 1], ah[mf], bl4[2], bl4[3]);
                }
            }
        }
    };

    issue(0, 0); CP_COMMIT();
    for (int s = 0; s < 8; s++) {
        int buf = s & 1;
        if (s + 1 < 8) { issue(s + 1, buf ^ 1); CP_COMMIT(); CP_WAIT1(); }
        else           { CP_WAIT0(); }
        __syncthreads();
        compute(buf);
        __syncthreads();
    }

    // epilogue: transpose per 32-row m-quarter via smem, write bf16 hi/lo
    float* tb = (float*)qsm;
    int g = lane >> 2, q = lane & 3;
#pragma unroll
    for (int mq = 0; mq < 4; mq++) {
        if (wm == mq) {
#pragma unroll
            for (int mf = 0; mf < 2; mf++)
#pragma unroll
                for (int nf = 0; nf < 8; nf++) {
                    int nl = wn * 64 + nf * 8 + q * 2;
                    int ml = mf * 16 + g;
                    tb[nl * 33 + ml]            = acc[mf][nf][0];
                    tb[(nl + 1) * 33 + ml]      = acc[mf][nf][1];
                    tb[nl * 33 + ml + 8]        = acc[mf][nf][2];
                    tb[(nl + 1) * 33 + ml + 8]  = acc[mf][nf][3];
                }
        }
        __syncthreads();
        int nl = tid >> 1, half = tid & 1;
        const float* src = tb + nl * 33 + half * 16;
        size_t dst = (size_t)(n0 + nl) * QKVC + m0 + mq * 32 + half * 16;
        unsigned short hs[16], ls[16];
#pragma unroll
        for (int u = 0; u < 16; u++) {
            float v = src[u];
            __nv_bfloat16 h, l;
            split_bf(v, h, l);
            hs[u] = __bfloat16_as_ushort(h); ls[u] = __bfloat16_as_ushort(l);
        }
        *(uint4*)&g_qh[dst]     = *(uint4*)&hs[0];
        *(uint4*)&g_qh[dst + 8] = *(uint4*)&hs[8];
        *(uint4*)&g_ql[dst]     = *(uint4*)&ls[0];
        *(uint4*)&g_ql[dst + 8] = *(uint4*)&ls[8];
        __syncthreads();
    }
}

// ---------------------------------------------------------------------------
// K2: tensor-core halo attention (unchanged from R5).
// ---------------------------------------------------------------------------
#define AT_SQH  0
#define AT_SQL  9216
#define AT_SK   18432
#define AT_SKL  55296
#define AT_REL  92160
#define AT_LW   92160
#define AT_LH   96256
#define AT_RMX  100352
#define AT_RSUM 100864
#define AT_SMEM 108288

__global__ void __launch_bounds__(256, 2) k_attn_tc(const float* __restrict__ relh,
                                                    const float* __restrict__ relw)
{
    extern __shared__ char smc[];
    uint32_t sb = smem_u32(smc);
    int t = threadIdx.x, lane = t & 31, wid = t >> 5;
    int wm = wid >> 1, wn = wid & 1;
    int nbk = blockIdx.x, hh = blockIdx.y;
    int bi = nbk >> 6, tbw = nbk & 63;
    int bh = tbw >> 3, bw = tbw & 7;
    int hco = hh * 64;

    uint32_t qhB = sb + AT_SQH, qlB = sb + AT_SQL;
    uint32_t khB = sb + AT_SK,  klB = sb + AT_SKL;

    {
        int chunk = t & 7, rr = t >> 3;
#pragma unroll
        for (int p = 0; p < 2; p++) {
            int row = p * 32 + rr;
            int qx = row >> 3, qy = row & 7;
            size_t pix = (size_t)(bi * 4096 + (bh * 8 + qx) * 64 + bw * 8 + qy) * QKVC + hco;
            ((uint4*)(smc + AT_SQH))[row * 9 + chunk] = *(const uint4*)(g_qh + pix + chunk * 8);
            ((uint4*)(smc + AT_SQL))[row * 9 + chunk] = *(const uint4*)(g_ql + pix + chunk * 8);
        }
#pragma unroll
        for (int p = 0; p < 8; p++) {
            int row = p * 32 + rr;
            int ki = row >> 4, kj = row & 15;
            int gh = bh * 8 - 4 + ki, gw = bw * 8 - 4 + kj;
            bool valid = ((unsigned)gh < 64u) && ((unsigned)gw < 64u);
            size_t pix = (size_t)(valid ? bi * 4096 + gh * 64 + gw : bi * 4096) * QKVC
                       + 256 + hco + chunk * 8;
            uint4 z = make_uint4(0, 0, 0, 0);
            uint4 vh = valid ? *(const uint4*)(g_qh + pix) : z;
            uint4 vl = valid ? *(const uint4*)(g_ql + pix) : z;
            ((uint4*)(smc + AT_SK ))[row * 9 + chunk] = vh;
            ((uint4*)(smc + AT_SKL))[row * 9 + chunk] = vl;
        }
        float* srh = (float*)(smc + AT_REL);
        float* srw = (float*)(smc + AT_REL + 8064);
        for (int idx = t; idx < 1984; idx += 256) {
            int r = idx >> 6, dd = idx & 63;
            srh[r * 65 + dd] = relh[idx];
            srw[r * 65 + dd] = relw[idx];
        }
    }
    __syncthreads();

    float rv[8];
    {
        const float* srh = (const float*)(smc + AT_REL);
        const float* srw = (const float*)(smc + AT_REL + 8064);
        const __nv_bfloat16* Qh = (const __nv_bfloat16*)(smc + AT_SQH);
        const __nv_bfloat16* Ql = (const __nv_bfloat16*)(smc + AT_SQL);
#pragma unroll
        for (int m = 0; m < 8; m++) {
            int wk = t + 256 * m;
            int qi = wk >> 5, sel = (wk >> 4) & 1, pos = wk & 15;
            int qx = qi >> 3, qy = qi & 7;
            int ridx = pos - (sel ? qy : qx) + 15;
            const float* rrow = (sel ? srw : srh) + ridx * 65;
            const __nv_bfloat16* qh = Qh + qi * 72;
            const __nv_bfloat16* ql = Ql + qi * 72;
            float a = 0.f;
#pragma unroll 16
            for (int dd = 0; dd < 64; dd++)
                a += (__bfloat162float(qh[dd]) + __bfloat162float(ql[dd])) * rrow[dd];
            rv[m] = a;
        }
    }
    __syncthreads();
    {
        float* lw = (float*)(smc + AT_LW);
        float* lh = (float*)(smc + AT_LH);
#pragma unroll
        for (int m = 0; m < 8; m++) {
            int wk = t + 256 * m;
            int qi = wk >> 5, sel = (wk >> 4) & 1, pos = wk & 15;
            (sel ? lw : lh)[qi * 16 + pos] = rv[m];
        }
    }

    float s[16][4];
#pragma unroll
    for (int a = 0; a < 16; a++)
#pragma unroll
        for (int b = 0; b < 4; b++) s[a][b] = 0.f;
#pragma unroll
    for (int kt = 0; kt < 4; kt++) {
        uint32_t ah[4], al[4];
        uint32_t aoff = (((wm * 16 + (lane & 15)) * 72 + kt * 16 + ((lane >> 4) << 3)) << 1);
        ldm4(ah, qhB + aoff);
        ldm4(al, qlB + aoff);
#pragma unroll
        for (int nb = 0; nb < 8; nb++) {
            uint32_t boff = (((wn * 128 + nb * 16 + ((lane >> 4) << 3) + (lane & 7)) * 72
                             + kt * 16 + (((lane >> 3) & 1) << 3)) << 1);
            uint32_t bh4[4], bl4[4];
            ldm4(bh4, khB + boff);
            ldm4(bl4, klB + boff);
            mma_bf16(s[nb * 2],     ah, bh4[0], bh4[1]);
            mma_bf16(s[nb * 2],     al, bh4[0], bh4[1]);
            mma_bf16(s[nb * 2],     ah, bl4[0], bl4[1]);
            mma_bf16(s[nb * 2 + 1], ah, bh4[2], bh4[3]);
            mma_bf16(s[nb * 2 + 1], al, bh4[2], bh4[3]);
            mma_bf16(s[nb * 2 + 1], ah, bl4[2], bl4[3]);
        }
    }
    __syncthreads();

    {
        int chunk = t & 7, rr = t >> 3;
#pragma unroll
        for (int p = 0; p < 8; p++) {
            int row = p * 32 + rr;
            int ki = row >> 4, kj = row & 15;
            int gh = bh * 8 - 4 + ki, gw = bw * 8 - 4 + kj;
            bool valid = ((unsigned)gh < 64u) && ((unsigned)gw < 64u);
            size_t pix = (size_t)(valid ? bi * 4096 + gh * 64 + gw : bi * 4096) * QKVC
                       + 512 + hco + chunk * 8;
            uint32_t doff = (uint32_t)(row * 9 + chunk) << 4;
            cp16(khB + doff, g_qh + pix);
            cp16(klB + doff, g_ql + pix);
        }
        CP_COMMIT();
    }

    {
        const float* lw = (const float*)(smc + AT_LW);
        const float* lh = (const float*)(smc + AT_LH);
        int g = lane >> 2, tt = lane & 3;
#pragma unroll
        for (int nt = 0; nt < 16; nt++) {
            int jbase = wn * 128 + nt * 8 + 2 * tt;
#pragma unroll
            for (int e = 0; e < 4; e++) {
                int row = wm * 16 + g + ((e >= 2) ? 8 : 0);
                int jj = jbase + (e & 1);
                int ki = jj >> 4, kj = jj & 15;
                int gh = bh * 8 - 4 + ki, gw = bw * 8 - 4 + kj;
                if (((unsigned)gh >= 64u) || ((unsigned)gw >= 64u))
                    s[nt][e] = -3.0e38f;
                else
                    s[nt][e] += lw[row * 16 + kj] + lh[row * 16 + ki];
            }
        }
    }

    float* rmx  = (float*)(smc + AT_RMX);
    float* rsum = (float*)(smc + AT_RSUM);
    int gg = lane >> 2;
    int rA = wm * 16 + gg, rB = rA + 8;
    {
        float mA = -3.4e38f, mB = -3.4e38f;
#pragma unroll
        for (int nt = 0; nt < 16; nt++) {
            mA = fmaxf(mA, fmaxf(s[nt][0], s[nt][1]));
            mB = fmaxf(mB, fmaxf(s[nt][2], s[nt][3]));
        }
        mA = fmaxf(mA, __shfl_xor_sync(0xffffffffu, mA, 1));
        mA = fmaxf(mA, __shfl_xor_sync(0xffffffffu, mA, 2));
        mB = fmaxf(mB, __shfl_xor_sync(0xffffffffu, mB, 1));
        mB = fmaxf(mB, __shfl_xor_sync(0xffffffffu, mB, 2));
        if ((lane & 3) == 0) { rmx[wn * 64 + rA] = mA; rmx[wn * 64 + rB] = mB; }
    }
    __syncthreads();
    {
        float mA = fmaxf(rmx[rA], rmx[64 + rA]);
        float mB = fmaxf(rmx[rB], rmx[64 + rB]);
        float sA = 0.f, sB = 0.f;
#pragma unroll
        for (int nt = 0; nt < 16; nt++) {
            s[nt][0] = __expf(s[nt][0] - mA); sA += s[nt][0];
            s[nt][1] = __expf(s[nt][1] - mA); sA += s[nt][1];
            s[nt][2] = __expf(s[nt][2] - mB); sB += s[nt][2];
            s[nt][3] = __expf(s[nt][3] - mB); sB += s[nt][3];
        }
        sA += __shfl_xor_sync(0xffffffffu, sA, 1);
        sA += __shfl_xor_sync(0xffffffffu, sA, 2);
        sB += __shfl_xor_sync(0xffffffffu, sB, 1);
        sB += __shfl_xor_sync(0xffffffffu, sB, 2);
        if ((lane & 3) == 0) { rsum[wn * 64 + rA] = sA; rsum[wn * 64 + rB] = sB; }
    }
    __syncthreads();
    {
        float invA = 1.0f / (rsum[rA] + rsum[64 + rA]);
        float invB = 1.0f / (rsum[rB] + rsum[64 + rB]);
#pragma unroll
        for (int nt = 0; nt < 16; nt++) {
            float v0 = s[nt][0] * invA, v1 = s[nt][1] * invA;
            float v2 = s[nt][2] * invB, v3 = s[nt][3] * invB;
            __nv_bfloat16 h0, l0, h1, l1, h2, l2, h3, l3;
            split_bf(v0, h0, l0); split_bf(v1, h1, l1);
            split_bf(v2, h2, l2); split_bf(v3, h3, l3);
            s[nt][0] = __uint_as_float(packbf(h0, h1));
            s[nt][1] = __uint_as_float(packbf(h2, h3));
            s[nt][2] = __uint_as_float(packbf(l0, l1));
            s[nt][3] = __uint_as_float(packbf(l2, l3));
        }
    }
    CP_WAIT0();
    __syncthreads();

    float avc[8][4];
#pragma unroll
    for (int a = 0; a < 8; a++)
#pragma unroll
        for (int b = 0; b < 4; b++) avc[a][b] = 0.f;
#pragma unroll
    for (int kt2 = 0; kt2 < 8; kt2++) {
        uint32_t pa[4] = { __float_as_uint(s[2 * kt2][0]), __float_as_uint(s[2 * kt2][1]),
                           __float_as_uint(s[2 * kt2 + 1][0]), __float_as_uint(s[2 * kt2 + 1][1]) };
        uint32_t qa[4] = { __float_as_uint(s[2 * kt2][2]), __float_as_uint(s[2 * kt2][3]),
                           __float_as_uint(s[2 * kt2 + 1][2]), __float_as_uint(s[2 * kt2 + 1][3]) };
#pragma unroll
        for (int nb = 0; nb < 4; nb++) {
            uint32_t off = (((wn * 128 + kt2 * 16 + ((lane >> 3) & 1) * 8 + (lane & 7)) * 72
                            + nb * 16 + ((lane >> 4) << 3)) << 1);
            uint32_t vh4[4], vl4[4];
            ldm4t(vh4, khB + off);
            ldm4t(vl4, klB + off);
            mma_bf16(avc[nb * 2],     pa, vh4[0], vh4[1]);
            mma_bf16(avc[nb * 2],     qa, vh4[0], vh4[1]);
            mma_bf16(avc[nb * 2],     pa, vl4[0], vl4[1]);
            mma_bf16(avc[nb * 2 + 1], pa, vh4[2], vh4[3]);
            mma_bf16(avc[nb * 2 + 1], qa, vh4[2], vh4[3]);
            mma_bf16(avc[nb * 2 + 1], pa, vl4[2], vl4[3]);
        }
    }

    float* Red = (float*)(smc + AT_SQH);
    __syncthreads();
    if (wn == 0) {
#pragma unroll
        for (int nf = 0; nf < 8; nf++)
#pragma unroll
            for (int e = 0; e < 4; e++) {
                int row = wm * 16 + gg + ((e >= 2) ? 8 : 0);
                int col = nf * 8 + 2 * (lane & 3) + (e & 1);
                Red[row * 68 + col] = avc[nf][e];
            }
    }
    __syncthreads();
    if (wn == 1) {
#pragma unroll
        for (int nf = 0; nf < 8; nf++)
#pragma unroll
            for (int e = 0; e < 4; e++) {
                int row = wm * 16 + gg + ((e >= 2) ? 8 : 0);
                int col = nf * 8 + 2 * (lane & 3) + (e & 1);
                Red[row * 68 + col] += avc[nf][e];
            }
    }
    __syncthreads();

    {
        int qi = t >> 2, c0 = (t & 3) * 16;
        int qx = qi >> 3, qy = qi & 7;
        size_t base = (size_t)(bi * 4096 + (bh * 8 + qx) * 64 + bw * 8 + qy) * 256 + hco + c0;
        unsigned short hs[16], ls[16];
#pragma unroll
        for (int u = 0; u < 16; u++) {
            float v = Red[qi * 68 + c0 + u];
            __nv_bfloat16 h, l;
            split_bf(v, h, l);
            hs[u] = __bfloat16_as_ushort(h); ls[u] = __bfloat16_as_ushort(l);
        }
        *(uint4*)&g_bh[base]     = *(uint4*)&hs[0];
        *(uint4*)&g_bh[base + 8] = *(uint4*)&hs[8];
        *(uint4*)&g_bl[base]     = *(uint4*)&ls[0];
        *(uint4*)&g_bl[base + 8] = *(uint4*)&ls[8];
    }
}

// ---------------------------------------------------------------------------
// K3: output GEMM (tensor cores) + PixelShuffle epilogue.
// Same single-pass hi/lo staging: 8 stages of k=32, 96 MMAs per stage.
// smem per buffer: Ah 10240 | Al 10240 | Bh 10240 | Bl 10240 = 40960 B, x2.
// ---------------------------------------------------------------------------
#define KO_BUF  40960
#define KO_SMEM (KO_BUF * 2)

__global__ void __launch_bounds__(256, 2) k_out_tc(float* __restrict__ out)
{
    extern __shared__ char osm[];
    uint32_t base = smem_u32(osm);
    int tid = threadIdx.x, lane = tid & 31, wrp = tid >> 5;
    int wm = wrp >> 1, wn = wrp & 1;
    int mt = blockIdx.y, n0 = blockIdx.x << 7;
    int m0 = mt << 7;

    float acc[2][8][4];
#pragma unroll
    for (int a = 0; a < 2; a++)
#pragma unroll
        for (int b = 0; b < 8; b++)
#pragma unroll
            for (int c = 0; c < 4; c++) acc[a][b][c] = 0.f;

    int ar = tid >> 1, ac = (tid & 1) << 4;

    auto issue = [&](int s, int buf) {
        int kk = s << 5;
        uint32_t qa = base + buf * KO_BUF;
        const __nv_bfloat16* Ah = g_wfh + (size_t)(m0 + ar) * 256 + kk + ac;
        const __nv_bfloat16* Al = g_wfl + (size_t)(m0 + ar) * 256 + kk + ac;
        uint32_t da = qa + ((ar * 40 + ac) << 1);
        cp16(da, Ah);            cp16(da + 16, Ah + 8);
        cp16(da + 10240, Al);    cp16(da + 10240 + 16, Al + 8);
        const __nv_bfloat16* Bh = g_bh + (size_t)(n0 + ar) * 256 + kk + ac;
        const __nv_bfloat16* Bl = g_bl + (size_t)(n0 + ar) * 256 + kk + ac;
        uint32_t db = qa + 20480 + ((ar * 40 + ac) << 1);
        cp16(db, Bh);            cp16(db + 16, Bh + 8);
        cp16(db + 10240, Bl);    cp16(db + 10240 + 16, Bl + 8);
    };
    auto compute = [&](int buf) {
        uint32_t qa  = base + buf * KO_BUF;
        uint32_t abh = qa, abl = qa + 10240;
        uint32_t bbh = qa + 20480, bbl = qa + 30720;
#pragma unroll
        for (int kh = 0; kh < 32; kh += 16) {
            uint32_t ah[2][4], al[2][4];
#pragma unroll
            for (int mf = 0; mf < 2; mf++) {
                uint32_t aoff = (((wm * 32 + mf * 16 + (lane & 15)) * 40
                                  + kh + ((lane >> 4) << 3)) << 1);
                ldm4(ah[mf], abh + aoff);
                ldm4(al[mf], abl + aoff);
            }
#pragma unroll
            for (int nb = 0; nb < 4; nb++) {
                uint32_t boff = (((wn * 64 + nb * 16 + ((lane >> 4) << 3) + (lane & 7)) * 40
                                  + kh + (((lane >> 3) & 1) << 3)) << 1);
                uint32_t bh4[4], bl4[4];
                ldm4(bh4, bbh + boff);
                ldm4(bl4, bbl + boff);
#pragma unroll
                for (int mf = 0; mf < 2; mf++) {
                    mma_bf16(acc[mf][nb * 2],     ah[mf], bh4[0], bh4[1]);
                    mma_bf16(acc[mf][nb * 2],     al[mf], bh4[0], bh4[1]);
                    mma_bf16(acc[mf][nb * 2],     ah[mf], bl4[0], bl4[1]);
                    mma_bf16(acc[mf][nb * 2 + 1], ah[mf], bh4[2], bh4[3]);
                    mma_bf16(acc[mf][nb * 2 + 1], al[mf], bh4[2], bh4[3]);
                    mma_bf16(acc[mf][nb * 2 + 1], ah[mf], bl4[2], bl4[3]);
                }
            }
        }
    };

    issue(0, 0); CP_COMMIT();
    for (int s = 0; s < 8; s++) {
        int buf = s & 1;
        if (s + 1 < 8) { issue(s + 1, buf ^ 1); CP_COMMIT(); CP_WAIT1(); }
        else           { CP_WAIT0(); }
        __syncthreads();
        compute(buf);
        __syncthreads();
    }

    int g = lane >> 2, q = lane & 3;
    int h0 = (n0 & 4095) >> 6, bimg = n0 >> 12;
    int hrow = h0 + wn;
#pragma unroll
    for (int mf = 0; mf < 2; mf++) {
#pragma unroll
        for (int which = 0; which < 2; which++) {
            int mm = m0 + wm * 32 + mf * 16 + g + which * 8;
            float bias = g_bf[mm];
            int cch = mm >> 2, r = (mm >> 1) & 1, s2 = mm & 1;
            float* rowp = out + ((size_t)(bimg * 256 + cch) * 128 + 2 * hrow + r) * 128 + s2;
#pragma unroll
            for (int nf = 0; nf < 8; nf++) {
                int w0 = nf * 8 + 2 * q;
                rowp[2 * w0]     = acc[mf][nf][which * 2 + 0] + bias;
                rowp[2 * w0 + 2] = acc[mf][nf][which * 2 + 1] + bias;
            }
        }
    }
}

// ---------------------------------------------------------------------------
extern "C" void kernel_launch(void* const* d_in, const int* in_sizes, int n_in,
                              void* d_out, int out_size)
{
    const float* x    = (const float*)d_in[0];
    const float* wq   = (const float*)d_in[1];
    const float* wkv  = (const float*)d_in[2];
    const float* wo   = (const float*)d_in[3];
    const float* bo   = (const float*)d_in[4];
    const float* relh = (const float*)d_in[5];
    const float* relw = (const float*)d_in[6];
    const float* wc   = (const float*)d_in[7];
    const float* bc   = (const float*)d_in[8];
    float* out = (float*)d_out;

    cudaFuncSetAttribute(k_qkv_tc,  cudaFuncAttributeMaxDynamicSharedMemorySize, QK_SMEM);
    cudaFuncSetAttribute(k_attn_tc, cudaFuncAttributeMaxDynamicSharedMemorySize, AT_SMEM);
    cudaFuncSetAttribute(k_out_tc,  cudaFuncAttributeMaxDynamicSharedMemorySize, KO_SMEM);

    k_fuse<<<256, 256>>>(wo, bo, wc, bc);
    k_splitw<<<768, 256>>>(wq, wkv);
    k_splitx<<<8192, 256>>>(x);
    k_qkv_tc<<<dim3(256, 6), 256, QK_SMEM>>>();
    k_attn_tc<<<dim3(512, 4), 256, AT_SMEM>>>(relh, relw);
    k_out_tc<<<dim3(256, 8), 256, KO_SMEM>>>(out);
}

// round 7
// speedup vs baseline: 2.8634x; 1.1898x over previous
#include <cuda_runtime.h>
#include <cuda_fp16.h>
#include <stdint.h>

#define NPIX 32768            // B*H*W
#define QKVC 768

// Scratch (device globals; 16B-aligned). fp16 hi/lo splits.
__device__ __align__(16) __half g_qh[NPIX * QKVC];  // qkv hi, [pixel][q|k|v]
__device__ __align__(16) __half g_ql[NPIX * QKVC];  // qkv lo
__device__ __align__(16) __half g_bh[NPIX * 256];   // attn out (single fp16), [n][256]
__device__ __align__(16) __half g_wfh[1024 * 256];  // fused conv W hi, [m][k]
__device__ __align__(16) __half g_wfl[1024 * 256];
__device__ __align__(16) __half g_wqh[QKVC * 256];  // qkv W hi (q pre-scaled), [m][k]
__device__ __align__(16) __half g_wql[QKVC * 256];
__device__ __align__(16) __half g_xh[256 * NPIX];   // x fp16, [k][n]
__device__ float g_bf[1024];

// ---------------------------------------------------------------------------
// helpers (non-arch-specific PTX only: cp.async / ldmatrix / mma.sync)
// ---------------------------------------------------------------------------
__device__ __forceinline__ uint32_t smem_u32(const void* p) {
    uint32_t a;
    asm("{ .reg .u64 t; cvta.to.shared.u64 t, %1; cvt.u32.u64 %0, t; }" : "=r"(a) : "l"(p));
    return a;
}
__device__ __forceinline__ void cp16(uint32_t d, const void* s) {
    asm volatile("cp.async.ca.shared.global [%0], [%1], 16;" :: "r"(d), "l"(s));
}
#define CP_COMMIT() asm volatile("cp.async.commit_group;")
#define CP_WAIT1()  asm volatile("cp.async.wait_group 1;")
#define CP_WAIT0()  asm volatile("cp.async.wait_group 0;")

__device__ __forceinline__ void ldm4(uint32_t* r, uint32_t a) {
    asm volatile("ldmatrix.sync.aligned.m8n8.x4.shared.b16 {%0,%1,%2,%3}, [%4];"
                 : "=r"(r[0]), "=r"(r[1]), "=r"(r[2]), "=r"(r[3]) : "r"(a));
}
__device__ __forceinline__ void ldm4t(uint32_t* r, uint32_t a) {
    asm volatile("ldmatrix.sync.aligned.m8n8.x4.trans.shared.b16 {%0,%1,%2,%3}, [%4];"
                 : "=r"(r[0]), "=r"(r[1]), "=r"(r[2]), "=r"(r[3]) : "r"(a));
}
__device__ __forceinline__ void mma_f16(float* d, const uint32_t* a, uint32_t b0, uint32_t b1) {
    asm volatile("mma.sync.aligned.m16n8k16.row.col.f32.f16.f16.f32 "
                 "{%0,%1,%2,%3}, {%4,%5,%6,%7}, {%8,%9}, {%0,%1,%2,%3};"
                 : "+f"(d[0]), "+f"(d[1]), "+f"(d[2]), "+f"(d[3])
                 : "r"(a[0]), "r"(a[1]), "r"(a[2]), "r"(a[3]), "r"(b0), "r"(b1));
}
__device__ __forceinline__ void split_h(float v, __half& h, __half& l) {
    h = __float2half_rn(v);
    l = __float2half_rn(v - __half2float(h));
}
__device__ __forceinline__ uint32_t packh(__half a, __half b) {
    return (uint32_t)__half_as_ushort(a) | ((uint32_t)__half_as_ushort(b) << 16);
}

// ---------------------------------------------------------------------------
// K0: fuse wo into conv: Wf = wc @ wo (fp16 hi/lo row-major), bf = wc@bo + bc
// ---------------------------------------------------------------------------
__global__ __launch_bounds__(256) void k_fuse(const float* __restrict__ wo,
                                              const float* __restrict__ bo,
                                              const float* __restrict__ wc,
                                              const float* __restrict__ bc)
{
    int ob = blockIdx.x * 4;
    int i  = threadIdx.x;
    float a0 = 0.f, a1 = 0.f, a2 = 0.f, a3 = 0.f;
    for (int cc = 0; cc < 256; cc++) {
        float w = wo[cc * 256 + i];
        a0 += wc[(ob + 0) * 256 + cc] * w;
        a1 += wc[(ob + 1) * 256 + cc] * w;
        a2 += wc[(ob + 2) * 256 + cc] * w;
        a3 += wc[(ob + 3) * 256 + cc] * w;
    }
    float vals[4] = {a0, a1, a2, a3};
#pragma unroll
    for (int j = 0; j < 4; j++) {
        __half h, l;
        split_h(vals[j], h, l);
        size_t idx = (size_t)(ob + j) * 256 + i;
        g_wfh[idx] = h; g_wfl[idx] = l;
    }
    if (i < 4) {
        int o = ob + i;
        float s = 0.f;
        for (int c2 = 0; c2 < 256; c2++) s += wc[o * 256 + c2] * bo[c2];
        g_bf[o] = s + bc[o];
    }
}

// ---------------------------------------------------------------------------
// K0b: split wq (pre-scaled by 0.125) / wkv to fp16 hi/lo, row-major [768][256]
// ---------------------------------------------------------------------------
__global__ __launch_bounds__(256) void k_splitw(const float* __restrict__ wq,
                                                const float* __restrict__ wkv)
{
    int i = blockIdx.x * 256 + threadIdx.x;
    int m = i >> 8, c = i & 255;
    float v = (m < 256) ? wq[m * 256 + c] * 0.125f : wkv[(m - 256) * 256 + c];
    __half h, l;
    split_h(v, h, l);
    g_wqh[i] = h; g_wql[i] = l;
}

// ---------------------------------------------------------------------------
// K0c: x -> fp16 [k=channel][n=b*4096+p] (single precision term)
// ---------------------------------------------------------------------------
__global__ __launch_bounds__(256) void k_splitx(const float* __restrict__ x)
{
    size_t i = (size_t)(blockIdx.x * 256 + threadIdx.x) * 4;
    float4 v = *(const float4*)(x + i);
    size_t o = (size_t)((i >> 12) & 255) * NPIX + ((i >> 20) << 12) + (i & 4095);
    *(uint2*)&g_xh[o] = make_uint2(packh(__float2half_rn(v.x), __float2half_rn(v.y)),
                                   packh(__float2half_rn(v.z), __float2half_rn(v.w)));
}

// ---------------------------------------------------------------------------
// K1: QKV projection. C[768,32768] = Wqkv @ X. 2-term: Wh.X + Wl.X.
// smem per buffer: Ah 10240 | Al 10240 | Bh 8704 = 29184 B, x2 bufs.
// ---------------------------------------------------------------------------
#define QK_BUF  29184
#define QK_SMEM (QK_BUF * 2)

__global__ void __launch_bounds__(256, 2) k_qkv_tc()
{
    extern __shared__ char qsm[];
    uint32_t base = smem_u32(qsm);
    int tid = threadIdx.x, lane = tid & 31, wrp = tid >> 5;
    int wm = wrp >> 1, wn = wrp & 1;
    int mt = blockIdx.y, n0 = blockIdx.x << 7;
    int m0 = mt << 7;

    float acc[2][8][4];
#pragma unroll
    for (int a = 0; a < 2; a++)
#pragma unroll
        for (int b = 0; b < 8; b++)
#pragma unroll
            for (int c = 0; c < 4; c++) acc[a][b][c] = 0.f;

    int ar = tid >> 1, ac = (tid & 1) << 4;
    int br = tid >> 3, bc = (tid & 7) << 4;

    auto issue = [&](int s, int buf) {
        int kk = s << 5;
        uint32_t qa = base + buf * QK_BUF;
        const __half* Ah = g_wqh + (size_t)(m0 + ar) * 256 + kk + ac;
        const __half* Al = g_wql + (size_t)(m0 + ar) * 256 + kk + ac;
        uint32_t da = qa + ((ar * 40 + ac) << 1);
        cp16(da, Ah);            cp16(da + 16, Ah + 8);
        cp16(da + 10240, Al);    cp16(da + 10240 + 16, Al + 8);
        const __half* Bh = g_xh + (size_t)(kk + br) * NPIX + n0 + bc;
        uint32_t db = qa + 20480 + ((br * 136 + bc) << 1);
        cp16(db, Bh);            cp16(db + 16, Bh + 8);
    };
    auto compute = [&](int buf) {
        uint32_t qa  = base + buf * QK_BUF;
        uint32_t abh = qa, abl = qa + 10240;
        uint32_t bbh = qa + 20480;
#pragma unroll
        for (int kh = 0; kh < 32; kh += 16) {
            uint32_t ah[2][4], al[2][4];
#pragma unroll
            for (int mf = 0; mf < 2; mf++) {
                uint32_t aoff = (((wm * 32 + mf * 16 + (lane & 15)) * 40
                                  + kh + ((lane >> 4) << 3)) << 1);
                ldm4(ah[mf], abh + aoff);
                ldm4(al[mf], abl + aoff);
            }
#pragma unroll
            for (int nb = 0; nb < 4; nb++) {
                uint32_t boff = (((kh + ((lane >> 3) & 1) * 8 + (lane & 7)) * 136
                                  + wn * 64 + nb * 16 + ((lane >> 4) << 3)) << 1);
                uint32_t bh4[4];
                ldm4t(bh4, bbh + boff);
#pragma unroll
                for (int mf = 0; mf < 2; mf++) {
                    mma_f16(acc[mf][nb * 2],     ah[mf], bh4[0], bh4[1]);
                    mma_f16(acc[mf][nb * 2],     al[mf], bh4[0], bh4[1]);
                    mma_f16(acc[mf][nb * 2 + 1], ah[mf], bh4[2], bh4[3]);
                    mma_f16(acc[mf][nb * 2 + 1], al[mf], bh4[2], bh4[3]);
                }
            }
        }
    };

    issue(0, 0); CP_COMMIT();
    for (int s = 0; s < 8; s++) {
        int buf = s & 1;
        if (s + 1 < 8) { issue(s + 1, buf ^ 1); CP_COMMIT(); CP_WAIT1(); }
        else           { CP_WAIT0(); }
        __syncthreads();
        compute(buf);
        __syncthreads();
    }

    // epilogue: transpose per 32-row m-quarter via smem, write fp16 hi/lo
    float* tb = (float*)qsm;
    int g = lane >> 2, q = lane & 3;
#pragma unroll
    for (int mq = 0; mq < 4; mq++) {
        if (wm == mq) {
#pragma unroll
            for (int mf = 0; mf < 2; mf++)
#pragma unroll
                for (int nf = 0; nf < 8; nf++) {
                    int nl = wn * 64 + nf * 8 + q * 2;
                    int ml = mf * 16 + g;
                    tb[nl * 33 + ml]            = acc[mf][nf][0];
                    tb[(nl + 1) * 33 + ml]      = acc[mf][nf][1];
                    tb[nl * 33 + ml + 8]        = acc[mf][nf][2];
                    tb[(nl + 1) * 33 + ml + 8]  = acc[mf][nf][3];
                }
        }
        __syncthreads();
        int nl = tid >> 1, half2 = tid & 1;
        const float* src = tb + nl * 33 + half2 * 16;
        size_t dst = (size_t)(n0 + nl) * QKVC + m0 + mq * 32 + half2 * 16;
        unsigned short hs[16], ls[16];
#pragma unroll
        for (int u = 0; u < 16; u++) {
            __half h, l;
            split_h(src[u], h, l);
            hs[u] = __half_as_ushort(h); ls[u] = __half_as_ushort(l);
        }
        *(uint4*)&g_qh[dst]     = *(uint4*)&hs[0];
        *(uint4*)&g_qh[dst + 8] = *(uint4*)&hs[8];
        *(uint4*)&g_ql[dst]     = *(uint4*)&ls[0];
        *(uint4*)&g_ql[dst + 8] = *(uint4*)&ls[8];
        __syncthreads();
    }
}

// ---------------------------------------------------------------------------
// K2: tensor-core halo attention (3-term fp16 split; output single fp16).
// ---------------------------------------------------------------------------
#define AT_SQH  0
#define AT_SQL  9216
#define AT_SK   18432
#define AT_SKL  55296
#define AT_REL  92160
#define AT_LW   92160
#define AT_LH   96256
#define AT_RMX  100352
#define AT_RSUM 100864
#define AT_SMEM 108288

__global__ void __launch_bounds__(256, 2) k_attn_tc(const float* __restrict__ relh,
                                                    const float* __restrict__ relw)
{
    extern __shared__ char smc[];
    uint32_t sb = smem_u32(smc);
    int t = threadIdx.x, lane = t & 31, wid = t >> 5;
    int wm = wid >> 1, wn = wid & 1;
    int nbk = blockIdx.x, hh = blockIdx.y;
    int bi = nbk >> 6, tbw = nbk & 63;
    int bh = tbw >> 3, bw = tbw & 7;
    int hco = hh * 64;

    uint32_t qhB = sb + AT_SQH, qlB = sb + AT_SQL;
    uint32_t khB = sb + AT_SK,  klB = sb + AT_SKL;

    {
        int chunk = t & 7, rr = t >> 3;
#pragma unroll
        for (int p = 0; p < 2; p++) {
            int row = p * 32 + rr;
            int qx = row >> 3, qy = row & 7;
            size_t pix = (size_t)(bi * 4096 + (bh * 8 + qx) * 64 + bw * 8 + qy) * QKVC + hco;
            ((uint4*)(smc + AT_SQH))[row * 9 + chunk] = *(const uint4*)(g_qh + pix + chunk * 8);
            ((uint4*)(smc + AT_SQL))[row * 9 + chunk] = *(const uint4*)(g_ql + pix + chunk * 8);
        }
#pragma unroll
        for (int p = 0; p < 8; p++) {
            int row = p * 32 + rr;
            int ki = row >> 4, kj = row & 15;
            int gh = bh * 8 - 4 + ki, gw = bw * 8 - 4 + kj;
            bool valid = ((unsigned)gh < 64u) && ((unsigned)gw < 64u);
            size_t pix = (size_t)(valid ? bi * 4096 + gh * 64 + gw : bi * 4096) * QKVC
                       + 256 + hco + chunk * 8;
            uint4 z = make_uint4(0, 0, 0, 0);
            uint4 vh = valid ? *(const uint4*)(g_qh + pix) : z;
            uint4 vl = valid ? *(const uint4*)(g_ql + pix) : z;
            ((uint4*)(smc + AT_SK ))[row * 9 + chunk] = vh;
            ((uint4*)(smc + AT_SKL))[row * 9 + chunk] = vl;
        }
        float* srh = (float*)(smc + AT_REL);
        float* srw = (float*)(smc + AT_REL + 8064);
        for (int idx = t; idx < 1984; idx += 256) {
            int r = idx >> 6, dd = idx & 63;
            srh[r * 65 + dd] = relh[idx];
            srw[r * 65 + dd] = relw[idx];
        }
    }
    __syncthreads();

    float rv[8];
    {
        const float* srh = (const float*)(smc + AT_REL);
        const float* srw = (const float*)(smc + AT_REL + 8064);
        const __half* Qh = (const __half*)(smc + AT_SQH);
        const __half* Ql = (const __half*)(smc + AT_SQL);
#pragma unroll
        for (int m = 0; m < 8; m++) {
            int wk = t + 256 * m;
            int qi = wk >> 5, sel = (wk >> 4) & 1, pos = wk & 15;
            int qx = qi >> 3, qy = qi & 7;
            int ridx = pos - (sel ? qy : qx) + 15;
            const float* rrow = (sel ? srw : srh) + ridx * 65;
            const __half* qh = Qh + qi * 72;
            const __half* ql = Ql + qi * 72;
            float a = 0.f;
#pragma unroll 16
            for (int dd = 0; dd < 64; dd++)
                a += (__half2float(qh[dd]) + __half2float(ql[dd])) * rrow[dd];
            rv[m] = a;
        }
    }
    __syncthreads();
    {
        float* lw = (float*)(smc + AT_LW);
        float* lh = (float*)(smc + AT_LH);
#pragma unroll
        for (int m = 0; m < 8; m++) {
            int wk = t + 256 * m;
            int qi = wk >> 5, sel = (wk >> 4) & 1, pos = wk & 15;
            (sel ? lw : lh)[qi * 16 + pos] = rv[m];
        }
    }

    float s[16][4];
#pragma unroll
    for (int a = 0; a < 16; a++)
#pragma unroll
        for (int b = 0; b < 4; b++) s[a][b] = 0.f;
#pragma unroll
    for (int kt = 0; kt < 4; kt++) {
        uint32_t ah[4], al[4];
        uint32_t aoff = (((wm * 16 + (lane & 15)) * 72 + kt * 16 + ((lane >> 4) << 3)) << 1);
        ldm4(ah, qhB + aoff);
        ldm4(al, qlB + aoff);
#pragma unroll
        for (int nb = 0; nb < 8; nb++) {
            uint32_t boff = (((wn * 128 + nb * 16 + ((lane >> 4) << 3) + (lane & 7)) * 72
                             + kt * 16 + (((lane >> 3) & 1) << 3)) << 1);
            uint32_t bh4[4], bl4[4];
            ldm4(bh4, khB + boff);
            ldm4(bl4, klB + boff);
            mma_f16(s[nb * 2],     ah, bh4[0], bh4[1]);
            mma_f16(s[nb * 2],     al, bh4[0], bh4[1]);
            mma_f16(s[nb * 2],     ah, bl4[0], bl4[1]);
            mma_f16(s[nb * 2 + 1], ah, bh4[2], bh4[3]);
            mma_f16(s[nb * 2 + 1], al, bh4[2], bh4[3]);
            mma_f16(s[nb * 2 + 1], ah, bl4[2], bl4[3]);
        }
    }
    __syncthreads();

    {
        int chunk = t & 7, rr = t >> 3;
#pragma unroll
        for (int p = 0; p < 8; p++) {
            int row = p * 32 + rr;
            int ki = row >> 4, kj = row & 15;
            int gh = bh * 8 - 4 + ki, gw = bw * 8 - 4 + kj;
            bool valid = ((unsigned)gh < 64u) && ((unsigned)gw < 64u);
            size_t pix = (size_t)(valid ? bi * 4096 + gh * 64 + gw : bi * 4096) * QKVC
                       + 512 + hco + chunk * 8;
            uint32_t doff = (uint32_t)(row * 9 + chunk) << 4;
            cp16(khB + doff, g_qh + pix);
            cp16(klB + doff, g_ql + pix);
        }
        CP_COMMIT();
    }

    {
        const float* lw = (const float*)(smc + AT_LW);
        const float* lh = (const float*)(smc + AT_LH);
        int g = lane >> 2, tt = lane & 3;
#pragma unroll
        for (int nt = 0; nt < 16; nt++) {
            int jbase = wn * 128 + nt * 8 + 2 * tt;
#pragma unroll
            for (int e = 0; e < 4; e++) {
                int row = wm * 16 + g + ((e >= 2) ? 8 : 0);
                int jj = jbase + (e & 1);
                int ki = jj >> 4, kj = jj & 15;
                int gh = bh * 8 - 4 + ki, gw = bw * 8 - 4 + kj;
                if (((unsigned)gh >= 64u) || ((unsigned)gw >= 64u))
                    s[nt][e] = -3.0e38f;
                else
                    s[nt][e] += lw[row * 16 + kj] + lh[row * 16 + ki];
            }
        }
    }

    float* rmx  = (float*)(smc + AT_RMX);
    float* rsum = (float*)(smc + AT_RSUM);
    int gg = lane >> 2;
    int rA = wm * 16 + gg, rB = rA + 8;
    {
        float mA = -3.4e38f, mB = -3.4e38f;
#pragma unroll
        for (int nt = 0; nt < 16; nt++) {
            mA = fmaxf(mA, fmaxf(s[nt][0], s[nt][1]));
            mB = fmaxf(mB, fmaxf(s[nt][2], s[nt][3]));
        }
        mA = fmaxf(mA, __shfl_xor_sync(0xffffffffu, mA, 1));
        mA = fmaxf(mA, __shfl_xor_sync(0xffffffffu, mA, 2));
        mB = fmaxf(mB, __shfl_xor_sync(0xffffffffu, mB, 1));
        mB = fmaxf(mB, __shfl_xor_sync(0xffffffffu, mB, 2));
        if ((lane & 3) == 0) { rmx[wn * 64 + rA] = mA; rmx[wn * 64 + rB] = mB; }
    }
    __syncthreads();
    {
        float mA = fmaxf(rmx[rA], rmx[64 + rA]);
        float mB = fmaxf(rmx[rB], rmx[64 + rB]);
        float sA = 0.f, sB = 0.f;
#pragma unroll
        for (int nt = 0; nt < 16; nt++) {
            s[nt][0] = __expf(s[nt][0] - mA); sA += s[nt][0];
            s[nt][1] = __expf(s[nt][1] - mA); sA += s[nt][1];
            s[nt][2] = __expf(s[nt][2] - mB); sB += s[nt][2];
            s[nt][3] = __expf(s[nt][3] - mB); sB += s[nt][3];
        }
        sA += __shfl_xor_sync(0xffffffffu, sA, 1);
        sA += __shfl_xor_sync(0xffffffffu, sA, 2);
        sB += __shfl_xor_sync(0xffffffffu, sB, 1);
        sB += __shfl_xor_sync(0xffffffffu, sB, 2);
        if ((lane & 3) == 0) { rsum[wn * 64 + rA] = sA; rsum[wn * 64 + rB] = sB; }
    }
    __syncthreads();
    {
        float invA = 1.0f / (rsum[rA] + rsum[64 + rA]);
        float invB = 1.0f / (rsum[rB] + rsum[64 + rB]);
#pragma unroll
        for (int nt = 0; nt < 16; nt++) {
            float v0 = s[nt][0] * invA, v1 = s[nt][1] * invA;
            float v2 = s[nt][2] * invB, v3 = s[nt][3] * invB;
            __half h0, l0, h1, l1, h2, l2, h3, l3;
            split_h(v0, h0, l0); split_h(v1, h1, l1);
            split_h(v2, h2, l2); split_h(v3, h3, l3);
            s[nt][0] = __uint_as_float(packh(h0, h1));
            s[nt][1] = __uint_as_float(packh(h2, h3));
            s[nt][2] = __uint_as_float(packh(l0, l1));
            s[nt][3] = __uint_as_float(packh(l2, l3));
        }
    }
    CP_WAIT0();
    __syncthreads();

    float avc[8][4];
#pragma unroll
    for (int a = 0; a < 8; a++)
#pragma unroll
        for (int b = 0; b < 4; b++) avc[a][b] = 0.f;
#pragma unroll
    for (int kt2 = 0; kt2 < 8; kt2++) {
        uint32_t pa[4] = { __float_as_uint(s[2 * kt2][0]), __float_as_uint(s[2 * kt2][1]),
                           __float_as_uint(s[2 * kt2 + 1][0]), __float_as_uint(s[2 * kt2 + 1][1]) };
        uint32_t qa[4] = { __float_as_uint(s[2 * kt2][2]), __float_as_uint(s[2 * kt2][3]),
                           __float_as_uint(s[2 * kt2 + 1][2]), __float_as_uint(s[2 * kt2 + 1][3]) };
#pragma unroll
        for (int nb = 0; nb < 4; nb++) {
            uint32_t off = (((wn * 128 + kt2 * 16 + ((lane >> 3) & 1) * 8 + (lane & 7)) * 72
                            + nb * 16 + ((lane >> 4) << 3)) << 1);
            uint32_t vh4[4], vl4[4];
            ldm4t(vh4, khB + off);
            ldm4t(vl4, klB + off);
            mma_f16(avc[nb * 2],     pa, vh4[0], vh4[1]);
            mma_f16(avc[nb * 2],     qa, vh4[0], vh4[1]);
            mma_f16(avc[nb * 2],     pa, vl4[0], vl4[1]);
            mma_f16(avc[nb * 2 + 1], pa, vh4[2], vh4[3]);
            mma_f16(avc[nb * 2 + 1], qa, vh4[2], vh4[3]);
            mma_f16(avc[nb * 2 + 1], pa, vl4[2], vl4[3]);
        }
    }

    float* Red = (float*)(smc + AT_SQH);
    __syncthreads();
    if (wn == 0) {
#pragma unroll
        for (int nf = 0; nf < 8; nf++)
#pragma unroll
            for (int e = 0; e < 4; e++) {
                int row = wm * 16 + gg + ((e >= 2) ? 8 : 0);
                int col = nf * 8 + 2 * (lane & 3) + (e & 1);
                Red[row * 68 + col] = avc[nf][e];
            }
    }
    __syncthreads();
    if (wn == 1) {
#pragma unroll
        for (int nf = 0; nf < 8; nf++)
#pragma unroll
            for (int e = 0; e < 4; e++) {
                int row = wm * 16 + gg + ((e >= 2) ? 8 : 0);
                int col = nf * 8 + 2 * (lane & 3) + (e & 1);
                Red[row * 68 + col] += avc[nf][e];
            }
    }
    __syncthreads();

    {
        int qi = t >> 2, c0 = (t & 3) * 16;
        int qx = qi >> 3, qy = qi & 7;
        size_t base = (size_t)(bi * 4096 + (bh * 8 + qx) * 64 + bw * 8 + qy) * 256 + hco + c0;
        unsigned short hs[16];
#pragma unroll
        for (int u = 0; u < 16; u++)
            hs[u] = __half_as_ushort(__float2half_rn(Red[qi * 68 + c0 + u]));
        *(uint4*)&g_bh[base]     = *(uint4*)&hs[0];
        *(uint4*)&g_bh[base + 8] = *(uint4*)&hs[8];
    }
}

// ---------------------------------------------------------------------------
// K3: output GEMM + PixelShuffle. 2-term: Wh.b + Wl.b (b single fp16).
// smem per buffer: Ah 10240 | Al 10240 | Bh 10240 = 30720 B, x2.
// ---------------------------------------------------------------------------
#define KO_BUF  30720
#define KO_SMEM (KO_BUF * 2)

__global__ void __launch_bounds__(256, 2) k_out_tc(float* __restrict__ out)
{
    extern __shared__ char osm[];
    uint32_t base = smem_u32(osm);
    int tid = threadIdx.x, lane = tid & 31, wrp = tid >> 5;
    int wm = wrp >> 1, wn = wrp & 1;
    int mt = blockIdx.y, n0 = blockIdx.x << 7;
    int m0 = mt << 7;

    float acc[2][8][4];
#pragma unroll
    for (int a = 0; a < 2; a++)
#pragma unroll
        for (int b = 0; b < 8; b++)
#pragma unroll
            for (int c = 0; c < 4; c++) acc[a][b][c] = 0.f;

    int ar = tid >> 1, ac = (tid & 1) << 4;

    auto issue = [&](int s, int buf) {
        int kk = s << 5;
        uint32_t qa = base + buf * KO_BUF;
        const __half* Ah = g_wfh + (size_t)(m0 + ar) * 256 + kk + ac;
        const __half* Al = g_wfl + (size_t)(m0 + ar) * 256 + kk + ac;
        uint32_t da = qa + ((ar * 40 + ac) << 1);
        cp16(da, Ah);            cp16(da + 16, Ah + 8);
        cp16(da + 10240, Al);    cp16(da + 10240 + 16, Al + 8);
        const __half* Bh = g_bh + (size_t)(n0 + ar) * 256 + kk + ac;
        uint32_t db = qa + 20480 + ((ar * 40 + ac) << 1);
        cp16(db, Bh);            cp16(db + 16, Bh + 8);
    };
    auto compute = [&](int buf) {
        uint32_t qa  = base + buf * KO_BUF;
        uint32_t abh = qa, abl = qa + 10240;
        uint32_t bbh = qa + 20480;
#pragma unroll
        for (int kh = 0; kh < 32; kh += 16) {
            uint32_t ah[2][4], al[2][4];
#pragma unroll
            for (int mf = 0; mf < 2; mf++) {
                uint32_t aoff = (((wm * 32 + mf * 16 + (lane & 15)) * 40
                                  + kh + ((lane >> 4) << 3)) << 1);
                ldm4(ah[mf], abh + aoff);
                ldm4(al[mf], abl + aoff);
            }
#pragma unroll
            for (int nb = 0; nb < 4; nb++) {
                uint32_t boff = (((wn * 64 + nb * 16 + ((lane >> 4) << 3) + (lane & 7)) * 40
                                  + kh + (((lane >> 3) & 1) << 3)) << 1);
                uint32_t bh4[4];
                ldm4(bh4, bbh + boff);
#pragma unroll
                for (int mf = 0; mf < 2; mf++) {
                    mma_f16(acc[mf][nb * 2],     ah[mf], bh4[0], bh4[1]);
                    mma_f16(acc[mf][nb * 2],     al[mf], bh4[0], bh4[1]);
                    mma_f16(acc[mf][nb * 2 + 1], ah[mf], bh4[2], bh4[3]);
                    mma_f16(acc[mf][nb * 2 + 1], al[mf], bh4[2], bh4[3]);
                }
            }
        }
    };

    issue(0, 0); CP_COMMIT();
    for (int s = 0; s < 8; s++) {
        int buf = s & 1;
        if (s + 1 < 8) { issue(s + 1, buf ^ 1); CP_COMMIT(); CP_WAIT1(); }
        else           { CP_WAIT0(); }
        __syncthreads();
        compute(buf);
        __syncthreads();
    }

    int g = lane >> 2, q = lane & 3;
    int h0 = (n0 & 4095) >> 6, bimg = n0 >> 12;
    int hrow = h0 + wn;
#pragma unroll
    for (int mf = 0; mf < 2; mf++) {
#pragma unroll
        for (int which = 0; which < 2; which++) {
            int mm = m0 + wm * 32 + mf * 16 + g + which * 8;
            float bias = g_bf[mm];
            int cch = mm >> 2, r = (mm >> 1) & 1, s2 = mm & 1;
            float* rowp = out + ((size_t)(bimg * 256 + cch) * 128 + 2 * hrow + r) * 128 + s2;
#pragma unroll
            for (int nf = 0; nf < 8; nf++) {
                int w0 = nf * 8 + 2 * q;
                rowp[2 * w0]     = acc[mf][nf][which * 2 + 0] + bias;
                rowp[2 * w0 + 2] = acc[mf][nf][which * 2 + 1] + bias;
            }
        }
    }
}

// ---------------------------------------------------------------------------
extern "C" void kernel_launch(void* const* d_in, const int* in_sizes, int n_in,
                              void* d_out, int out_size)
{
    const float* x    = (const float*)d_in[0];
    const float* wq   = (const float*)d_in[1];
    const float* wkv  = (const float*)d_in[2];
    const float* wo   = (const float*)d_in[3];
    const float* bo   = (const float*)d_in[4];
    const float* relh = (const float*)d_in[5];
    const float* relw = (const float*)d_in[6];
    const float* wc   = (const float*)d_in[7];
    const float* bc   = (const float*)d_in[8];
    float* out = (float*)d_out;

    cudaFuncSetAttribute(k_qkv_tc,  cudaFuncAttributeMaxDynamicSharedMemorySize, QK_SMEM);
    cudaFuncSetAttribute(k_attn_tc, cudaFuncAttributeMaxDynamicSharedMemorySize, AT_SMEM);
    cudaFuncSetAttribute(k_out_tc,  cudaFuncAttributeMaxDynamicSharedMemorySize, KO_SMEM);

    k_fuse<<<256, 256>>>(wo, bo, wc, bc);
    k_splitw<<<768, 256>>>(wq, wkv);
    k_splitx<<<8192, 256>>>(x);
    k_qkv_tc<<<dim3(256, 6), 256, QK_SMEM>>>();
    k_attn_tc<<<dim3(512, 4), 256, AT_SMEM>>>(relh, relw);
    k_out_tc<<<dim3(256, 8), 256, KO_SMEM>>>(out);
}

// round 8
// speedup vs baseline: 3.5770x; 1.2492x over previous
#include <cuda_runtime.h>
#include <cuda_fp16.h>
#include <stdint.h>

#define NPIX 32768            // B*H*W
#define QKVC 768

// Scratch (device globals; 16B-aligned)
__device__ __align__(16) __half g_qh[NPIX * QKVC];  // qkv hi, [pixel][q|k|v]
__device__ __align__(16) __half g_ql[NPIX * QKVC];  // qkv lo (only q region used)
__device__ __align__(16) __half g_bh[NPIX * 256];   // attn out fp16, [n][256]
__device__ __align__(16) __half g_wfh[1024 * 256];  // fused conv W fp16, [m][k]
__device__ __align__(16) __half g_wqh[QKVC * 256];  // qkv W fp16 (q pre-scaled), [m][k]
__device__ __align__(16) __half g_xh[256 * NPIX];   // x fp16, [k][n]
__device__ float g_bf[1024];

// ---------------------------------------------------------------------------
// helpers (non-arch-specific PTX only: cp.async / ldmatrix / mma.sync)
// ---------------------------------------------------------------------------
__device__ __forceinline__ uint32_t smem_u32(const void* p) {
    uint32_t a;
    asm("{ .reg .u64 t; cvta.to.shared.u64 t, %1; cvt.u32.u64 %0, t; }" : "=r"(a) : "l"(p));
    return a;
}
__device__ __forceinline__ void cp16(uint32_t d, const void* s) {
    asm volatile("cp.async.ca.shared.global [%0], [%1], 16;" :: "r"(d), "l"(s));
}
#define CP_COMMIT() asm volatile("cp.async.commit_group;")
#define CP_WAIT1()  asm volatile("cp.async.wait_group 1;")
#define CP_WAIT0()  asm volatile("cp.async.wait_group 0;")

__device__ __forceinline__ void ldm4(uint32_t* r, uint32_t a) {
    asm volatile("ldmatrix.sync.aligned.m8n8.x4.shared.b16 {%0,%1,%2,%3}, [%4];"
                 : "=r"(r[0]), "=r"(r[1]), "=r"(r[2]), "=r"(r[3]) : "r"(a));
}
__device__ __forceinline__ void ldm4t(uint32_t* r, uint32_t a) {
    asm volatile("ldmatrix.sync.aligned.m8n8.x4.trans.shared.b16 {%0,%1,%2,%3}, [%4];"
                 : "=r"(r[0]), "=r"(r[1]), "=r"(r[2]), "=r"(r[3]) : "r"(a));
}
__device__ __forceinline__ void mma_f16(float* d, const uint32_t* a, uint32_t b0, uint32_t b1) {
    asm volatile("mma.sync.aligned.m16n8k16.row.col.f32.f16.f16.f32 "
                 "{%0,%1,%2,%3}, {%4,%5,%6,%7}, {%8,%9}, {%0,%1,%2,%3};"
                 : "+f"(d[0]), "+f"(d[1]), "+f"(d[2]), "+f"(d[3])
                 : "r"(a[0]), "r"(a[1]), "r"(a[2]), "r"(a[3]), "r"(b0), "r"(b1));
}
__device__ __forceinline__ void split_h(float v, __half& h, __half& l) {
    h = __float2half_rn(v);
    l = __float2half_rn(v - __half2float(h));
}
__device__ __forceinline__ uint32_t packh(__half a, __half b) {
    return (uint32_t)__half_as_ushort(a) | ((uint32_t)__half_as_ushort(b) << 16);
}

// ---------------------------------------------------------------------------
// K0: fuse wo into conv: Wf = wc @ wo (single fp16), bf = wc@bo + bc
// ---------------------------------------------------------------------------
__global__ __launch_bounds__(256) void k_fuse(const float* __restrict__ wo,
                                              const float* __restrict__ bo,
                                              const float* __restrict__ wc,
                                              const float* __restrict__ bc)
{
    int ob = blockIdx.x * 4;
    int i  = threadIdx.x;
    float a0 = 0.f, a1 = 0.f, a2 = 0.f, a3 = 0.f;
    for (int cc = 0; cc < 256; cc++) {
        float w = wo[cc * 256 + i];
        a0 += wc[(ob + 0) * 256 + cc] * w;
        a1 += wc[(ob + 1) * 256 + cc] * w;
        a2 += wc[(ob + 2) * 256 + cc] * w;
        a3 += wc[(ob + 3) * 256 + cc] * w;
    }
    float vals[4] = {a0, a1, a2, a3};
#pragma unroll
    for (int j = 0; j < 4; j++)
        g_wfh[(size_t)(ob + j) * 256 + i] = __float2half_rn(vals[j]);
    if (i < 4) {
        int o = ob + i;
        float s = 0.f;
        for (int c2 = 0; c2 < 256; c2++) s += wc[o * 256 + c2] * bo[c2];
        g_bf[o] = s + bc[o];
    }
}

// ---------------------------------------------------------------------------
// K0b: wq (pre-scaled by 0.125) / wkv -> single fp16 row-major [768][256]
// ---------------------------------------------------------------------------
__global__ __launch_bounds__(256) void k_splitw(const float* __restrict__ wq,
                                                const float* __restrict__ wkv)
{
    int i = blockIdx.x * 256 + threadIdx.x;
    int m = i >> 8, c = i & 255;
    float v = (m < 256) ? wq[m * 256 + c] * 0.125f : wkv[(m - 256) * 256 + c];
    g_wqh[i] = __float2half_rn(v);
}

// ---------------------------------------------------------------------------
// K0c: x -> fp16 [k=channel][n=b*4096+p]
// ---------------------------------------------------------------------------
__global__ __launch_bounds__(256) void k_splitx(const float* __restrict__ x)
{
    size_t i = (size_t)(blockIdx.x * 256 + threadIdx.x) * 4;
    float4 v = *(const float4*)(x + i);
    size_t o = (size_t)((i >> 12) & 255) * NPIX + ((i >> 20) << 12) + (i & 4095);
    *(uint2*)&g_xh[o] = make_uint2(packh(__float2half_rn(v.x), __float2half_rn(v.y)),
                                   packh(__float2half_rn(v.z), __float2half_rn(v.w)));
}

// ---------------------------------------------------------------------------
// K1: QKV projection. C[768,32768] = W @ X, single-term fp16.
// smem per buffer: A 10240 | B 8704 = 18944 B, x2 bufs.
// ---------------------------------------------------------------------------
#define QK_BUF  18944
#define QK_SMEM (QK_BUF * 2)

__global__ void __launch_bounds__(256, 2) k_qkv_tc()
{
    extern __shared__ char qsm[];
    uint32_t base = smem_u32(qsm);
    int tid = threadIdx.x, lane = tid & 31, wrp = tid >> 5;
    int wm = wrp >> 1, wn = wrp & 1;
    int mt = blockIdx.y, n0 = blockIdx.x << 7;
    int m0 = mt << 7;

    float acc[2][8][4];
#pragma unroll
    for (int a = 0; a < 2; a++)
#pragma unroll
        for (int b = 0; b < 8; b++)
#pragma unroll
            for (int c = 0; c < 4; c++) acc[a][b][c] = 0.f;

    int ar = tid >> 1, ac = (tid & 1) << 4;
    int br = tid >> 3, bc = (tid & 7) << 4;

    auto issue = [&](int s, int buf) {
        int kk = s << 5;
        uint32_t qa = base + buf * QK_BUF;
        const __half* A = g_wqh + (size_t)(m0 + ar) * 256 + kk + ac;
        uint32_t da = qa + ((ar * 40 + ac) << 1);
        cp16(da, A); cp16(da + 16, A + 8);
        const __half* B = g_xh + (size_t)(kk + br) * NPIX + n0 + bc;
        uint32_t db = qa + 10240 + ((br * 136 + bc) << 1);
        cp16(db, B); cp16(db + 16, B + 8);
    };
    auto compute = [&](int buf) {
        uint32_t qa = base + buf * QK_BUF;
        uint32_t ab = qa, bb = qa + 10240;
#pragma unroll
        for (int kh = 0; kh < 32; kh += 16) {
            uint32_t ah[2][4];
#pragma unroll
            for (int mf = 0; mf < 2; mf++)
                ldm4(ah[mf], ab + (((wm * 32 + mf * 16 + (lane & 15)) * 40
                                   + kh + ((lane >> 4) << 3)) << 1));
#pragma unroll
            for (int nb = 0; nb < 4; nb++) {
                uint32_t bh4[4];
                ldm4t(bh4, bb + (((kh + ((lane >> 3) & 1) * 8 + (lane & 7)) * 136
                                  + wn * 64 + nb * 16 + ((lane >> 4) << 3)) << 1));
#pragma unroll
                for (int mf = 0; mf < 2; mf++) {
                    mma_f16(acc[mf][nb * 2],     ah[mf], bh4[0], bh4[1]);
                    mma_f16(acc[mf][nb * 2 + 1], ah[mf], bh4[2], bh4[3]);
                }
            }
        }
    };

    issue(0, 0); CP_COMMIT();
    for (int s = 0; s < 8; s++) {
        int buf = s & 1;
        if (s + 1 < 8) { issue(s + 1, buf ^ 1); CP_COMMIT(); CP_WAIT1(); }
        else           { CP_WAIT0(); }
        __syncthreads();
        compute(buf);
        __syncthreads();
    }

    // epilogue: transpose per 32-row m-quarter via smem; lo written only for q tiles
    float* tb = (float*)qsm;
    int g = lane >> 2, q = lane & 3;
    bool writelo = (m0 < 256);
#pragma unroll
    for (int mq = 0; mq < 4; mq++) {
        if (wm == mq) {
#pragma unroll
            for (int mf = 0; mf < 2; mf++)
#pragma unroll
                for (int nf = 0; nf < 8; nf++) {
                    int nl = wn * 64 + nf * 8 + q * 2;
                    int ml = mf * 16 + g;
                    tb[nl * 33 + ml]            = acc[mf][nf][0];
                    tb[(nl + 1) * 33 + ml]      = acc[mf][nf][1];
                    tb[nl * 33 + ml + 8]        = acc[mf][nf][2];
                    tb[(nl + 1) * 33 + ml + 8]  = acc[mf][nf][3];
                }
        }
        __syncthreads();
        int nl = tid >> 1, half2 = tid & 1;
        const float* src = tb + nl * 33 + half2 * 16;
        size_t dst = (size_t)(n0 + nl) * QKVC + m0 + mq * 32 + half2 * 16;
        unsigned short hs[16], ls[16];
#pragma unroll
        for (int u = 0; u < 16; u++) {
            __half h, l;
            split_h(src[u], h, l);
            hs[u] = __half_as_ushort(h); ls[u] = __half_as_ushort(l);
        }
        *(uint4*)&g_qh[dst]     = *(uint4*)&hs[0];
        *(uint4*)&g_qh[dst + 8] = *(uint4*)&hs[8];
        if (writelo) {
            *(uint4*)&g_ql[dst]     = *(uint4*)&ls[0];
            *(uint4*)&g_ql[dst + 8] = *(uint4*)&ls[8];
        }
        __syncthreads();
    }
}

// ---------------------------------------------------------------------------
// K2: tensor-core halo attention. QK 2-term (q hi/lo, k single);
// AV 2-term (p hi/lo, v single). K/V gather single-precision.
// smem: sQh [64][72] 9216 | sQl 9216 | sK(->V) [256][72] 36864 |
//       rel 16128 (lw/lh/rmx/rsum overlay) => 71424 B. Red overlays sQ.
// ---------------------------------------------------------------------------
#define AT_SQH  0
#define AT_SQL  9216
#define AT_SK   18432
#define AT_REL  55296
#define AT_LW   55296
#define AT_LH   59392
#define AT_RMX  63488
#define AT_RSUM 64000
#define AT_SMEM 71424

__global__ void __launch_bounds__(256, 2) k_attn_tc(const float* __restrict__ relh,
                                                    const float* __restrict__ relw)
{
    extern __shared__ char smc[];
    uint32_t sb = smem_u32(smc);
    int t = threadIdx.x, lane = t & 31, wid = t >> 5;
    int wm = wid >> 1, wn = wid & 1;
    int nbk = blockIdx.x, hh = blockIdx.y;
    int bi = nbk >> 6, tbw = nbk & 63;
    int bh = tbw >> 3, bw = tbw & 7;
    int hco = hh * 64;

    uint32_t qhB = sb + AT_SQH, qlB = sb + AT_SQL;
    uint32_t khB = sb + AT_SK;

    {
        int chunk = t & 7, rr = t >> 3;
#pragma unroll
        for (int p = 0; p < 2; p++) {
            int row = p * 32 + rr;
            int qx = row >> 3, qy = row & 7;
            size_t pix = (size_t)(bi * 4096 + (bh * 8 + qx) * 64 + bw * 8 + qy) * QKVC + hco;
            ((uint4*)(smc + AT_SQH))[row * 9 + chunk] = *(const uint4*)(g_qh + pix + chunk * 8);
            ((uint4*)(smc + AT_SQL))[row * 9 + chunk] = *(const uint4*)(g_ql + pix + chunk * 8);
        }
#pragma unroll
        for (int p = 0; p < 8; p++) {
            int row = p * 32 + rr;
            int ki = row >> 4, kj = row & 15;
            int gh = bh * 8 - 4 + ki, gw = bw * 8 - 4 + kj;
            bool valid = ((unsigned)gh < 64u) && ((unsigned)gw < 64u);
            size_t pix = (size_t)(valid ? bi * 4096 + gh * 64 + gw : bi * 4096) * QKVC
                       + 256 + hco + chunk * 8;
            uint4 z = make_uint4(0, 0, 0, 0);
            ((uint4*)(smc + AT_SK))[row * 9 + chunk] = valid ? *(const uint4*)(g_qh + pix) : z;
        }
        float* srh = (float*)(smc + AT_REL);
        float* srw = (float*)(smc + AT_REL + 8064);
        for (int idx = t; idx < 1984; idx += 256) {
            int r = idx >> 6, dd = idx & 63;
            srh[r * 65 + dd] = relh[idx];
            srw[r * 65 + dd] = relw[idx];
        }
    }
    __syncthreads();

    float rv[8];
    {
        const float* srh = (const float*)(smc + AT_REL);
        const float* srw = (const float*)(smc + AT_REL + 8064);
        const __half* Qh = (const __half*)(smc + AT_SQH);
        const __half* Ql = (const __half*)(smc + AT_SQL);
#pragma unroll
        for (int m = 0; m < 8; m++) {
            int wk = t + 256 * m;
            int qi = wk >> 5, sel = (wk >> 4) & 1, pos = wk & 15;
            int qx = qi >> 3, qy = qi & 7;
            int ridx = pos - (sel ? qy : qx) + 15;
            const float* rrow = (sel ? srw : srh) + ridx * 65;
            const __half* qh = Qh + qi * 72;
            const __half* ql = Ql + qi * 72;
            float a = 0.f;
#pragma unroll 16
            for (int dd = 0; dd < 64; dd++)
                a += (__half2float(qh[dd]) + __half2float(ql[dd])) * rrow[dd];
            rv[m] = a;
        }
    }
    __syncthreads();
    {
        float* lw = (float*)(smc + AT_LW);
        float* lh = (float*)(smc + AT_LH);
#pragma unroll
        for (int m = 0; m < 8; m++) {
            int wk = t + 256 * m;
            int qi = wk >> 5, sel = (wk >> 4) & 1, pos = wk & 15;
            (sel ? lw : lh)[qi * 16 + pos] = rv[m];
        }
    }

    // ---- QK^T: 2-term (qh + ql) . kh ----
    float s[16][4];
#pragma unroll
    for (int a = 0; a < 16; a++)
#pragma unroll
        for (int b = 0; b < 4; b++) s[a][b] = 0.f;
#pragma unroll
    for (int kt = 0; kt < 4; kt++) {
        uint32_t ah[4], al[4];
        uint32_t aoff = (((wm * 16 + (lane & 15)) * 72 + kt * 16 + ((lane >> 4) << 3)) << 1);
        ldm4(ah, qhB + aoff);
        ldm4(al, qlB + aoff);
#pragma unroll
        for (int nb = 0; nb < 8; nb++) {
            uint32_t boff = (((wn * 128 + nb * 16 + ((lane >> 4) << 3) + (lane & 7)) * 72
                             + kt * 16 + (((lane >> 3) & 1) << 3)) << 1);
            uint32_t bh4[4];
            ldm4(bh4, khB + boff);
            mma_f16(s[nb * 2],     ah, bh4[0], bh4[1]);
            mma_f16(s[nb * 2],     al, bh4[0], bh4[1]);
            mma_f16(s[nb * 2 + 1], ah, bh4[2], bh4[3]);
            mma_f16(s[nb * 2 + 1], al, bh4[2], bh4[3]);
        }
    }
    __syncthreads();

    // ---- prefetch V (single fp16) into K buffer ----
    {
        int chunk = t & 7, rr = t >> 3;
#pragma unroll
        for (int p = 0; p < 8; p++) {
            int row = p * 32 + rr;
            int ki = row >> 4, kj = row & 15;
            int gh = bh * 8 - 4 + ki, gw = bw * 8 - 4 + kj;
            bool valid = ((unsigned)gh < 64u) && ((unsigned)gw < 64u);
            size_t pix = (size_t)(valid ? bi * 4096 + gh * 64 + gw : bi * 4096) * QKVC
                       + 512 + hco + chunk * 8;
            cp16(khB + ((uint32_t)(row * 9 + chunk) << 4), g_qh + pix);
        }
        CP_COMMIT();
    }

    {
        const float* lw = (const float*)(smc + AT_LW);
        const float* lh = (const float*)(smc + AT_LH);
        int g = lane >> 2, tt = lane & 3;
#pragma unroll
        for (int nt = 0; nt < 16; nt++) {
            int jbase = wn * 128 + nt * 8 + 2 * tt;
#pragma unroll
            for (int e = 0; e < 4; e++) {
                int row = wm * 16 + g + ((e >= 2) ? 8 : 0);
                int jj = jbase + (e & 1);
                int ki = jj >> 4, kj = jj & 15;
                int gh = bh * 8 - 4 + ki, gw = bw * 8 - 4 + kj;
                if (((unsigned)gh >= 64u) || ((unsigned)gw >= 64u))
                    s[nt][e] = -3.0e38f;
                else
                    s[nt][e] += lw[row * 16 + kj] + lh[row * 16 + ki];
            }
        }
    }

    float* rmx  = (float*)(smc + AT_RMX);
    float* rsum = (float*)(smc + AT_RSUM);
    int gg = lane >> 2;
    int rA = wm * 16 + gg, rB = rA + 8;
    {
        float mA = -3.4e38f, mB = -3.4e38f;
#pragma unroll
        for (int nt = 0; nt < 16; nt++) {
            mA = fmaxf(mA, fmaxf(s[nt][0], s[nt][1]));
            mB = fmaxf(mB, fmaxf(s[nt][2], s[nt][3]));
        }
        mA = fmaxf(mA, __shfl_xor_sync(0xffffffffu, mA, 1));
        mA = fmaxf(mA, __shfl_xor_sync(0xffffffffu, mA, 2));
        mB = fmaxf(mB, __shfl_xor_sync(0xffffffffu, mB, 1));
        mB = fmaxf(mB, __shfl_xor_sync(0xffffffffu, mB, 2));
        if ((lane & 3) == 0) { rmx[wn * 64 + rA] = mA; rmx[wn * 64 + rB] = mB; }
    }
    __syncthreads();
    {
        float mA = fmaxf(rmx[rA], rmx[64 + rA]);
        float mB = fmaxf(rmx[rB], rmx[64 + rB]);
        float sA = 0.f, sB = 0.f;
#pragma unroll
        for (int nt = 0; nt < 16; nt++) {
            s[nt][0] = __expf(s[nt][0] - mA); sA += s[nt][0];
            s[nt][1] = __expf(s[nt][1] - mA); sA += s[nt][1];
            s[nt][2] = __expf(s[nt][2] - mB); sB += s[nt][2];
            s[nt][3] = __expf(s[nt][3] - mB); sB += s[nt][3];
        }
        sA += __shfl_xor_sync(0xffffffffu, sA, 1);
        sA += __shfl_xor_sync(0xffffffffu, sA, 2);
        sB += __shfl_xor_sync(0xffffffffu, sB, 1);
        sB += __shfl_xor_sync(0xffffffffu, sB, 2);
        if ((lane & 3) == 0) { rsum[wn * 64 + rA] = sA; rsum[wn * 64 + rB] = sB; }
    }
    __syncthreads();
    {
        float invA = 1.0f / (rsum[rA] + rsum[64 + rA]);
        float invB = 1.0f / (rsum[rB] + rsum[64 + rB]);
#pragma unroll
        for (int nt = 0; nt < 16; nt++) {
            float v0 = s[nt][0] * invA, v1 = s[nt][1] * invA;
            float v2 = s[nt][2] * invB, v3 = s[nt][3] * invB;
            __half h0, l0, h1, l1, h2, l2, h3, l3;
            split_h(v0, h0, l0); split_h(v1, h1, l1);
            split_h(v2, h2, l2); split_h(v3, h3, l3);
            s[nt][0] = __uint_as_float(packh(h0, h1));
            s[nt][1] = __uint_as_float(packh(h2, h3));
            s[nt][2] = __uint_as_float(packh(l0, l1));
            s[nt][3] = __uint_as_float(packh(l2, l3));
        }
    }
    CP_WAIT0();
    __syncthreads();

    // ---- AV: 2-term (p hi + lo) . vh ----
    float avc[8][4];
#pragma unroll
    for (int a = 0; a < 8; a++)
#pragma unroll
        for (int b = 0; b < 4; b++) avc[a][b] = 0.f;
#pragma unroll
    for (int kt2 = 0; kt2 < 8; kt2++) {
        uint32_t pa[4] = { __float_as_uint(s[2 * kt2][0]), __float_as_uint(s[2 * kt2][1]),
                           __float_as_uint(s[2 * kt2 + 1][0]), __float_as_uint(s[2 * kt2 + 1][1]) };
        uint32_t qa[4] = { __float_as_uint(s[2 * kt2][2]), __float_as_uint(s[2 * kt2][3]),
                           __float_as_uint(s[2 * kt2 + 1][2]), __float_as_uint(s[2 * kt2 + 1][3]) };
#pragma unroll
        for (int nb = 0; nb < 4; nb++) {
            uint32_t off = (((wn * 128 + kt2 * 16 + ((lane >> 3) & 1) * 8 + (lane & 7)) * 72
                            + nb * 16 + ((lane >> 4) << 3)) << 1);
            uint32_t vh4[4];
            ldm4t(vh4, khB + off);
            mma_f16(avc[nb * 2],     pa, vh4[0], vh4[1]);
            mma_f16(avc[nb * 2],     qa, vh4[0], vh4[1]);
            mma_f16(avc[nb * 2 + 1], pa, vh4[2], vh4[3]);
            mma_f16(avc[nb * 2 + 1], qa, vh4[2], vh4[3]);
        }
    }

    float* Red = (float*)(smc + AT_SQH);
    __syncthreads();
    if (wn == 0) {
#pragma unroll
        for (int nf = 0; nf < 8; nf++)
#pragma unroll
            for (int e = 0; e < 4; e++) {
                int row = wm * 16 + gg + ((e >= 2) ? 8 : 0);
                int col = nf * 8 + 2 * (lane & 3) + (e & 1);
                Red[row * 68 + col] = avc[nf][e];
            }
    }
    __syncthreads();
    if (wn == 1) {
#pragma unroll
        for (int nf = 0; nf < 8; nf++)
#pragma unroll
            for (int e = 0; e < 4; e++) {
                int row = wm * 16 + gg + ((e >= 2) ? 8 : 0);
                int col = nf * 8 + 2 * (lane & 3) + (e & 1);
                Red[row * 68 + col] += avc[nf][e];
            }
    }
    __syncthreads();

    {
        int qi = t >> 2, c0 = (t & 3) * 16;
        int qx = qi >> 3, qy = qi & 7;
        size_t base = (size_t)(bi * 4096 + (bh * 8 + qx) * 64 + bw * 8 + qy) * 256 + hco + c0;
        unsigned short hs[16];
#pragma unroll
        for (int u = 0; u < 16; u++)
            hs[u] = __half_as_ushort(__float2half_rn(Red[qi * 68 + c0 + u]));
        *(uint4*)&g_bh[base]     = *(uint4*)&hs[0];
        *(uint4*)&g_bh[base + 8] = *(uint4*)&hs[8];
    }
}

// ---------------------------------------------------------------------------
// K3: output GEMM + PixelShuffle. Single-term fp16.
// smem per buffer: A 10240 | B 10240 = 20480, x2.
// ---------------------------------------------------------------------------
#define KO_BUF  20480
#define KO_SMEM (KO_BUF * 2)

__global__ void __launch_bounds__(256, 2) k_out_tc(float* __restrict__ out)
{
    extern __shared__ char osm[];
    uint32_t base = smem_u32(osm);
    int tid = threadIdx.x, lane = tid & 31, wrp = tid >> 5;
    int wm = wrp >> 1, wn = wrp & 1;
    int mt = blockIdx.y, n0 = blockIdx.x << 7;
    int m0 = mt << 7;

    float acc[2][8][4];
#pragma unroll
    for (int a = 0; a < 2; a++)
#pragma unroll
        for (int b = 0; b < 8; b++)
#pragma unroll
            for (int c = 0; c < 4; c++) acc[a][b][c] = 0.f;

    int ar = tid >> 1, ac = (tid & 1) << 4;

    auto issue = [&](int s, int buf) {
        int kk = s << 5;
        uint32_t qa = base + buf * KO_BUF;
        const __half* A = g_wfh + (size_t)(m0 + ar) * 256 + kk + ac;
        uint32_t da = qa + ((ar * 40 + ac) << 1);
        cp16(da, A); cp16(da + 16, A + 8);
        const __half* B = g_bh + (size_t)(n0 + ar) * 256 + kk + ac;
        uint32_t db = qa + 10240 + ((ar * 40 + ac) << 1);
        cp16(db, B); cp16(db + 16, B + 8);
    };
    auto compute = [&](int buf) {
        uint32_t qa = base + buf * KO_BUF;
        uint32_t ab = qa, bb = qa + 10240;
#pragma unroll
        for (int kh = 0; kh < 32; kh += 16) {
            uint32_t ah[2][4];
#pragma unroll
            for (int mf = 0; mf < 2; mf++)
                ldm4(ah[mf], ab + (((wm * 32 + mf * 16 + (lane & 15)) * 40
                                   + kh + ((lane >> 4) << 3)) << 1));
#pragma unroll
            for (int nb = 0; nb < 4; nb++) {
                uint32_t bh4[4];
                ldm4(bh4, bb + (((wn * 64 + nb * 16 + ((lane >> 4) << 3) + (lane & 7)) * 40
                                 + kh + (((lane >> 3) & 1) << 3)) << 1));
#pragma unroll
                for (int mf = 0; mf < 2; mf++) {
                    mma_f16(acc[mf][nb * 2],     ah[mf], bh4[0], bh4[1]);
                    mma_f16(acc[mf][nb * 2 + 1], ah[mf], bh4[2], bh4[3]);
                }
            }
        }
    };

    issue(0, 0); CP_COMMIT();
    for (int s = 0; s < 8; s++) {
        int buf = s & 1;
        if (s + 1 < 8) { issue(s + 1, buf ^ 1); CP_COMMIT(); CP_WAIT1(); }
        else           { CP_WAIT0(); }
        __syncthreads();
        compute(buf);
        __syncthreads();
    }

    int g = lane >> 2, q = lane & 3;
    int h0 = (n0 & 4095) >> 6, bimg = n0 >> 12;
    int hrow = h0 + wn;
#pragma unroll
    for (int mf = 0; mf < 2; mf++) {
#pragma unroll
        for (int which = 0; which < 2; which++) {
            int mm = m0 + wm * 32 + mf * 16 + g + which * 8;
            float bias = g_bf[mm];
            int cch = mm >> 2, r = (mm >> 1) & 1, s2 = mm & 1;
            float* rowp = out + ((size_t)(bimg * 256 + cch) * 128 + 2 * hrow + r) * 128 + s2;
#pragma unroll
            for (int nf = 0; nf < 8; nf++) {
                int w0 = nf * 8 + 2 * q;
                rowp[2 * w0]     = acc[mf][nf][which * 2 + 0] + bias;
                rowp[2 * w0 + 2] = acc[mf][nf][which * 2 + 1] + bias;
            }
        }
    }
}

// ---------------------------------------------------------------------------
extern "C" void kernel_launch(void* const* d_in, const int* in_sizes, int n_in,
                              void* d_out, int out_size)
{
    const float* x    = (const float*)d_in[0];
    const float* wq   = (const float*)d_in[1];
    const float* wkv  = (const float*)d_in[2];
    const float* wo   = (const float*)d_in[3];
    const float* bo   = (const float*)d_in[4];
    const float* relh = (const float*)d_in[5];
    const float* relw = (const float*)d_in[6];
    const float* wc   = (const float*)d_in[7];
    const float* bc   = (const float*)d_in[8];
    float* out = (float*)d_out;

    cudaFuncSetAttribute(k_qkv_tc,  cudaFuncAttributeMaxDynamicSharedMemorySize, QK_SMEM);
    cudaFuncSetAttribute(k_attn_tc, cudaFuncAttributeMaxDynamicSharedMemorySize, AT_SMEM);
    cudaFuncSetAttribute(k_out_tc,  cudaFuncAttributeMaxDynamicSharedMemorySize, KO_SMEM);

    k_fuse<<<256, 256>>>(wo, bo, wc, bc);
    k_splitw<<<768, 256>>>(wq, wkv);
    k_splitx<<<8192, 256>>>(x);
    k_qkv_tc<<<dim3(256, 6), 256, QK_SMEM>>>();
    k_attn_tc<<<dim3(512, 4), 256, AT_SMEM>>>(relh, relw);
    k_out_tc<<<dim3(256, 8), 256, KO_SMEM>>>(out);
}

// round 9
// speedup vs baseline: 3.8405x; 1.0737x over previous
#include <cuda_runtime.h>
#include <cuda_fp16.h>
#include <stdint.h>

#define NPIX 32768            // B*H*W
#define QKVC 768

// Scratch (device globals; 16B-aligned)
__device__ __align__(16) __half g_qh[NPIX * QKVC];  // qkv fp16, [pixel][q|k|v]
__device__ __align__(16) __half g_bh[NPIX * 256];   // attn out fp16, [n][256]
__device__ __align__(16) __half g_wfh[1024 * 256];  // fused conv W fp16, [m][k]
__device__ __align__(16) __half g_wqh[QKVC * 256];  // qkv W fp16 (q pre-scaled), [m][k]
__device__ __align__(16) __half g_xh[256 * NPIX];   // x fp16, [k][n]
__device__ float g_bf[1024];

// ---------------------------------------------------------------------------
// helpers (non-arch-specific PTX only: cp.async / ldmatrix / mma.sync)
// ---------------------------------------------------------------------------
__device__ __forceinline__ uint32_t smem_u32(const void* p) {
    uint32_t a;
    asm("{ .reg .u64 t; cvta.to.shared.u64 t, %1; cvt.u32.u64 %0, t; }" : "=r"(a) : "l"(p));
    return a;
}
__device__ __forceinline__ void cp16(uint32_t d, const void* s) {
    asm volatile("cp.async.ca.shared.global [%0], [%1], 16;" :: "r"(d), "l"(s));
}
#define CP_COMMIT() asm volatile("cp.async.commit_group;")
#define CP_WAIT1()  asm volatile("cp.async.wait_group 1;")
#define CP_WAIT0()  asm volatile("cp.async.wait_group 0;")

__device__ __forceinline__ void ldm4(uint32_t* r, uint32_t a) {
    asm volatile("ldmatrix.sync.aligned.m8n8.x4.shared.b16 {%0,%1,%2,%3}, [%4];"
                 : "=r"(r[0]), "=r"(r[1]), "=r"(r[2]), "=r"(r[3]) : "r"(a));
}
__device__ __forceinline__ void ldm4t(uint32_t* r, uint32_t a) {
    asm volatile("ldmatrix.sync.aligned.m8n8.x4.trans.shared.b16 {%0,%1,%2,%3}, [%4];"
                 : "=r"(r[0]), "=r"(r[1]), "=r"(r[2]), "=r"(r[3]) : "r"(a));
}
__device__ __forceinline__ void mma_f16(float* d, const uint32_t* a, uint32_t b0, uint32_t b1) {
    asm volatile("mma.sync.aligned.m16n8k16.row.col.f32.f16.f16.f32 "
                 "{%0,%1,%2,%3}, {%4,%5,%6,%7}, {%8,%9}, {%0,%1,%2,%3};"
                 : "+f"(d[0]), "+f"(d[1]), "+f"(d[2]), "+f"(d[3])
                 : "r"(a[0]), "r"(a[1]), "r"(a[2]), "r"(a[3]), "r"(b0), "r"(b1));
}
__device__ __forceinline__ uint32_t packh(__half a, __half b) {
    return (uint32_t)__half_as_ushort(a) | ((uint32_t)__half_as_ushort(b) << 16);
}

// ---------------------------------------------------------------------------
// K0: fuse wo into conv: Wf = wc @ wo (fp16), bf = wc@bo + bc
// ---------------------------------------------------------------------------
__global__ __launch_bounds__(256) void k_fuse(const float* __restrict__ wo,
                                              const float* __restrict__ bo,
                                              const float* __restrict__ wc,
                                              const float* __restrict__ bc)
{
    int ob = blockIdx.x * 4;
    int i  = threadIdx.x;
    float a0 = 0.f, a1 = 0.f, a2 = 0.f, a3 = 0.f;
    for (int cc = 0; cc < 256; cc++) {
        float w = wo[cc * 256 + i];
        a0 += wc[(ob + 0) * 256 + cc] * w;
        a1 += wc[(ob + 1) * 256 + cc] * w;
        a2 += wc[(ob + 2) * 256 + cc] * w;
        a3 += wc[(ob + 3) * 256 + cc] * w;
    }
    float vals[4] = {a0, a1, a2, a3};
#pragma unroll
    for (int j = 0; j < 4; j++)
        g_wfh[(size_t)(ob + j) * 256 + i] = __float2half_rn(vals[j]);
    if (i < 4) {
        int o = ob + i;
        float s = 0.f;
        for (int c2 = 0; c2 < 256; c2++) s += wc[o * 256 + c2] * bo[c2];
        g_bf[o] = s + bc[o];
    }
}

// ---------------------------------------------------------------------------
// K0b: wq (pre-scaled by 0.125) / wkv -> fp16 row-major [768][256]
// ---------------------------------------------------------------------------
__global__ __launch_bounds__(256) void k_splitw(const float* __restrict__ wq,
                                                const float* __restrict__ wkv)
{
    int i = blockIdx.x * 256 + threadIdx.x;
    int m = i >> 8, c = i & 255;
    float v = (m < 256) ? wq[m * 256 + c] * 0.125f : wkv[(m - 256) * 256 + c];
    g_wqh[i] = __float2half_rn(v);
}

// ---------------------------------------------------------------------------
// K0c: x -> fp16 [k=channel][n=b*4096+p]
// ---------------------------------------------------------------------------
__global__ __launch_bounds__(256) void k_splitx(const float* __restrict__ x)
{
    size_t i = (size_t)(blockIdx.x * 256 + threadIdx.x) * 4;
    float4 v = *(const float4*)(x + i);
    size_t o = (size_t)((i >> 12) & 255) * NPIX + ((i >> 20) << 12) + (i & 4095);
    *(uint2*)&g_xh[o] = make_uint2(packh(__float2half_rn(v.x), __float2half_rn(v.y)),
                                   packh(__float2half_rn(v.z), __float2half_rn(v.w)));
}

// ---------------------------------------------------------------------------
// K1: QKV projection. C[768,32768] = W @ X, fp16 single-term.
// 3-stage cp.async ring, one __syncthreads per stage.
// smem per buffer: A 10240 | B 8704 = 18944 B, x3 bufs.
// ---------------------------------------------------------------------------
#define QK_BUF  18944
#define QK_SMEM (QK_BUF * 3)

__global__ void __launch_bounds__(256, 2) k_qkv_tc()
{
    extern __shared__ char qsm[];
    uint32_t base = smem_u32(qsm);
    int tid = threadIdx.x, lane = tid & 31, wrp = tid >> 5;
    int wm = wrp >> 1, wn = wrp & 1;
    int mt = blockIdx.y, n0 = blockIdx.x << 7;
    int m0 = mt << 7;

    float acc[2][8][4];
#pragma unroll
    for (int a = 0; a < 2; a++)
#pragma unroll
        for (int b = 0; b < 8; b++)
#pragma unroll
            for (int c = 0; c < 4; c++) acc[a][b][c] = 0.f;

    int ar = tid >> 1, ac = (tid & 1) << 4;
    int br = tid >> 3, bc = (tid & 7) << 4;

    auto issue = [&](int s, int buf) {
        int kk = s << 5;
        uint32_t qa = base + buf * QK_BUF;
        const __half* A = g_wqh + (size_t)(m0 + ar) * 256 + kk + ac;
        uint32_t da = qa + ((ar * 40 + ac) << 1);
        cp16(da, A); cp16(da + 16, A + 8);
        const __half* B = g_xh + (size_t)(kk + br) * NPIX + n0 + bc;
        uint32_t db = qa + 10240 + ((br * 136 + bc) << 1);
        cp16(db, B); cp16(db + 16, B + 8);
    };
    auto compute = [&](int buf) {
        uint32_t qa = base + buf * QK_BUF;
        uint32_t ab = qa, bb = qa + 10240;
#pragma unroll
        for (int kh = 0; kh < 32; kh += 16) {
            uint32_t ah[2][4];
#pragma unroll
            for (int mf = 0; mf < 2; mf++)
                ldm4(ah[mf], ab + (((wm * 32 + mf * 16 + (lane & 15)) * 40
                                   + kh + ((lane >> 4) << 3)) << 1));
#pragma unroll
            for (int nb = 0; nb < 4; nb++) {
                uint32_t bh4[4];
                ldm4t(bh4, bb + (((kh + ((lane >> 3) & 1) * 8 + (lane & 7)) * 136
                                  + wn * 64 + nb * 16 + ((lane >> 4) << 3)) << 1));
#pragma unroll
                for (int mf = 0; mf < 2; mf++) {
                    mma_f16(acc[mf][nb * 2],     ah[mf], bh4[0], bh4[1]);
                    mma_f16(acc[mf][nb * 2 + 1], ah[mf], bh4[2], bh4[3]);
                }
            }
        }
    };

    issue(0, 0); CP_COMMIT();
    issue(1, 1); CP_COMMIT();
    for (int s = 0; s < 8; s++) {
        if (s < 7) CP_WAIT1(); else CP_WAIT0();
        __syncthreads();
        if (s + 2 < 8) { issue(s + 2, (s + 2) % 3); CP_COMMIT(); }
        compute(s % 3);
    }
    __syncthreads();

    // epilogue: transpose per 32-row m-quarter via smem; write fp16
    float* tb = (float*)qsm;
    int g = lane >> 2, q = lane & 3;
#pragma unroll
    for (int mq = 0; mq < 4; mq++) {
        if (wm == mq) {
#pragma unroll
            for (int mf = 0; mf < 2; mf++)
#pragma unroll
                for (int nf = 0; nf < 8; nf++) {
                    int nl = wn * 64 + nf * 8 + q * 2;
                    int ml = mf * 16 + g;
                    tb[nl * 33 + ml]            = acc[mf][nf][0];
                    tb[(nl + 1) * 33 + ml]      = acc[mf][nf][1];
                    tb[nl * 33 + ml + 8]        = acc[mf][nf][2];
                    tb[(nl + 1) * 33 + ml + 8]  = acc[mf][nf][3];
                }
        }
        __syncthreads();
        int nl = tid >> 1, half2 = tid & 1;
        const float* src = tb + nl * 33 + half2 * 16;
        size_t dst = (size_t)(n0 + nl) * QKVC + m0 + mq * 32 + half2 * 16;
        unsigned short hs[16];
#pragma unroll
        for (int u = 0; u < 16; u++)
            hs[u] = __half_as_ushort(__float2half_rn(src[u]));
        *(uint4*)&g_qh[dst]     = *(uint4*)&hs[0];
        *(uint4*)&g_qh[dst + 8] = *(uint4*)&hs[8];
        __syncthreads();
    }
}

// ---------------------------------------------------------------------------
// K2: tensor-core halo attention, all-fp16 single-term MMAs.
// smem: sQ [64][72] 9216 | sK(->V) [256][72] 36864 | rel 16128 (lw/lh/rmx/rsum
// overlay) = 62208 B. Red overlays sK after AV.
// ---------------------------------------------------------------------------
#define AT_SQ   0
#define AT_SK   9216
#define AT_REL  46080
#define AT_LW   46080
#define AT_LH   50176
#define AT_RMX  54272
#define AT_RSUM 54784
#define AT_SMEM 62208

__global__ void __launch_bounds__(256, 2) k_attn_tc(const float* __restrict__ relh,
                                                    const float* __restrict__ relw)
{
    extern __shared__ char smc[];
    uint32_t sb = smem_u32(smc);
    int t = threadIdx.x, lane = t & 31, wid = t >> 5;
    int wm = wid >> 1, wn = wid & 1;
    int nbk = blockIdx.x, hh = blockIdx.y;
    int bi = nbk >> 6, tbw = nbk & 63;
    int bh = tbw >> 3, bw = tbw & 7;
    int hco = hh * 64;

    uint32_t qB = sb + AT_SQ;
    uint32_t kB = sb + AT_SK;

    {
        int chunk = t & 7, rr = t >> 3;
        {
            int row = rr;               // rows 0..31
            int qx = row >> 3, qy = row & 7;
            size_t pix = (size_t)(bi * 4096 + (bh * 8 + qx) * 64 + bw * 8 + qy) * QKVC + hco;
            ((uint4*)(smc + AT_SQ))[row * 9 + chunk] = *(const uint4*)(g_qh + pix + chunk * 8);
            row = rr + 32;
            qx = row >> 3; qy = row & 7;
            pix = (size_t)(bi * 4096 + (bh * 8 + qx) * 64 + bw * 8 + qy) * QKVC + hco;
            ((uint4*)(smc + AT_SQ))[row * 9 + chunk] = *(const uint4*)(g_qh + pix + chunk * 8);
        }
#pragma unroll
        for (int p = 0; p < 8; p++) {
            int row = p * 32 + rr;
            int ki = row >> 4, kj = row & 15;
            int gh = bh * 8 - 4 + ki, gw = bw * 8 - 4 + kj;
            bool valid = ((unsigned)gh < 64u) && ((unsigned)gw < 64u);
            size_t pix = (size_t)(valid ? bi * 4096 + gh * 64 + gw : bi * 4096) * QKVC
                       + 256 + hco + chunk * 8;
            uint4 z = make_uint4(0, 0, 0, 0);
            ((uint4*)(smc + AT_SK))[row * 9 + chunk] = valid ? *(const uint4*)(g_qh + pix) : z;
        }
        float* srh = (float*)(smc + AT_REL);
        float* srw = (float*)(smc + AT_REL + 8064);
        for (int idx = t; idx < 1984; idx += 256) {
            int r = idx >> 6, dd = idx & 63;
            srh[r * 65 + dd] = relh[idx];
            srw[r * 65 + dd] = relw[idx];
        }
    }
    __syncthreads();

    float rv[8];
    {
        const float* srh = (const float*)(smc + AT_REL);
        const float* srw = (const float*)(smc + AT_REL + 8064);
        const __half* Q = (const __half*)(smc + AT_SQ);
#pragma unroll
        for (int m = 0; m < 8; m++) {
            int wk = t + 256 * m;
            int qi = wk >> 5, sel = (wk >> 4) & 1, pos = wk & 15;
            int qx = qi >> 3, qy = qi & 7;
            int ridx = pos - (sel ? qy : qx) + 15;
            const float* rrow = (sel ? srw : srh) + ridx * 65;
            const __half* qh = Q + qi * 72;
            float a = 0.f;
#pragma unroll 16
            for (int dd = 0; dd < 64; dd++)
                a += __half2float(qh[dd]) * rrow[dd];
            rv[m] = a;
        }
    }
    __syncthreads();
    {
        float* lw = (float*)(smc + AT_LW);
        float* lh = (float*)(smc + AT_LH);
#pragma unroll
        for (int m = 0; m < 8; m++) {
            int wk = t + 256 * m;
            int qi = wk >> 5, sel = (wk >> 4) & 1, pos = wk & 15;
            (sel ? lw : lh)[qi * 16 + pos] = rv[m];
        }
    }

    // ---- QK^T: single-term fp16 ----
    float s[16][4];
#pragma unroll
    for (int a = 0; a < 16; a++)
#pragma unroll
        for (int b = 0; b < 4; b++) s[a][b] = 0.f;
#pragma unroll
    for (int kt = 0; kt < 4; kt++) {
        uint32_t ah[4];
        ldm4(ah, qB + (((wm * 16 + (lane & 15)) * 72 + kt * 16 + ((lane >> 4) << 3)) << 1));
#pragma unroll
        for (int nb = 0; nb < 8; nb++) {
            uint32_t boff = (((wn * 128 + nb * 16 + ((lane >> 4) << 3) + (lane & 7)) * 72
                             + kt * 16 + (((lane >> 3) & 1) << 3)) << 1);
            uint32_t bh4[4];
            ldm4(bh4, kB + boff);
            mma_f16(s[nb * 2],     ah, bh4[0], bh4[1]);
            mma_f16(s[nb * 2 + 1], ah, bh4[2], bh4[3]);
        }
    }
    __syncthreads();

    // ---- prefetch V into K buffer ----
    {
        int chunk = t & 7, rr = t >> 3;
#pragma unroll
        for (int p = 0; p < 8; p++) {
            int row = p * 32 + rr;
            int ki = row >> 4, kj = row & 15;
            int gh = bh * 8 - 4 + ki, gw = bw * 8 - 4 + kj;
            bool valid = ((unsigned)gh < 64u) && ((unsigned)gw < 64u);
            size_t pix = (size_t)(valid ? bi * 4096 + gh * 64 + gw : bi * 4096) * QKVC
                       + 512 + hco + chunk * 8;
            cp16(kB + ((uint32_t)(row * 9 + chunk) << 4), g_qh + pix);
        }
        CP_COMMIT();
    }

    {
        const float* lw = (const float*)(smc + AT_LW);
        const float* lh = (const float*)(smc + AT_LH);
        int g = lane >> 2, tt = lane & 3;
#pragma unroll
        for (int nt = 0; nt < 16; nt++) {
            int jbase = wn * 128 + nt * 8 + 2 * tt;
#pragma unroll
            for (int e = 0; e < 4; e++) {
                int row = wm * 16 + g + ((e >= 2) ? 8 : 0);
                int jj = jbase + (e & 1);
                int ki = jj >> 4, kj = jj & 15;
                int gh = bh * 8 - 4 + ki, gw = bw * 8 - 4 + kj;
                if (((unsigned)gh >= 64u) || ((unsigned)gw >= 64u))
                    s[nt][e] = -3.0e38f;
                else
                    s[nt][e] += lw[row * 16 + kj] + lh[row * 16 + ki];
            }
        }
    }

    float* rmx  = (float*)(smc + AT_RMX);
    float* rsum = (float*)(smc + AT_RSUM);
    int gg = lane >> 2;
    int rA = wm * 16 + gg, rB = rA + 8;
    {
        float mA = -3.4e38f, mB = -3.4e38f;
#pragma unroll
        for (int nt = 0; nt < 16; nt++) {
            mA = fmaxf(mA, fmaxf(s[nt][0], s[nt][1]));
            mB = fmaxf(mB, fmaxf(s[nt][2], s[nt][3]));
        }
        mA = fmaxf(mA, __shfl_xor_sync(0xffffffffu, mA, 1));
        mA = fmaxf(mA, __shfl_xor_sync(0xffffffffu, mA, 2));
        mB = fmaxf(mB, __shfl_xor_sync(0xffffffffu, mB, 1));
        mB = fmaxf(mB, __shfl_xor_sync(0xffffffffu, mB, 2));
        if ((lane & 3) == 0) { rmx[wn * 64 + rA] = mA; rmx[wn * 64 + rB] = mB; }
    }
    __syncthreads();
    {
        float mA = fmaxf(rmx[rA], rmx[64 + rA]);
        float mB = fmaxf(rmx[rB], rmx[64 + rB]);
        float sA = 0.f, sB = 0.f;
#pragma unroll
        for (int nt = 0; nt < 16; nt++) {
            s[nt][0] = __expf(s[nt][0] - mA); sA += s[nt][0];
            s[nt][1] = __expf(s[nt][1] - mA); sA += s[nt][1];
            s[nt][2] = __expf(s[nt][2] - mB); sB += s[nt][2];
            s[nt][3] = __expf(s[nt][3] - mB); sB += s[nt][3];
        }
        sA += __shfl_xor_sync(0xffffffffu, sA, 1);
        sA += __shfl_xor_sync(0xffffffffu, sA, 2);
        sB += __shfl_xor_sync(0xffffffffu, sB, 1);
        sB += __shfl_xor_sync(0xffffffffu, sB, 2);
        if ((lane & 3) == 0) { rsum[wn * 64 + rA] = sA; rsum[wn * 64 + rB] = sB; }
    }
    __syncthreads();
    {
        float invA = 1.0f / (rsum[rA] + rsum[64 + rA]);
        float invB = 1.0f / (rsum[rB] + rsum[64 + rB]);
        // P -> fp16 A-fragments in place (hi only)
#pragma unroll
        for (int nt = 0; nt < 16; nt++) {
            __half h0 = __float2half_rn(s[nt][0] * invA);
            __half h1 = __float2half_rn(s[nt][1] * invA);
            __half h2 = __float2half_rn(s[nt][2] * invB);
            __half h3 = __float2half_rn(s[nt][3] * invB);
            s[nt][0] = __uint_as_float(packh(h0, h1));
            s[nt][1] = __uint_as_float(packh(h2, h3));
        }
    }
    CP_WAIT0();
    __syncthreads();

    // ---- AV: single-term fp16 ----
    float avc[8][4];
#pragma unroll
    for (int a = 0; a < 8; a++)
#pragma unroll
        for (int b = 0; b < 4; b++) avc[a][b] = 0.f;
#pragma unroll
    for (int kt2 = 0; kt2 < 8; kt2++) {
        uint32_t pa[4] = { __float_as_uint(s[2 * kt2][0]), __float_as_uint(s[2 * kt2][1]),
                           __float_as_uint(s[2 * kt2 + 1][0]), __float_as_uint(s[2 * kt2 + 1][1]) };
#pragma unroll
        for (int nb = 0; nb < 4; nb++) {
            uint32_t off = (((wn * 128 + kt2 * 16 + ((lane >> 3) & 1) * 8 + (lane & 7)) * 72
                            + nb * 16 + ((lane >> 4) << 3)) << 1);
            uint32_t vh4[4];
            ldm4t(vh4, kB + off);
            mma_f16(avc[nb * 2],     pa, vh4[0], vh4[1]);
            mma_f16(avc[nb * 2 + 1], pa, vh4[2], vh4[3]);
        }
    }

    // cross-warp reduction (Red overlays sK; V consumed)
    float* Red = (float*)(smc + AT_SK);
    __syncthreads();
    if (wn == 0) {
#pragma unroll
        for (int nf = 0; nf < 8; nf++)
#pragma unroll
            for (int e = 0; e < 4; e++) {
                int row = wm * 16 + gg + ((e >= 2) ? 8 : 0);
                int col = nf * 8 + 2 * (lane & 3) + (e & 1);
                Red[row * 68 + col] = avc[nf][e];
            }
    }
    __syncthreads();
    if (wn == 1) {
#pragma unroll
        for (int nf = 0; nf < 8; nf++)
#pragma unroll
            for (int e = 0; e < 4; e++) {
                int row = wm * 16 + gg + ((e >= 2) ? 8 : 0);
                int col = nf * 8 + 2 * (lane & 3) + (e & 1);
                Red[row * 68 + col] += avc[nf][e];
            }
    }
    __syncthreads();

    {
        int qi = t >> 2, c0 = (t & 3) * 16;
        int qx = qi >> 3, qy = qi & 7;
        size_t base = (size_t)(bi * 4096 + (bh * 8 + qx) * 64 + bw * 8 + qy) * 256 + hco + c0;
        unsigned short hs[16];
#pragma unroll
        for (int u = 0; u < 16; u++)
            hs[u] = __half_as_ushort(__float2half_rn(Red[qi * 68 + c0 + u]));
        *(uint4*)&g_bh[base]     = *(uint4*)&hs[0];
        *(uint4*)&g_bh[base + 8] = *(uint4*)&hs[8];
    }
}

// ---------------------------------------------------------------------------
// K3: output GEMM + PixelShuffle. fp16 single-term, 3-stage ring.
// smem per buffer: A 10240 | B 10240 = 20480, x3.
// ---------------------------------------------------------------------------
#define KO_BUF  20480
#define KO_SMEM (KO_BUF * 3)

__global__ void __launch_bounds__(256, 2) k_out_tc(float* __restrict__ out)
{
    extern __shared__ char osm[];
    uint32_t base = smem_u32(osm);
    int tid = threadIdx.x, lane = tid & 31, wrp = tid >> 5;
    int wm = wrp >> 1, wn = wrp & 1;
    int mt = blockIdx.y, n0 = blockIdx.x << 7;
    int m0 = mt << 7;

    float acc[2][8][4];
#pragma unroll
    for (int a = 0; a < 2; a++)
#pragma unroll
        for (int b = 0; b < 8; b++)
#pragma unroll
            for (int c = 0; c < 4; c++) acc[a][b][c] = 0.f;

    int ar = tid >> 1, ac = (tid & 1) << 4;

    auto issue = [&](int s, int buf) {
        int kk = s << 5;
        uint32_t qa = base + buf * KO_BUF;
        const __half* A = g_wfh + (size_t)(m0 + ar) * 256 + kk + ac;
        uint32_t da = qa + ((ar * 40 + ac) << 1);
        cp16(da, A); cp16(da + 16, A + 8);
        const __half* B = g_bh + (size_t)(n0 + ar) * 256 + kk + ac;
        uint32_t db = qa + 10240 + ((ar * 40 + ac) << 1);
        cp16(db, B); cp16(db + 16, B + 8);
    };
    auto compute = [&](int buf) {
        uint32_t qa = base + buf * KO_BUF;
        uint32_t ab = qa, bb = qa + 10240;
#pragma unroll
        for (int kh = 0; kh < 32; kh += 16) {
            uint32_t ah[2][4];
#pragma unroll
            for (int mf = 0; mf < 2; mf++)
                ldm4(ah[mf], ab + (((wm * 32 + mf * 16 + (lane & 15)) * 40
                                   + kh + ((lane >> 4) << 3)) << 1));
#pragma unroll
            for (int nb = 0; nb < 4; nb++) {
                uint32_t bh4[4];
                ldm4(bh4, bb + (((wn * 64 + nb * 16 + ((lane >> 4) << 3) + (lane & 7)) * 40
                                 + kh + (((lane >> 3) & 1) << 3)) << 1));
#pragma unroll
                for (int mf = 0; mf < 2; mf++) {
                    mma_f16(acc[mf][nb * 2],     ah[mf], bh4[0], bh4[1]);
                    mma_f16(acc[mf][nb * 2 + 1], ah[mf], bh4[2], bh4[3]);
                }
            }
        }
    };

    issue(0, 0); CP_COMMIT();
    issue(1, 1); CP_COMMIT();
    for (int s = 0; s < 8; s++) {
        if (s < 7) CP_WAIT1(); else CP_WAIT0();
        __syncthreads();
        if (s + 2 < 8) { issue(s + 2, (s + 2) % 3); CP_COMMIT(); }
        compute(s % 3);
    }

    int g = lane >> 2, q = lane & 3;
    int h0 = (n0 & 4095) >> 6, bimg = n0 >> 12;
    int hrow = h0 + wn;
#pragma unroll
    for (int mf = 0; mf < 2; mf++) {
#pragma unroll
        for (int which = 0; which < 2; which++) {
            int mm = m0 + wm * 32 + mf * 16 + g + which * 8;
            float bias = g_bf[mm];
            int cch = mm >> 2, r = (mm >> 1) & 1, s2 = mm & 1;
            float* rowp = out + ((size_t)(bimg * 256 + cch) * 128 + 2 * hrow + r) * 128 + s2;
#pragma unroll
            for (int nf = 0; nf < 8; nf++) {
                int w0 = nf * 8 + 2 * q;
                rowp[2 * w0]     = acc[mf][nf][which * 2 + 0] + bias;
                rowp[2 * w0 + 2] = acc[mf][nf][which * 2 + 1] + bias;
            }
        }
    }
}

// ---------------------------------------------------------------------------
extern "C" void kernel_launch(void* const* d_in, const int* in_sizes, int n_in,
                              void* d_out, int out_size)
{
    const float* x    = (const float*)d_in[0];
    const float* wq   = (const float*)d_in[1];
    const float* wkv  = (const float*)d_in[2];
    const float* wo   = (const float*)d_in[3];
    const float* bo   = (const float*)d_in[4];
    const float* relh = (const float*)d_in[5];
    const float* relw = (const float*)d_in[6];
    const float* wc   = (const float*)d_in[7];
    const float* bc   = (const float*)d_in[8];
    float* out = (float*)d_out;

    cudaFuncSetAttribute(k_qkv_tc,  cudaFuncAttributeMaxDynamicSharedMemorySize, QK_SMEM);
    cudaFuncSetAttribute(k_attn_tc, cudaFuncAttributeMaxDynamicSharedMemorySize, AT_SMEM);
    cudaFuncSetAttribute(k_out_tc,  cudaFuncAttributeMaxDynamicSharedMemorySize, KO_SMEM);

    k_fuse<<<256, 256>>>(wo, bo, wc, bc);
    k_splitw<<<768, 256>>>(wq, wkv);
    k_splitx<<<8192, 256>>>(x);
    k_qkv_tc<<<dim3(256, 6), 256, QK_SMEM>>>();
    k_attn_tc<<<dim3(512, 4), 256, AT_SMEM>>>(relh, relw);
    k_out_tc<<<dim3(256, 8), 256, KO_SMEM>>>(out);
}

// round 10
// speedup vs baseline: 4.4701x; 1.1639x over previous
#include <cuda_runtime.h>
#include <cuda_fp16.h>
#include <stdint.h>

#define NPIX 32768            // B*H*W
#define QKVC 768

// Scratch (device globals; 16B-aligned)
__device__ __align__(16) __half g_qh[NPIX * QKVC];  // qkv fp16, [pixel][q|k|v]
__device__ __align__(16) __half g_bh[NPIX * 256];   // attn out fp16, [n][256]
__device__ __align__(16) __half g_wfh[1024 * 256];  // fused conv W fp16, [m][k]
__device__ __align__(16) __half g_wqh[QKVC * 256];  // qkv W fp16 (q pre-scaled), [m][k]
__device__ __align__(16) __half g_xh[256 * NPIX];   // x fp16, [k][n]
__device__ float g_bf[1024];

// ---------------------------------------------------------------------------
// helpers (non-arch-specific PTX only: cp.async / ldmatrix / mma.sync)
// ---------------------------------------------------------------------------
__device__ __forceinline__ uint32_t smem_u32(const void* p) {
    uint32_t a;
    asm("{ .reg .u64 t; cvta.to.shared.u64 t, %1; cvt.u32.u64 %0, t; }" : "=r"(a) : "l"(p));
    return a;
}
__device__ __forceinline__ void cp16(uint32_t d, const void* s) {
    asm volatile("cp.async.ca.shared.global [%0], [%1], 16;" :: "r"(d), "l"(s));
}
#define CP_COMMIT() asm volatile("cp.async.commit_group;")
#define CP_WAIT1()  asm volatile("cp.async.wait_group 1;")
#define CP_WAIT0()  asm volatile("cp.async.wait_group 0;")

__device__ __forceinline__ void ldm4(uint32_t* r, uint32_t a) {
    asm volatile("ldmatrix.sync.aligned.m8n8.x4.shared.b16 {%0,%1,%2,%3}, [%4];"
                 : "=r"(r[0]), "=r"(r[1]), "=r"(r[2]), "=r"(r[3]) : "r"(a));
}
__device__ __forceinline__ void ldm4t(uint32_t* r, uint32_t a) {
    asm volatile("ldmatrix.sync.aligned.m8n8.x4.trans.shared.b16 {%0,%1,%2,%3}, [%4];"
                 : "=r"(r[0]), "=r"(r[1]), "=r"(r[2]), "=r"(r[3]) : "r"(a));
}
__device__ __forceinline__ void mma_f16(float* d, const uint32_t* a, uint32_t b0, uint32_t b1) {
    asm volatile("mma.sync.aligned.m16n8k16.row.col.f32.f16.f16.f32 "
                 "{%0,%1,%2,%3}, {%4,%5,%6,%7}, {%8,%9}, {%0,%1,%2,%3};"
                 : "+f"(d[0]), "+f"(d[1]), "+f"(d[2]), "+f"(d[3])
                 : "r"(a[0]), "r"(a[1]), "r"(a[2]), "r"(a[3]), "r"(b0), "r"(b1));
}
__device__ __forceinline__ uint32_t packh(__half a, __half b) {
    return (uint32_t)__half_as_ushort(a) | ((uint32_t)__half_as_ushort(b) << 16);
}

// ---------------------------------------------------------------------------
// K0: fuse wo into conv: Wf = wc @ wo (fp16), bf = wc@bo + bc
// ---------------------------------------------------------------------------
__global__ __launch_bounds__(256) void k_fuse(const float* __restrict__ wo,
                                              const float* __restrict__ bo,
                                              const float* __restrict__ wc,
                                              const float* __restrict__ bc)
{
    int ob = blockIdx.x * 4;
    int i  = threadIdx.x;
    float a0 = 0.f, a1 = 0.f, a2 = 0.f, a3 = 0.f;
    for (int cc = 0; cc < 256; cc++) {
        float w = wo[cc * 256 + i];
        a0 += wc[(ob + 0) * 256 + cc] * w;
        a1 += wc[(ob + 1) * 256 + cc] * w;
        a2 += wc[(ob + 2) * 256 + cc] * w;
        a3 += wc[(ob + 3) * 256 + cc] * w;
    }
    float vals[4] = {a0, a1, a2, a3};
#pragma unroll
    for (int j = 0; j < 4; j++)
        g_wfh[(size_t)(ob + j) * 256 + i] = __float2half_rn(vals[j]);
    if (i < 4) {
        int o = ob + i;
        float s = 0.f;
        for (int c2 = 0; c2 < 256; c2++) s += wc[o * 256 + c2] * bo[c2];
        g_bf[o] = s + bc[o];
    }
}

// ---------------------------------------------------------------------------
// K0b: wq (pre-scaled by 0.125) / wkv -> fp16 row-major [768][256]
// ---------------------------------------------------------------------------
__global__ __launch_bounds__(256) void k_splitw(const float* __restrict__ wq,
                                                const float* __restrict__ wkv)
{
    int i = blockIdx.x * 256 + threadIdx.x;
    int m = i >> 8, c = i & 255;
    float v = (m < 256) ? wq[m * 256 + c] * 0.125f : wkv[(m - 256) * 256 + c];
    g_wqh[i] = __float2half_rn(v);
}

// ---------------------------------------------------------------------------
// K0c: x -> fp16 [k=channel][n=b*4096+p]
// ---------------------------------------------------------------------------
__global__ __launch_bounds__(256) void k_splitx(const float* __restrict__ x)
{
    size_t i = (size_t)(blockIdx.x * 256 + threadIdx.x) * 4;
    float4 v = *(const float4*)(x + i);
    size_t o = (size_t)((i >> 12) & 255) * NPIX + ((i >> 20) << 12) + (i & 4095);
    *(uint2*)&g_xh[o] = make_uint2(packh(__float2half_rn(v.x), __float2half_rn(v.y)),
                                   packh(__float2half_rn(v.z), __float2half_rn(v.w)));
}

// ---------------------------------------------------------------------------
// K1: QKV projection. C[768,32768] = W @ X, fp16 single-term.
// 3-stage cp.async ring, one __syncthreads per stage.
// ---------------------------------------------------------------------------
#define QK_BUF  18944
#define QK_SMEM (QK_BUF * 3)

__global__ void __launch_bounds__(256, 2) k_qkv_tc()
{
    extern __shared__ char qsm[];
    uint32_t base = smem_u32(qsm);
    int tid = threadIdx.x, lane = tid & 31, wrp = tid >> 5;
    int wm = wrp >> 1, wn = wrp & 1;
    int mt = blockIdx.y, n0 = blockIdx.x << 7;
    int m0 = mt << 7;

    float acc[2][8][4];
#pragma unroll
    for (int a = 0; a < 2; a++)
#pragma unroll
        for (int b = 0; b < 8; b++)
#pragma unroll
            for (int c = 0; c < 4; c++) acc[a][b][c] = 0.f;

    int ar = tid >> 1, ac = (tid & 1) << 4;
    int br = tid >> 3, bc = (tid & 7) << 4;

    auto issue = [&](int s, int buf) {
        int kk = s << 5;
        uint32_t qa = base + buf * QK_BUF;
        const __half* A = g_wqh + (size_t)(m0 + ar) * 256 + kk + ac;
        uint32_t da = qa + ((ar * 40 + ac) << 1);
        cp16(da, A); cp16(da + 16, A + 8);
        const __half* B = g_xh + (size_t)(kk + br) * NPIX + n0 + bc;
        uint32_t db = qa + 10240 + ((br * 136 + bc) << 1);
        cp16(db, B); cp16(db + 16, B + 8);
    };
    auto compute = [&](int buf) {
        uint32_t qa = base + buf * QK_BUF;
        uint32_t ab = qa, bb = qa + 10240;
#pragma unroll
        for (int kh = 0; kh < 32; kh += 16) {
            uint32_t ah[2][4];
#pragma unroll
            for (int mf = 0; mf < 2; mf++)
                ldm4(ah[mf], ab + (((wm * 32 + mf * 16 + (lane & 15)) * 40
                                   + kh + ((lane >> 4) << 3)) << 1));
#pragma unroll
            for (int nb = 0; nb < 4; nb++) {
                uint32_t bh4[4];
                ldm4t(bh4, bb + (((kh + ((lane >> 3) & 1) * 8 + (lane & 7)) * 136
                                  + wn * 64 + nb * 16 + ((lane >> 4) << 3)) << 1));
#pragma unroll
                for (int mf = 0; mf < 2; mf++) {
                    mma_f16(acc[mf][nb * 2],     ah[mf], bh4[0], bh4[1]);
                    mma_f16(acc[mf][nb * 2 + 1], ah[mf], bh4[2], bh4[3]);
                }
            }
        }
    };

    issue(0, 0); CP_COMMIT();
    issue(1, 1); CP_COMMIT();
    for (int s = 0; s < 8; s++) {
        if (s < 7) CP_WAIT1(); else CP_WAIT0();
        __syncthreads();
        if (s + 2 < 8) { issue(s + 2, (s + 2) % 3); CP_COMMIT(); }
        compute(s % 3);
    }
    __syncthreads();

    // epilogue: transpose per 32-row m-quarter via smem; write fp16
    float* tb = (float*)qsm;
    int g = lane >> 2, q = lane & 3;
#pragma unroll
    for (int mq = 0; mq < 4; mq++) {
        if (wm == mq) {
#pragma unroll
            for (int mf = 0; mf < 2; mf++)
#pragma unroll
                for (int nf = 0; nf < 8; nf++) {
                    int nl = wn * 64 + nf * 8 + q * 2;
                    int ml = mf * 16 + g;
                    tb[nl * 33 + ml]            = acc[mf][nf][0];
                    tb[(nl + 1) * 33 + ml]      = acc[mf][nf][1];
                    tb[nl * 33 + ml + 8]        = acc[mf][nf][2];
                    tb[(nl + 1) * 33 + ml + 8]  = acc[mf][nf][3];
                }
        }
        __syncthreads();
        int nl = tid >> 1, half2 = tid & 1;
        const float* src = tb + nl * 33 + half2 * 16;
        size_t dst = (size_t)(n0 + nl) * QKVC + m0 + mq * 32 + half2 * 16;
        unsigned short hs[16];
#pragma unroll
        for (int u = 0; u < 16; u++)
            hs[u] = __half_as_ushort(__float2half_rn(src[u]));
        *(uint4*)&g_qh[dst]     = *(uint4*)&hs[0];
        *(uint4*)&g_qh[dst + 8] = *(uint4*)&hs[8];
        __syncthreads();
    }
}

// ---------------------------------------------------------------------------
// K2: tensor-core halo attention, all-fp16 single-term MMAs.
// Rel logits via MMA: Gw = Q @ relw^T (64x31), Gh = Q @ relh^T, then
// lw[qi][pos] = Gw[qi][pos - qy + 15], lh[qi][pos] = Gh[qi][pos - qx + 15].
// smem: sQ [64][72] | sK(->V) [256][72] | srelh/srelw fp16 [32][72] |
//       Gw/Gh fp32 [64][33] | rmx/rsum. Red overlays sK after AV.
// ---------------------------------------------------------------------------
#define AT_SQ    0
#define AT_SK    9216
#define AT_RELH  46080
#define AT_RELW  50688
#define AT_GW    55296
#define AT_GH    63744
#define AT_RMX   72192
#define AT_RSUM  72704
#define AT_SMEM  73216

__global__ void __launch_bounds__(256, 2) k_attn_tc(const float* __restrict__ relh,
                                                    const float* __restrict__ relw)
{
    extern __shared__ char smc[];
    uint32_t sb = smem_u32(smc);
    int t = threadIdx.x, lane = t & 31, wid = t >> 5;
    int wm = wid >> 1, wn = wid & 1;
    int nbk = blockIdx.x, hh = blockIdx.y;
    int bi = nbk >> 6, tbw = nbk & 63;
    int bh = tbw >> 3, bw = tbw & 7;
    int hco = hh * 64;

    uint32_t qB = sb + AT_SQ;
    uint32_t kB = sb + AT_SK;

    {
        int chunk = t & 7, rr = t >> 3;
        {
            int row = rr;               // rows 0..31
            int qx = row >> 3, qy = row & 7;
            size_t pix = (size_t)(bi * 4096 + (bh * 8 + qx) * 64 + bw * 8 + qy) * QKVC + hco;
            ((uint4*)(smc + AT_SQ))[row * 9 + chunk] = *(const uint4*)(g_qh + pix + chunk * 8);
            row = rr + 32;
            qx = row >> 3; qy = row & 7;
            pix = (size_t)(bi * 4096 + (bh * 8 + qx) * 64 + bw * 8 + qy) * QKVC + hco;
            ((uint4*)(smc + AT_SQ))[row * 9 + chunk] = *(const uint4*)(g_qh + pix + chunk * 8);
        }
#pragma unroll
        for (int p = 0; p < 8; p++) {
            int row = p * 32 + rr;
            int ki = row >> 4, kj = row & 15;
            int gh = bh * 8 - 4 + ki, gw = bw * 8 - 4 + kj;
            bool valid = ((unsigned)gh < 64u) && ((unsigned)gw < 64u);
            size_t pix = (size_t)(valid ? bi * 4096 + gh * 64 + gw : bi * 4096) * QKVC
                       + 256 + hco + chunk * 8;
            uint4 z = make_uint4(0, 0, 0, 0);
            ((uint4*)(smc + AT_SK))[row * 9 + chunk] = valid ? *(const uint4*)(g_qh + pix) : z;
        }
        // rel tables -> fp16 smem [32][72]; zero first (row 31 must be 0)
        for (int idx = t; idx < 1152; idx += 256) {
            ((uint32_t*)(smc + AT_RELH))[idx] = 0;
            ((uint32_t*)(smc + AT_RELW))[idx] = 0;
        }
        __syncthreads();
        for (int idx = t; idx < 1984; idx += 256) {
            int r = idx >> 6, dd = idx & 63;
            ((__half*)(smc + AT_RELH))[r * 72 + dd] = __float2half_rn(relh[idx]);
            ((__half*)(smc + AT_RELW))[r * 72 + dd] = __float2half_rn(relw[idx]);
        }
    }
    __syncthreads();

    // ---- rel logits via MMA: wn==0 -> Gw (relw), wn==1 -> Gh (relh) ----
    {
        float racc[4][4];
#pragma unroll
        for (int a = 0; a < 4; a++)
#pragma unroll
            for (int b = 0; b < 4; b++) racc[a][b] = 0.f;
        uint32_t relB = sb + (wn ? AT_RELH : AT_RELW);
#pragma unroll
        for (int kt = 0; kt < 4; kt++) {
            uint32_t ah[4];
            ldm4(ah, qB + (((wm * 16 + (lane & 15)) * 72 + kt * 16 + ((lane >> 4) << 3)) << 1));
#pragma unroll
            for (int nb = 0; nb < 2; nb++) {
                uint32_t bh4[4];
                ldm4(bh4, relB + (((nb * 16 + ((lane >> 4) << 3) + (lane & 7)) * 72
                                   + kt * 16 + (((lane >> 3) & 1) << 3)) << 1));
                mma_f16(racc[nb * 2],     ah, bh4[0], bh4[1]);
                mma_f16(racc[nb * 2 + 1], ah, bh4[2], bh4[3]);
            }
        }
        float* G = (float*)(smc + (wn ? AT_GH : AT_GW));
        int g2 = lane >> 2, tt = lane & 3;
#pragma unroll
        for (int j = 0; j < 4; j++)
#pragma unroll
            for (int e = 0; e < 4; e++) {
                int row = wm * 16 + g2 + ((e >= 2) ? 8 : 0);
                int col = j * 8 + 2 * tt + (e & 1);
                G[row * 33 + col] = racc[j][e];
            }
    }

    // ---- QK^T: single-term fp16 ----
    float s[16][4];
#pragma unroll
    for (int a = 0; a < 16; a++)
#pragma unroll
        for (int b = 0; b < 4; b++) s[a][b] = 0.f;
#pragma unroll
    for (int kt = 0; kt < 4; kt++) {
        uint32_t ah[4];
        ldm4(ah, qB + (((wm * 16 + (lane & 15)) * 72 + kt * 16 + ((lane >> 4) << 3)) << 1));
#pragma unroll
        for (int nb = 0; nb < 8; nb++) {
            uint32_t boff = (((wn * 128 + nb * 16 + ((lane >> 4) << 3) + (lane & 7)) * 72
                             + kt * 16 + (((lane >> 3) & 1) << 3)) << 1);
            uint32_t bh4[4];
            ldm4(bh4, kB + boff);
            mma_f16(s[nb * 2],     ah, bh4[0], bh4[1]);
            mma_f16(s[nb * 2 + 1], ah, bh4[2], bh4[3]);
        }
    }
    __syncthreads();

    // ---- prefetch V into K buffer ----
    {
        int chunk = t & 7, rr = t >> 3;
#pragma unroll
        for (int p = 0; p < 8; p++) {
            int row = p * 32 + rr;
            int ki = row >> 4, kj = row & 15;
            int gh = bh * 8 - 4 + ki, gw = bw * 8 - 4 + kj;
            bool valid = ((unsigned)gh < 64u) && ((unsigned)gw < 64u);
            size_t pix = (size_t)(valid ? bi * 4096 + gh * 64 + gw : bi * 4096) * QKVC
                       + 512 + hco + chunk * 8;
            cp16(kB + ((uint32_t)(row * 9 + chunk) << 4), g_qh + pix);
        }
        CP_COMMIT();
    }

    // ---- fixup: rel logits (from Gw/Gh) + mask ----
    {
        const float* Gw = (const float*)(smc + AT_GW);
        const float* Gh = (const float*)(smc + AT_GH);
        int g = lane >> 2, tt = lane & 3;
#pragma unroll
        for (int nt = 0; nt < 16; nt++) {
            int jbase = wn * 128 + nt * 8 + 2 * tt;
#pragma unroll
            for (int e = 0; e < 4; e++) {
                int row = wm * 16 + g + ((e >= 2) ? 8 : 0);
                int jj = jbase + (e & 1);
                int ki = jj >> 4, kj = jj & 15;
                int gh = bh * 8 - 4 + ki, gw = bw * 8 - 4 + kj;
                if (((unsigned)gh >= 64u) || ((unsigned)gw >= 64u))
                    s[nt][e] = -3.0e38f;
                else
                    s[nt][e] += Gw[row * 33 + kj - (row & 7) + 15]
                              + Gh[row * 33 + ki - (row >> 3) + 15];
            }
        }
    }

    float* rmx  = (float*)(smc + AT_RMX);
    float* rsum = (float*)(smc + AT_RSUM);
    int gg = lane >> 2;
    int rA = wm * 16 + gg, rB = rA + 8;
    {
        float mA = -3.4e38f, mB = -3.4e38f;
#pragma unroll
        for (int nt = 0; nt < 16; nt++) {
            mA = fmaxf(mA, fmaxf(s[nt][0], s[nt][1]));
            mB = fmaxf(mB, fmaxf(s[nt][2], s[nt][3]));
        }
        mA = fmaxf(mA, __shfl_xor_sync(0xffffffffu, mA, 1));
        mA = fmaxf(mA, __shfl_xor_sync(0xffffffffu, mA, 2));
        mB = fmaxf(mB, __shfl_xor_sync(0xffffffffu, mB, 1));
        mB = fmaxf(mB, __shfl_xor_sync(0xffffffffu, mB, 2));
        if ((lane & 3) == 0) { rmx[wn * 64 + rA] = mA; rmx[wn * 64 + rB] = mB; }
    }
    __syncthreads();
    {
        float mA = fmaxf(rmx[rA], rmx[64 + rA]);
        float mB = fmaxf(rmx[rB], rmx[64 + rB]);
        float sA = 0.f, sB = 0.f;
#pragma unroll
        for (int nt = 0; nt < 16; nt++) {
            s[nt][0] = __expf(s[nt][0] - mA); sA += s[nt][0];
            s[nt][1] = __expf(s[nt][1] - mA); sA += s[nt][1];
            s[nt][2] = __expf(s[nt][2] - mB); sB += s[nt][2];
            s[nt][3] = __expf(s[nt][3] - mB); sB += s[nt][3];
        }
        sA += __shfl_xor_sync(0xffffffffu, sA, 1);
        sA += __shfl_xor_sync(0xffffffffu, sA, 2);
        sB += __shfl_xor_sync(0xffffffffu, sB, 1);
        sB += __shfl_xor_sync(0xffffffffu, sB, 2);
        if ((lane & 3) == 0) { rsum[wn * 64 + rA] = sA; rsum[wn * 64 + rB] = sB; }
    }
    __syncthreads();
    {
        float invA = 1.0f / (rsum[rA] + rsum[64 + rA]);
        float invB = 1.0f / (rsum[rB] + rsum[64 + rB]);
#pragma unroll
        for (int nt = 0; nt < 16; nt++) {
            __half h0 = __float2half_rn(s[nt][0] * invA);
            __half h1 = __float2half_rn(s[nt][1] * invA);
            __half h2 = __float2half_rn(s[nt][2] * invB);
            __half h3 = __float2half_rn(s[nt][3] * invB);
            s[nt][0] = __uint_as_float(packh(h0, h1));
            s[nt][1] = __uint_as_float(packh(h2, h3));
        }
    }
    CP_WAIT0();
    __syncthreads();

    // ---- AV: single-term fp16 ----
    float avc[8][4];
#pragma unroll
    for (int a = 0; a < 8; a++)
#pragma unroll
        for (int b = 0; b < 4; b++) avc[a][b] = 0.f;
#pragma unroll
    for (int kt2 = 0; kt2 < 8; kt2++) {
        uint32_t pa[4] = { __float_as_uint(s[2 * kt2][0]), __float_as_uint(s[2 * kt2][1]),
                           __float_as_uint(s[2 * kt2 + 1][0]), __float_as_uint(s[2 * kt2 + 1][1]) };
#pragma unroll
        for (int nb = 0; nb < 4; nb++) {
            uint32_t off = (((wn * 128 + kt2 * 16 + ((lane >> 3) & 1) * 8 + (lane & 7)) * 72
                            + nb * 16 + ((lane >> 4) << 3)) << 1);
            uint32_t vh4[4];
            ldm4t(vh4, kB + off);
            mma_f16(avc[nb * 2],     pa, vh4[0], vh4[1]);
            mma_f16(avc[nb * 2 + 1], pa, vh4[2], vh4[3]);
        }
    }

    // cross-warp reduction (Red overlays sK; V consumed)
    float* Red = (float*)(smc + AT_SK);
    __syncthreads();
    if (wn == 0) {
#pragma unroll
        for (int nf = 0; nf < 8; nf++)
#pragma unroll
            for (int e = 0; e < 4; e++) {
                int row = wm * 16 + gg + ((e >= 2) ? 8 : 0);
                int col = nf * 8 + 2 * (lane & 3) + (e & 1);
                Red[row * 68 + col] = avc[nf][e];
            }
    }
    __syncthreads();
    if (wn == 1) {
#pragma unroll
        for (int nf = 0; nf < 8; nf++)
#pragma unroll
            for (int e = 0; e < 4; e++) {
                int row = wm * 16 + gg + ((e >= 2) ? 8 : 0);
                int col = nf * 8 + 2 * (lane & 3) + (e & 1);
                Red[row * 68 + col] += avc[nf][e];
            }
    }
    __syncthreads();

    {
        int qi = t >> 2, c0 = (t & 3) * 16;
        int qx = qi >> 3, qy = qi & 7;
        size_t base = (size_t)(bi * 4096 + (bh * 8 + qx) * 64 + bw * 8 + qy) * 256 + hco + c0;
        unsigned short hs[16];
#pragma unroll
        for (int u = 0; u < 16; u++)
            hs[u] = __half_as_ushort(__float2half_rn(Red[qi * 68 + c0 + u]));
        *(uint4*)&g_bh[base]     = *(uint4*)&hs[0];
        *(uint4*)&g_bh[base + 8] = *(uint4*)&hs[8];
    }
}

// ---------------------------------------------------------------------------
// K3: output GEMM + PixelShuffle. fp16 single-term, 3-stage ring.
// ---------------------------------------------------------------------------
#define KO_BUF  20480
#define KO_SMEM (KO_BUF * 3)

__global__ void __launch_bounds__(256, 2) k_out_tc(float* __restrict__ out)
{
    extern __shared__ char osm[];
    uint32_t base = smem_u32(osm);
    int tid = threadIdx.x, lane = tid & 31, wrp = tid >> 5;
    int wm = wrp >> 1, wn = wrp & 1;
    int mt = blockIdx.y, n0 = blockIdx.x << 7;
    int m0 = mt << 7;

    float acc[2][8][4];
#pragma unroll
    for (int a = 0; a < 2; a++)
#pragma unroll
        for (int b = 0; b < 8; b++)
#pragma unroll
            for (int c = 0; c < 4; c++) acc[a][b][c] = 0.f;

    int ar = tid >> 1, ac = (tid & 1) << 4;

    auto issue = [&](int s, int buf) {
        int kk = s << 5;
        uint32_t qa = base + buf * KO_BUF;
        const __half* A = g_wfh + (size_t)(m0 + ar) * 256 + kk + ac;
        uint32_t da = qa + ((ar * 40 + ac) << 1);
        cp16(da, A); cp16(da + 16, A + 8);
        const __half* B = g_bh + (size_t)(n0 + ar) * 256 + kk + ac;
        uint32_t db = qa + 10240 + ((ar * 40 + ac) << 1);
        cp16(db, B); cp16(db + 16, B + 8);
    };
    auto compute = [&](int buf) {
        uint32_t qa = base + buf * KO_BUF;
        uint32_t ab = qa, bb = qa + 10240;
#pragma unroll
        for (int kh = 0; kh < 32; kh += 16) {
            uint32_t ah[2][4];
#pragma unroll
            for (int mf = 0; mf < 2; mf++)
                ldm4(ah[mf], ab + (((wm * 32 + mf * 16 + (lane & 15)) * 40
                                   + kh + ((lane >> 4) << 3)) << 1));
#pragma unroll
            for (int nb = 0; nb < 4; nb++) {
                uint32_t bh4[4];
                ldm4(bh4, bb + (((wn * 64 + nb * 16 + ((lane >> 4) << 3) + (lane & 7)) * 40
                                 + kh + (((lane >> 3) & 1) << 3)) << 1));
#pragma unroll
                for (int mf = 0; mf < 2; mf++) {
                    mma_f16(acc[mf][nb * 2],     ah[mf], bh4[0], bh4[1]);
                    mma_f16(acc[mf][nb * 2 + 1], ah[mf], bh4[2], bh4[3]);
                }
            }
        }
    };

    issue(0, 0); CP_COMMIT();
    issue(1, 1); CP_COMMIT();
    for (int s = 0; s < 8; s++) {
        if (s < 7) CP_WAIT1(); else CP_WAIT0();
        __syncthreads();
        if (s + 2 < 8) { issue(s + 2, (s + 2) % 3); CP_COMMIT(); }
        compute(s % 3);
    }

    int g = lane >> 2, q = lane & 3;
    int h0 = (n0 & 4095) >> 6, bimg = n0 >> 12;
    int hrow = h0 + wn;
#pragma unroll
    for (int mf = 0; mf < 2; mf++) {
#pragma unroll
        for (int which = 0; which < 2; which++) {
            int mm = m0 + wm * 32 + mf * 16 + g + which * 8;
            float bias = g_bf[mm];
            int cch = mm >> 2, r = (mm >> 1) & 1, s2 = mm & 1;
            float* rowp = out + ((size_t)(bimg * 256 + cch) * 128 + 2 * hrow + r) * 128 + s2;
#pragma unroll
            for (int nf = 0; nf < 8; nf++) {
                int w0 = nf * 8 + 2 * q;
                rowp[2 * w0]     = acc[mf][nf][which * 2 + 0] + bias;
                rowp[2 * w0 + 2] = acc[mf][nf][which * 2 + 1] + bias;
            }
        }
    }
}

// ---------------------------------------------------------------------------
extern "C" void kernel_launch(void* const* d_in, const int* in_sizes, int n_in,
                              void* d_out, int out_size)
{
    const float* x    = (const float*)d_in[0];
    const float* wq   = (const float*)d_in[1];
    const float* wkv  = (const float*)d_in[2];
    const float* wo   = (const float*)d_in[3];
    const float* bo   = (const float*)d_in[4];
    const float* relh = (const float*)d_in[5];
    const float* relw = (const float*)d_in[6];
    const float* wc   = (const float*)d_in[7];
    const float* bc   = (const float*)d_in[8];
    float* out = (float*)d_out;

    cudaFuncSetAttribute(k_qkv_tc,  cudaFuncAttributeMaxDynamicSharedMemorySize, QK_SMEM);
    cudaFuncSetAttribute(k_attn_tc, cudaFuncAttributeMaxDynamicSharedMemorySize, AT_SMEM);
    cudaFuncSetAttribute(k_out_tc,  cudaFuncAttributeMaxDynamicSharedMemorySize, KO_SMEM);

    k_fuse<<<256, 256>>>(wo, bo, wc, bc);
    k_splitw<<<768, 256>>>(wq, wkv);
    k_splitx<<<8192, 256>>>(x);
    k_qkv_tc<<<dim3(256, 6), 256, QK_SMEM>>>();
    k_attn_tc<<<dim3(512, 4), 256, AT_SMEM>>>(relh, relw);
    k_out_tc<<<dim3(256, 8), 256, KO_SMEM>>>(out);
}